// round 1
// baseline (speedup 1.0000x reference)
#include <cuda_runtime.h>

#define N_NODES 50000
#define N_EDGES 500000
#define INCH 128
#define HC 128
#define TD 64
#define ED 192

__device__ float g_q[(size_t)N_NODES * HC];
__device__ float g_k[(size_t)N_NODES * HC];
__device__ float g_v[(size_t)N_NODES * HC];
__device__ float g_e[(size_t)N_EDGES * HC];
__device__ float g_alpha[(size_t)N_EDGES * 2];
__device__ float g_asum[(size_t)N_NODES * 2];
__device__ int   g_edge_i32[(size_t)2 * N_EDGES];
__device__ int   g_is64;

__global__ void k_zero()
{
    int i = blockIdx.x * blockDim.x + threadIdx.x;
    if (i < N_NODES * 2) g_asum[i] = 0.f;
}

// edge_index dtype detection: int64 buffers have all-zero high words.
__global__ void k_detect(const int* __restrict__ words)
{
    __shared__ int nz;
    if (threadIdx.x == 0) nz = 0;
    __syncthreads();
    int local = 0;
    for (int idx = threadIdx.x; idx < 4096; idx += blockDim.x)
        if (words[2 * idx + 1] != 0) local = 1;
    if (local) atomicOr(&nz, 1);
    __syncthreads();
    if (threadIdx.x == 0) g_is64 = (nz == 0) ? 1 : 0;
}

__global__ void k_convert(const void* __restrict__ ei)
{
    int idx = blockIdx.x * blockDim.x + threadIdx.x;
    if (idx >= 2 * N_EDGES) return;
    int v;
    if (g_is64) v = (int)((const long long*)ei)[idx];
    else        v = ((const int*)ei)[idx];
    g_edge_i32[idx] = v;
}

#define K1_SMEM ((128 * 132 + 128 * 128) * 4)

__global__ void __launch_bounds__(256, 1)
k_node(const float* __restrict__ x,
       const float* __restrict__ Wq, const float* __restrict__ bq,
       const float* __restrict__ Wk, const float* __restrict__ bk,
       const float* __restrict__ Wv, const float* __restrict__ bv,
       const float* __restrict__ Ws, const float* __restrict__ bs,
       float* __restrict__ out)
{
    extern __shared__ float sm[];
    float* Xs = sm;
    float* Bs = sm + 128 * 132;

    const int tid = threadIdx.x;
    const int mat = blockIdx.y;
    const float* W    = (mat == 0) ? Wq : (mat == 1) ? Wk : (mat == 2) ? Wv : Ws;
    const float* bias = (mat == 0) ? bq : (mat == 1) ? bk : (mat == 2) ? bv : bs;
    float* dst        = (mat == 0) ? g_q : (mat == 1) ? g_k : (mat == 2) ? g_v : out;

    const int base = blockIdx.x * 128;

    for (int idx = tid; idx < 128 * 32; idx += 256) {
        int n  = idx >> 5;
        int c4 = idx & 31;
        int node = base + n;
        float4 xv = make_float4(0.f, 0.f, 0.f, 0.f);
        if (node < N_NODES) xv = ((const float4*)x)[(size_t)node * 32 + c4];
        Xs[(c4 * 4 + 0) * 132 + n] = xv.x;
        Xs[(c4 * 4 + 1) * 132 + n] = xv.y;
        Xs[(c4 * 4 + 2) * 132 + n] = xv.z;
        Xs[(c4 * 4 + 3) * 132 + n] = xv.w;
    }
    for (int idx = tid; idx < 128 * 32; idx += 256)
        ((float4*)Bs)[idx] = ((const float4*)W)[idx];
    __syncthreads();

    const int tx = tid & 15;
    const int ty = tid >> 4;

    float acc[8][8];
#pragma unroll
    for (int i = 0; i < 8; ++i)
#pragma unroll
        for (int j = 0; j < 8; ++j) acc[i][j] = 0.f;

#pragma unroll 4
    for (int kk = 0; kk < 128; ++kk) {
        float a[8], b[8];
        reinterpret_cast<float4*>(a)[0] = *reinterpret_cast<const float4*>(&Xs[kk * 132 + ty * 8]);
        reinterpret_cast<float4*>(a)[1] = *reinterpret_cast<const float4*>(&Xs[kk * 132 + ty * 8 + 4]);
        reinterpret_cast<float4*>(b)[0] = *reinterpret_cast<const float4*>(&Bs[kk * 128 + tx * 8]);
        reinterpret_cast<float4*>(b)[1] = *reinterpret_cast<const float4*>(&Bs[kk * 128 + tx * 8 + 4]);
#pragma unroll
        for (int i = 0; i < 8; ++i)
#pragma unroll
            for (int j = 0; j < 8; ++j)
                acc[i][j] = fmaf(a[i], b[j], acc[i][j]);
    }

    float bb[8];
    reinterpret_cast<float4*>(bb)[0] = *reinterpret_cast<const float4*>(&bias[tx * 8]);
    reinterpret_cast<float4*>(bb)[1] = *reinterpret_cast<const float4*>(&bias[tx * 8 + 4]);

#pragma unroll
    for (int i = 0; i < 8; ++i) {
        int node = base + ty * 8 + i;
        if (node < N_NODES) {
            float4 o0 = make_float4(acc[i][0] + bb[0], acc[i][1] + bb[1],
                                    acc[i][2] + bb[2], acc[i][3] + bb[3]);
            float4 o1 = make_float4(acc[i][4] + bb[4], acc[i][5] + bb[5],
                                    acc[i][6] + bb[6], acc[i][7] + bb[7]);
            ((float4*)dst)[(size_t)node * 32 + tx * 2 + 0] = o0;
            ((float4*)dst)[(size_t)node * 32 + tx * 2 + 1] = o1;
        }
    }
}

#define K2_AS (192 * 132)
#define K2_BS (192 * 128)
#define K2_SMEM ((K2_AS + K2_BS) * 4 + 128 * 4 * 3)

__global__ void __launch_bounds__(256, 1)
k_edge(const float* __restrict__ t,
       const float* __restrict__ last_update,
       const float* __restrict__ msg,
       const float* __restrict__ time_w,
       const float* __restrict__ time_b,
       const float* __restrict__ We)
{
    extern __shared__ float sm[];
    float* As    = sm;
    float* Bs    = sm + K2_AS;
    int*   s_src = (int*)(sm + K2_AS + K2_BS);
    int*   s_dst = s_src + 128;
    float* s_rel = (float*)(s_dst + 128);

    const int tid  = threadIdx.x;
    const int base = blockIdx.x * 128;

    if (tid < 128) {
        int edge = base + tid;
        if (edge < N_EDGES) {
            int s = g_edge_i32[edge];
            s_src[tid] = s;
            s_dst[tid] = g_edge_i32[N_EDGES + edge];
            s_rel[tid] = t[edge] - last_update[s];
        } else {
            s_src[tid] = 0; s_dst[tid] = 0; s_rel[tid] = 0.f;
        }
    }
    __syncthreads();

    for (int idx = tid; idx < 128 * 64; idx += 256) {
        int i = idx >> 6;
        int j = idx & 63;
        As[j * 132 + i] = cosf(s_rel[i] * time_w[j] + time_b[j]);
    }
    for (int idx = tid; idx < 128 * 32; idx += 256) {
        int i  = idx >> 5;
        int c4 = idx & 31;
        float4 m = make_float4(0.f, 0.f, 0.f, 0.f);
        if (base + i < N_EDGES) m = ((const float4*)msg)[(size_t)(base + i) * 32 + c4];
        As[(64 + c4 * 4 + 0) * 132 + i] = m.x;
        As[(64 + c4 * 4 + 1) * 132 + i] = m.y;
        As[(64 + c4 * 4 + 2) * 132 + i] = m.z;
        As[(64 + c4 * 4 + 3) * 132 + i] = m.w;
    }
    for (int idx = tid; idx < 192 * 32; idx += 256)
        ((float4*)Bs)[idx] = ((const float4*)We)[idx];
    __syncthreads();

    const int tx = tid & 15;
    const int ty = tid >> 4;

    float acc[8][8];
#pragma unroll
    for (int i = 0; i < 8; ++i)
#pragma unroll
        for (int j = 0; j < 8; ++j) acc[i][j] = 0.f;

#pragma unroll 4
    for (int kk = 0; kk < 192; ++kk) {
        float a[8], b[8];
        reinterpret_cast<float4*>(a)[0] = *reinterpret_cast<const float4*>(&As[kk * 132 + ty * 8]);
        reinterpret_cast<float4*>(a)[1] = *reinterpret_cast<const float4*>(&As[kk * 132 + ty * 8 + 4]);
        reinterpret_cast<float4*>(b)[0] = *reinterpret_cast<const float4*>(&Bs[kk * 128 + tx * 8]);
        reinterpret_cast<float4*>(b)[1] = *reinterpret_cast<const float4*>(&Bs[kk * 128 + tx * 8 + 4]);
#pragma unroll
        for (int i = 0; i < 8; ++i)
#pragma unroll
            for (int j = 0; j < 8; ++j)
                acc[i][j] = fmaf(a[i], b[j], acc[i][j]);
    }
    __syncthreads();

    float* Es = As;
#pragma unroll
    for (int i = 0; i < 8; ++i) {
        int row = ty * 8 + i;
        *reinterpret_cast<float4*>(&Es[row * 132 + tx * 8]) =
            make_float4(acc[i][0], acc[i][1], acc[i][2], acc[i][3]);
        *reinterpret_cast<float4*>(&Es[row * 132 + tx * 8 + 4]) =
            make_float4(acc[i][4], acc[i][5], acc[i][6], acc[i][7]);
    }
    __syncthreads();

    for (int idx = tid; idx < 128 * 32; idx += 256) {
        int i  = idx >> 5;
        int c4 = idx & 31;
        if (base + i < N_EDGES)
            ((float4*)g_e)[(size_t)(base + i) * 32 + c4] =
                *reinterpret_cast<const float4*>(&Es[i * 132 + c4 * 4]);
    }

    const int w = tid >> 5;
    const int l = tid & 31;
    for (int it = 0; it < 16; ++it) {
        int i    = it * 8 + w;
        int edge = base + i;
        if (edge < N_EDGES) {
            int sn = s_src[i];
            int dn = s_dst[i];
            float4 qv = ((const float4*)g_q)[(size_t)dn * 32 + l];
            float4 kv = ((const float4*)g_k)[(size_t)sn * 32 + l];
            float4 ev = *reinterpret_cast<const float4*>(&Es[i * 132 + l * 4]);
            float s = qv.x * (kv.x + ev.x) + qv.y * (kv.y + ev.y)
                    + qv.z * (kv.z + ev.z) + qv.w * (kv.w + ev.w);
            s += __shfl_xor_sync(0xffffffffu, s, 8, 16);
            s += __shfl_xor_sync(0xffffffffu, s, 4, 16);
            s += __shfl_xor_sync(0xffffffffu, s, 2, 16);
            s += __shfl_xor_sync(0xffffffffu, s, 1, 16);
            if ((l & 15) == 0) {
                int h = l >> 4;
                float a = expf(s * 0.125f);
                g_alpha[(size_t)edge * 2 + h] = a;
                atomicAdd(&g_asum[dn * 2 + h], a);
            }
        }
    }
}

__global__ void __launch_bounds__(256)
k_scatter(float* __restrict__ out)
{
    int gw = (blockIdx.x * blockDim.x + threadIdx.x) >> 5;
    if (gw >= N_EDGES) return;
    int l = threadIdx.x & 31;
    int src = g_edge_i32[gw];
    int dst = g_edge_i32[N_EDGES + gw];
    int h = l >> 4;

    float wgt = g_alpha[(size_t)gw * 2 + h] / (g_asum[dst * 2 + h] + 1e-16f);
    float4 e4 = ((const float4*)g_e)[(size_t)gw * 32 + l];
    float4 v4 = ((const float4*)g_v)[(size_t)src * 32 + l];

    float ox = (v4.x + e4.x) * wgt;
    float oy = (v4.y + e4.y) * wgt;
    float oz = (v4.z + e4.z) * wgt;
    float ow = (v4.w + e4.w) * wgt;

    float* p = out + (size_t)dst * 128 + l * 4;
    asm volatile("red.global.add.v4.f32 [%0], {%1,%2,%3,%4};"
                 :: "l"(p), "f"(ox), "f"(oy), "f"(oz), "f"(ow)
                 : "memory");
}

extern "C" void kernel_launch(void* const* d_in, const int* in_sizes, int n_in,
                              void* d_out, int out_size)
{
    const float* x    = (const float*)d_in[0];
    const float* lu   = (const float*)d_in[1];
    const float* t    = (const float*)d_in[2];
    const float* msg  = (const float*)d_in[3];
    const float* tw   = (const float*)d_in[4];
    const float* tb   = (const float*)d_in[5];
    const float* Wq   = (const float*)d_in[6];
    const float* bq   = (const float*)d_in[7];
    const float* Wk   = (const float*)d_in[8];
    const float* bk   = (const float*)d_in[9];
    const float* Wv   = (const float*)d_in[10];
    const float* bv   = (const float*)d_in[11];
    const float* We   = (const float*)d_in[12];
    const float* Wsk  = (const float*)d_in[13];
    const float* bsk  = (const float*)d_in[14];
    const void*  ei   = d_in[15];
    float* out = (float*)d_out;

    cudaFuncSetAttribute(k_node, cudaFuncAttributeMaxDynamicSharedMemorySize, K1_SMEM);
    cudaFuncSetAttribute(k_edge, cudaFuncAttributeMaxDynamicSharedMemorySize, K2_SMEM);

    k_detect<<<1, 256>>>((const int*)ei);
    k_convert<<<(2 * N_EDGES + 255) / 256, 256>>>(ei);
    k_zero<<<(N_NODES * 2 + 255) / 256, 256>>>();

    dim3 g1((N_NODES + 127) / 128, 4);
    k_node<<<g1, 256, K1_SMEM>>>(x, Wq, bq, Wk, bk, Wv, bv, Wsk, bsk, out);

    k_edge<<<(N_EDGES + 127) / 128, 256, K2_SMEM>>>(t, lu, msg, tw, tb, We);

    // one warp per edge: E*32 threads / 256 = 62500 blocks
    k_scatter<<<(N_EDGES + 7) / 8, 256>>>(out);
}

// round 3
// speedup vs baseline: 1.3024x; 1.3024x over previous
#include <cuda_runtime.h>
#include <cuda_bf16.h>
#include <cstdint>

#define N_NODES 50000
#define N_EDGES 500000
#define NT_EDGE ((N_EDGES + 127) / 128)   // 3907
#define NT_NODE ((N_NODES + 127) / 128)   // 391

// ---------------- global scratch ----------------
__device__ float g_q[(size_t)N_NODES * 128];
__device__ float g_k[(size_t)N_NODES * 128];
__device__ float g_v[(size_t)N_NODES * 128];
__device__ float g_e[(size_t)N_EDGES * 128];
__device__ float g_alpha[(size_t)N_EDGES * 2];
__device__ float g_asum[(size_t)N_NODES * 2];
__device__ int   g_edge_i32[(size_t)2 * N_EDGES];
__device__ int   g_is64;
// pre-transposed bf16x2 hi/lo weight images: B[n][k] = W[k][n]
__device__ uint32_t g_imgWe_h[128 * 96], g_imgWe_l[128 * 96];   // edge: N=128, K=192
__device__ uint32_t g_imgW_h[4][128 * 64], g_imgW_l[4][128 * 64]; // node: N=128, K=128

// ---------------- helpers ----------------
__device__ __forceinline__ uint32_t s2u(const void* p) {
    uint32_t r;
    asm("{ .reg .u64 t; cvta.to.shared.u64 t, %1; cvt.u32.u64 %0, t; }" : "=r"(r) : "l"(p));
    return r;
}

__device__ __forceinline__ void ldsm4(uint32_t& r0, uint32_t& r1, uint32_t& r2, uint32_t& r3,
                                      uint32_t addr) {
    asm volatile("ldmatrix.sync.aligned.m8n8.x4.shared.b16 {%0,%1,%2,%3}, [%4];"
                 : "=r"(r0), "=r"(r1), "=r"(r2), "=r"(r3) : "r"(addr));
}

__device__ __forceinline__ void mma16816(float* d, const uint32_t* a, uint32_t b0, uint32_t b1) {
    asm volatile("mma.sync.aligned.m16n8k16.row.col.f32.bf16.bf16.f32 "
                 "{%0,%1,%2,%3}, {%4,%5,%6,%7}, {%8,%9}, {%0,%1,%2,%3};"
                 : "+f"(d[0]), "+f"(d[1]), "+f"(d[2]), "+f"(d[3])
                 : "r"(a[0]), "r"(a[1]), "r"(a[2]), "r"(a[3]), "r"(b0), "r"(b1));
}

// split two fp32 into packed bf16x2 hi and residual-lo words
__device__ __forceinline__ void split2(float a, float b, uint32_t& hi, uint32_t& lo) {
    __nv_bfloat16 ah = __float2bfloat16(a), bh = __float2bfloat16(b);
    float ar = a - __bfloat162float(ah);
    float br = b - __bfloat162float(bh);
    __nv_bfloat16 al = __float2bfloat16(ar), bl = __float2bfloat16(br);
    hi = ((uint32_t)__bfloat16_as_ushort(bh) << 16) | (uint32_t)__bfloat16_as_ushort(ah);
    lo = ((uint32_t)__bfloat16_as_ushort(bl) << 16) | (uint32_t)__bfloat16_as_ushort(al);
}

// ---------------- small kernels ----------------
__global__ void k_zero()
{
    int i = blockIdx.x * blockDim.x + threadIdx.x;
    if (i < N_NODES * 2) g_asum[i] = 0.f;
}

__global__ void k_detect(const int* __restrict__ words)
{
    __shared__ int nz;
    if (threadIdx.x == 0) nz = 0;
    __syncthreads();
    int local = 0;
    for (int idx = threadIdx.x; idx < 4096; idx += blockDim.x)
        if (words[2 * idx + 1] != 0) local = 1;
    if (local) atomicOr(&nz, 1);
    __syncthreads();
    if (threadIdx.x == 0) g_is64 = (nz == 0) ? 1 : 0;
}

__global__ void k_convert(const void* __restrict__ ei)
{
    int idx = blockIdx.x * blockDim.x + threadIdx.x;
    if (idx >= 2 * N_EDGES) return;
    int v;
    if (g_is64) v = (int)((const long long*)ei)[idx];
    else        v = ((const int*)ei)[idx];
    g_edge_i32[idx] = v;
}

__global__ void k_prep(const float* __restrict__ We,
                       const float* __restrict__ Wq, const float* __restrict__ Wk,
                       const float* __restrict__ Wv, const float* __restrict__ Ws)
{
    int idx = blockIdx.x * blockDim.x + threadIdx.x;
    if (idx < 12288) {                        // We: [n][p], p in [0,96)
        int n = idx / 96, p = idx % 96;
        float a = We[(2 * p) * 128 + n];
        float b = We[(2 * p + 1) * 128 + n];
        uint32_t h, l; split2(a, b, h, l);
        g_imgWe_h[idx] = h; g_imgWe_l[idx] = l;
    } else if (idx < 45056) {                 // node mats: [n][p], p in [0,64)
        int r = idx - 12288;
        int mat = r >> 13;
        int w_  = r & 8191;
        int n = w_ >> 6, p = w_ & 63;
        const float* W = (mat == 0) ? Wq : (mat == 1) ? Wk : (mat == 2) ? Wv : Ws;
        float a = W[(2 * p) * 128 + n];
        float b = W[(2 * p + 1) * 128 + n];
        uint32_t h, l; split2(a, b, h, l);
        g_imgW_h[mat][w_] = h; g_imgW_l[mat][w_] = l;
    }
}

// ---------------- node GEMM (HMMA, 3-split bf16) ----------------
// SMEM words: AH@0 (128*68), AL@8704, BH@17408, BL@26112; total 34816 w = 139264 B
// Es (128*129 fp32 = 16512 w) overlays AH+AL.
#define KN_SA 68          // uint32 row stride (136 halves)
#define KN_SMEM (34816 * 4)

__global__ void __launch_bounds__(256, 1)
k_node_tc(const float* __restrict__ x,
          const float* __restrict__ bq, const float* __restrict__ bk,
          const float* __restrict__ bv, const float* __restrict__ bs,
          float* __restrict__ out)
{
    extern __shared__ uint32_t sm4[];
    const uint32_t smem_base = s2u(sm4);
    const int tid = threadIdx.x;
    const int wid = tid >> 5;
    const int lane = tid & 31;
    const int mat = blockIdx.y;
    const int base = blockIdx.x * 128;

    uint32_t* AH = sm4;
    uint32_t* AL = sm4 + 8704;
    uint32_t* BH = sm4 + 17408;
    uint32_t* BL = sm4 + 26112;
    float* Es = (float*)sm4;

    // B image -> SMEM (padded rows)
    {
        const uint4* gh = (const uint4*)g_imgW_h[mat];
        const uint4* gl = (const uint4*)g_imgW_l[mat];
        for (int idx = tid; idx < 128 * 16; idx += 256) {
            int row = idx >> 4, q = idx & 15;
            ((uint4*)(BH + row * KN_SA))[q] = gh[row * 16 + q];
            ((uint4*)(BL + row * KN_SA))[q] = gl[row * 16 + q];
        }
    }
    // A: split x tile
    for (int idx = tid; idx < 128 * 64; idx += 256) {
        int i = idx >> 6, p = idx & 63;
        int node = base + i;
        float2 xv = make_float2(0.f, 0.f);
        if (node < N_NODES) xv = ((const float2*)x)[(size_t)node * 64 + p];
        uint32_t h, l; split2(xv.x, xv.y, h, l);
        AH[i * KN_SA + p] = h; AL[i * KN_SA + p] = l;
    }
    __syncthreads();

    const int wm = wid & 3;       // 4 m-blocks of 32 rows
    const int wn = wid >> 2;      // 2 n-blocks of 64 cols
    const int lrow = lane & 15;
    const int lk   = (lane >> 4) * 8;

    float d[2][8][4];
#pragma unroll
    for (int mi = 0; mi < 2; ++mi)
#pragma unroll
        for (int ni = 0; ni < 8; ++ni)
#pragma unroll
            for (int c = 0; c < 4; ++c) d[mi][ni][c] = 0.f;

#pragma unroll
    for (int pass = 0; pass < 3; ++pass) {
        const uint32_t aoff = (pass == 2) ? 8704u * 4u : 0u;
        const uint32_t boff = (pass == 1) ? 26112u * 4u : 17408u * 4u;
#pragma unroll
        for (int ks = 0; ks < 8; ++ks) {
            const int k0 = ks * 16;
            uint32_t a[2][4];
#pragma unroll
            for (int mi = 0; mi < 2; ++mi) {
                int row = wm * 32 + mi * 16 + lrow;
                uint32_t addr = smem_base + aoff + (uint32_t)(row * (KN_SA * 4)) + (uint32_t)((k0 + lk) * 2);
                ldsm4(a[mi][0], a[mi][1], a[mi][2], a[mi][3], addr);
            }
            uint32_t bf[4][4];
#pragma unroll
            for (int g = 0; g < 4; ++g) {
                int n = wn * 64 + g * 16 + lrow;
                uint32_t addr = smem_base + boff + (uint32_t)(n * (KN_SA * 4)) + (uint32_t)((k0 + lk) * 2);
                ldsm4(bf[g][0], bf[g][1], bf[g][2], bf[g][3], addr);
            }
#pragma unroll
            for (int mi = 0; mi < 2; ++mi)
#pragma unroll
                for (int g = 0; g < 4; ++g) {
                    mma16816(d[mi][2 * g + 0], a[mi], bf[g][0], bf[g][2]);
                    mma16816(d[mi][2 * g + 1], a[mi], bf[g][1], bf[g][3]);
                }
        }
    }
    __syncthreads();

    // stage to Es (col-major, stride 129)
#pragma unroll
    for (int mi = 0; mi < 2; ++mi) {
        int row0 = wm * 32 + mi * 16 + (lane >> 2);
#pragma unroll
        for (int ni = 0; ni < 8; ++ni) {
            int col = wn * 64 + ni * 8 + (lane & 3) * 2;
            Es[col * 129 + row0]           = d[mi][ni][0];
            Es[(col + 1) * 129 + row0]     = d[mi][ni][1];
            Es[col * 129 + row0 + 8]       = d[mi][ni][2];
            Es[(col + 1) * 129 + row0 + 8] = d[mi][ni][3];
        }
    }
    __syncthreads();

    const float* bias = (mat == 0) ? bq : (mat == 1) ? bk : (mat == 2) ? bv : bs;
    float* dst        = (mat == 0) ? g_q : (mat == 1) ? g_k : (mat == 2) ? g_v : out;

    for (int idx = tid; idx < 128 * 32; idx += 256) {
        int i = idx >> 5, c4 = idx & 31;
        int node = base + i;
        if (node < N_NODES) {
            float4 bb = ((const float4*)bias)[c4];
            float4 v = make_float4(Es[(c4 * 4 + 0) * 129 + i] + bb.x,
                                   Es[(c4 * 4 + 1) * 129 + i] + bb.y,
                                   Es[(c4 * 4 + 2) * 129 + i] + bb.z,
                                   Es[(c4 * 4 + 3) * 129 + i] + bb.w);
            ((float4*)dst)[(size_t)node * 32 + c4] = v;
        }
    }
}

// ---------------- edge GEMM + attention (persistent, HMMA) ----------------
// SMEM words: src@0(128) dst@128 rel@256 tw@384 tb@448,
// AH@512 (128*100), AL@13312, BH@26112, BL@38912 -> total 51712 w = 206848 B
// Es (16512 w) overlays AH+AL (25600 w).
#define KE_SA 100
#define KE_SMEM (51712 * 4)

__global__ void __launch_bounds__(256, 1)
k_edge_tc(const float* __restrict__ t,
          const float* __restrict__ last_update,
          const float* __restrict__ msg,
          const float* __restrict__ time_w,
          const float* __restrict__ time_b)
{
    extern __shared__ uint32_t sm4[];
    const uint32_t smem_base = s2u(sm4);
    const int tid = threadIdx.x;
    const int wid = tid >> 5;
    const int lane = tid & 31;

    int*   s_src = (int*)(sm4);
    int*   s_dst = (int*)(sm4 + 128);
    float* s_rel = (float*)(sm4 + 256);
    float* s_tw  = (float*)(sm4 + 384);
    float* s_tb  = (float*)(sm4 + 448);
    uint32_t* AH = sm4 + 512;
    uint32_t* AL = sm4 + 13312;
    uint32_t* BH = sm4 + 26112;
    uint32_t* BL = sm4 + 38912;
    float* Es = (float*)AH;

    // B image -> SMEM once (persistent CTA)
    {
        const uint4* gh = (const uint4*)g_imgWe_h;
        const uint4* gl = (const uint4*)g_imgWe_l;
        for (int idx = tid; idx < 128 * 24; idx += 256) {
            int row = idx / 24, q = idx % 24;
            ((uint4*)(BH + row * KE_SA))[q] = gh[row * 24 + q];
            ((uint4*)(BL + row * KE_SA))[q] = gl[row * 24 + q];
        }
    }
    if (tid < 64) { s_tw[tid] = time_w[tid]; s_tb[tid] = time_b[tid]; }

    const int wm = wid & 3;
    const int wn = wid >> 2;
    const int lrow = lane & 15;
    const int lk   = (lane >> 4) * 8;

    for (int tile = blockIdx.x; tile < NT_EDGE; tile += gridDim.x) {
        __syncthreads();   // previous tile's Es/indices fully consumed
        const int base = tile * 128;

        if (tid < 128) {
            int edge = base + tid;
            if (edge < N_EDGES) {
                int s = g_edge_i32[edge];
                s_src[tid] = s;
                s_dst[tid] = g_edge_i32[N_EDGES + edge];
                s_rel[tid] = t[edge] - last_update[s];
            } else {
                s_src[tid] = 0; s_dst[tid] = 0; s_rel[tid] = 0.f;
            }
        }
        __syncthreads();

        // A: time encoding colpairs 0..31 (|arg| small -> __cosf is exact enough)
        for (int idx = tid; idx < 128 * 32; idx += 256) {
            int i = idx >> 5, p = idx & 31;
            float rel = s_rel[i];
            float c0 = __cosf(fmaf(rel, s_tw[2 * p],     s_tb[2 * p]));
            float c1 = __cosf(fmaf(rel, s_tw[2 * p + 1], s_tb[2 * p + 1]));
            uint32_t h, l; split2(c0, c1, h, l);
            AH[i * KE_SA + p] = h; AL[i * KE_SA + p] = l;
        }
        // A: msg colpairs 32..95
        for (int idx = tid; idx < 128 * 64; idx += 256) {
            int i = idx >> 6, pm = idx & 63;
            int edge = base + i;
            float2 m = make_float2(0.f, 0.f);
            if (edge < N_EDGES) m = ((const float2*)msg)[(size_t)edge * 64 + pm];
            uint32_t h, l; split2(m.x, m.y, h, l);
            AH[i * KE_SA + 32 + pm] = h; AL[i * KE_SA + 32 + pm] = l;
        }
        __syncthreads();

        float d[2][8][4];
#pragma unroll
        for (int mi = 0; mi < 2; ++mi)
#pragma unroll
            for (int ni = 0; ni < 8; ++ni)
#pragma unroll
                for (int c = 0; c < 4; ++c) d[mi][ni][c] = 0.f;

#pragma unroll
        for (int pass = 0; pass < 3; ++pass) {
            const uint32_t aoff = (pass == 2) ? 13312u * 4u : 512u * 4u;
            const uint32_t boff = (pass == 1) ? 38912u * 4u : 26112u * 4u;
#pragma unroll
            for (int ks = 0; ks < 12; ++ks) {
                const int k0 = ks * 16;
                uint32_t a[2][4];
#pragma unroll
                for (int mi = 0; mi < 2; ++mi) {
                    int row = wm * 32 + mi * 16 + lrow;
                    uint32_t addr = smem_base + aoff + (uint32_t)(row * (KE_SA * 4)) + (uint32_t)((k0 + lk) * 2);
                    ldsm4(a[mi][0], a[mi][1], a[mi][2], a[mi][3], addr);
                }
                uint32_t bf[4][4];
#pragma unroll
                for (int g = 0; g < 4; ++g) {
                    int n = wn * 64 + g * 16 + lrow;
                    uint32_t addr = smem_base + boff + (uint32_t)(n * (KE_SA * 4)) + (uint32_t)((k0 + lk) * 2);
                    ldsm4(bf[g][0], bf[g][1], bf[g][2], bf[g][3], addr);
                }
#pragma unroll
                for (int mi = 0; mi < 2; ++mi)
#pragma unroll
                    for (int g = 0; g < 4; ++g) {
                        mma16816(d[mi][2 * g + 0], a[mi], bf[g][0], bf[g][2]);
                        mma16816(d[mi][2 * g + 1], a[mi], bf[g][1], bf[g][3]);
                    }
            }
        }
        __syncthreads();   // all warps done reading A before Es overlays it

#pragma unroll
        for (int mi = 0; mi < 2; ++mi) {
            int row0 = wm * 32 + mi * 16 + (lane >> 2);
#pragma unroll
            for (int ni = 0; ni < 8; ++ni) {
                int col = wn * 64 + ni * 8 + (lane & 3) * 2;
                Es[col * 129 + row0]           = d[mi][ni][0];
                Es[(col + 1) * 129 + row0]     = d[mi][ni][1];
                Es[col * 129 + row0 + 8]       = d[mi][ni][2];
                Es[(col + 1) * 129 + row0 + 8] = d[mi][ni][3];
            }
        }
        __syncthreads();

        // e -> global (coalesced)
        for (int idx = tid; idx < 128 * 32; idx += 256) {
            int i = idx >> 5, c4 = idx & 31;
            int edge = base + i;
            if (edge < N_EDGES) {
                float4 v = make_float4(Es[(c4 * 4 + 0) * 129 + i],
                                       Es[(c4 * 4 + 1) * 129 + i],
                                       Es[(c4 * 4 + 2) * 129 + i],
                                       Es[(c4 * 4 + 3) * 129 + i]);
                ((float4*)g_e)[(size_t)edge * 32 + c4] = v;
            }
        }

        // attention logits + segment sums (one warp per edge per iter)
        for (int it = 0; it < 16; ++it) {
            int i = it * 8 + wid;
            int ee = base + i;
            if (ee < N_EDGES) {
                int sn = s_src[i];
                int dn = s_dst[i];
                float q0 = g_q[(size_t)dn * 128 + lane];
                float q1 = g_q[(size_t)dn * 128 + 32 + lane];
                float q2 = g_q[(size_t)dn * 128 + 64 + lane];
                float q3 = g_q[(size_t)dn * 128 + 96 + lane];
                float k0 = g_k[(size_t)sn * 128 + lane];
                float k1 = g_k[(size_t)sn * 128 + 32 + lane];
                float k2 = g_k[(size_t)sn * 128 + 64 + lane];
                float k3 = g_k[(size_t)sn * 128 + 96 + lane];
                float e0 = Es[(lane)      * 129 + i];
                float e1 = Es[(lane + 32) * 129 + i];
                float e2 = Es[(lane + 64) * 129 + i];
                float e3 = Es[(lane + 96) * 129 + i];
                float s0 = q0 * (k0 + e0) + q1 * (k1 + e1);
                float s1 = q2 * (k2 + e2) + q3 * (k3 + e3);
#pragma unroll
                for (int off = 16; off >= 1; off >>= 1) {
                    s0 += __shfl_xor_sync(0xffffffffu, s0, off);
                    s1 += __shfl_xor_sync(0xffffffffu, s1, off);
                }
                if (lane == 0) {
                    float a0 = expf(s0 * 0.125f);
                    float a1 = expf(s1 * 0.125f);
                    g_alpha[(size_t)ee * 2 + 0] = a0;
                    g_alpha[(size_t)ee * 2 + 1] = a1;
                    atomicAdd(&g_asum[dn * 2 + 0], a0);
                    atomicAdd(&g_asum[dn * 2 + 1], a1);
                }
            }
        }
    }
}

// ---------------- scatter ----------------
__global__ void __launch_bounds__(256)
k_scatter(float* __restrict__ out)
{
    int gw = (blockIdx.x * blockDim.x + threadIdx.x) >> 5;
    if (gw >= N_EDGES) return;
    int l = threadIdx.x & 31;
    int src = g_edge_i32[gw];
    int dst = g_edge_i32[N_EDGES + gw];
    int h = l >> 4;

    float wgt = g_alpha[(size_t)gw * 2 + h] / (g_asum[dst * 2 + h] + 1e-16f);
    float4 e4 = ((const float4*)g_e)[(size_t)gw * 32 + l];
    float4 v4 = ((const float4*)g_v)[(size_t)src * 32 + l];

    float ox = (v4.x + e4.x) * wgt;
    float oy = (v4.y + e4.y) * wgt;
    float oz = (v4.z + e4.z) * wgt;
    float ow = (v4.w + e4.w) * wgt;

    float* p = out + (size_t)dst * 128 + l * 4;
    asm volatile("red.global.add.v4.f32 [%0], {%1,%2,%3,%4};"
                 :: "l"(p), "f"(ox), "f"(oy), "f"(oz), "f"(ow)
                 : "memory");
}

// ---------------- launch ----------------
extern "C" void kernel_launch(void* const* d_in, const int* in_sizes, int n_in,
                              void* d_out, int out_size)
{
    const float* x    = (const float*)d_in[0];
    const float* lu   = (const float*)d_in[1];
    const float* t    = (const float*)d_in[2];
    const float* msg  = (const float*)d_in[3];
    const float* tw   = (const float*)d_in[4];
    const float* tb   = (const float*)d_in[5];
    const float* Wq   = (const float*)d_in[6];
    const float* bq   = (const float*)d_in[7];
    const float* Wk   = (const float*)d_in[8];
    const float* bk   = (const float*)d_in[9];
    const float* Wv   = (const float*)d_in[10];
    const float* bv   = (const float*)d_in[11];
    const float* We   = (const float*)d_in[12];
    const float* Wsk  = (const float*)d_in[13];
    const float* bsk  = (const float*)d_in[14];
    const void*  ei   = d_in[15];
    float* out = (float*)d_out;

    cudaFuncSetAttribute(k_node_tc, cudaFuncAttributeMaxDynamicSharedMemorySize, KN_SMEM);
    cudaFuncSetAttribute(k_edge_tc, cudaFuncAttributeMaxDynamicSharedMemorySize, KE_SMEM);

    k_detect<<<1, 256>>>((const int*)ei);
    k_convert<<<(2 * N_EDGES + 255) / 256, 256>>>(ei);
    k_zero<<<(N_NODES * 2 + 255) / 256, 256>>>();
    k_prep<<<176, 256>>>(We, Wq, Wk, Wv, Wsk);

    dim3 gnode(NT_NODE, 4);
    k_node_tc<<<gnode, 256, KN_SMEM>>>(x, bq, bk, bv, bsk, out);

    k_edge_tc<<<148, 256, KE_SMEM>>>(t, lu, msg, tw, tb);

    k_scatter<<<(N_EDGES + 7) / 8, 256>>>(out);
}

// round 4
// speedup vs baseline: 1.5301x; 1.1748x over previous
#include <cuda_runtime.h>
#include <cuda_bf16.h>
#include <cstdint>

#define N_NODES 50000
#define N_EDGES 500000
#define NT_EDGE ((N_EDGES + 127) / 128)   // 3907
#define NT_NODE ((N_NODES + 127) / 128)   // 391

// ---------------- global scratch ----------------
__device__ float g_q[(size_t)N_NODES * 128];
__device__ float g_k[(size_t)N_NODES * 128];
__device__ float g_v[(size_t)N_NODES * 128];
__device__ float g_acc[(size_t)N_NODES * 128];   // unnormalized aggregation
__device__ float g_asum[(size_t)N_NODES * 2];
__device__ int   g_edge_i32[(size_t)2 * N_EDGES];
__device__ int   g_is64;
// pre-transposed bf16x2 hi/lo weight images: B[n][k] = W[k][n]
__device__ uint32_t g_imgWe_h[128 * 96], g_imgWe_l[128 * 96];     // edge: N=128, K=192
__device__ uint32_t g_imgW_h[4][128 * 64], g_imgW_l[4][128 * 64]; // node: N=128, K=128

// ---------------- helpers ----------------
__device__ __forceinline__ uint32_t s2u(const void* p) {
    uint32_t r;
    asm("{ .reg .u64 t; cvta.to.shared.u64 t, %1; cvt.u32.u64 %0, t; }" : "=r"(r) : "l"(p));
    return r;
}

__device__ __forceinline__ void ldsm4(uint32_t& r0, uint32_t& r1, uint32_t& r2, uint32_t& r3,
                                      uint32_t addr) {
    asm volatile("ldmatrix.sync.aligned.m8n8.x4.shared.b16 {%0,%1,%2,%3}, [%4];"
                 : "=r"(r0), "=r"(r1), "=r"(r2), "=r"(r3) : "r"(addr));
}

__device__ __forceinline__ void mma16816(float* d, const uint32_t* a, uint32_t b0, uint32_t b1) {
    asm volatile("mma.sync.aligned.m16n8k16.row.col.f32.bf16.bf16.f32 "
                 "{%0,%1,%2,%3}, {%4,%5,%6,%7}, {%8,%9}, {%0,%1,%2,%3};"
                 : "+f"(d[0]), "+f"(d[1]), "+f"(d[2]), "+f"(d[3])
                 : "r"(a[0]), "r"(a[1]), "r"(a[2]), "r"(a[3]), "r"(b0), "r"(b1));
}

__device__ __forceinline__ void split2(float a, float b, uint32_t& hi, uint32_t& lo) {
    __nv_bfloat16 ah = __float2bfloat16(a), bh = __float2bfloat16(b);
    float ar = a - __bfloat162float(ah);
    float br = b - __bfloat162float(bh);
    __nv_bfloat16 al = __float2bfloat16(ar), bl = __float2bfloat16(br);
    hi = ((uint32_t)__bfloat16_as_ushort(bh) << 16) | (uint32_t)__bfloat16_as_ushort(ah);
    lo = ((uint32_t)__bfloat16_as_ushort(bl) << 16) | (uint32_t)__bfloat16_as_ushort(al);
}

// ---------------- small kernels ----------------
__global__ void k_zero()
{
    int i = blockIdx.x * blockDim.x + threadIdx.x;
    if (i < N_NODES * 2) g_asum[i] = 0.f;
    if (i < N_NODES * 32) ((float4*)g_acc)[i] = make_float4(0.f, 0.f, 0.f, 0.f);
}

__global__ void k_detect(const int* __restrict__ words)
{
    __shared__ int nz;
    if (threadIdx.x == 0) nz = 0;
    __syncthreads();
    int local = 0;
    for (int idx = threadIdx.x; idx < 4096; idx += blockDim.x)
        if (words[2 * idx + 1] != 0) local = 1;
    if (local) atomicOr(&nz, 1);
    __syncthreads();
    if (threadIdx.x == 0) g_is64 = (nz == 0) ? 1 : 0;
}

__global__ void k_convert(const void* __restrict__ ei)
{
    int idx = blockIdx.x * blockDim.x + threadIdx.x;
    if (idx >= 2 * N_EDGES) return;
    int v;
    if (g_is64) v = (int)((const long long*)ei)[idx];
    else        v = ((const int*)ei)[idx];
    g_edge_i32[idx] = v;
}

__global__ void k_prep(const float* __restrict__ We,
                       const float* __restrict__ Wq, const float* __restrict__ Wk,
                       const float* __restrict__ Wv, const float* __restrict__ Ws)
{
    int idx = blockIdx.x * blockDim.x + threadIdx.x;
    if (idx < 12288) {
        int n = idx / 96, p = idx % 96;
        float a = We[(2 * p) * 128 + n];
        float b = We[(2 * p + 1) * 128 + n];
        uint32_t h, l; split2(a, b, h, l);
        g_imgWe_h[idx] = h; g_imgWe_l[idx] = l;
    } else if (idx < 45056) {
        int r = idx - 12288;
        int mat = r >> 13;
        int w_  = r & 8191;
        int n = w_ >> 6, p = w_ & 63;
        const float* W = (mat == 0) ? Wq : (mat == 1) ? Wk : (mat == 2) ? Wv : Ws;
        float a = W[(2 * p) * 128 + n];
        float b = W[(2 * p + 1) * 128 + n];
        uint32_t h, l; split2(a, b, h, l);
        g_imgW_h[mat][w_] = h; g_imgW_l[mat][w_] = l;
    }
}

// ---------------- node GEMM (HMMA, 3-split bf16) ----------------
#define KN_SA 68
#define KN_SMEM (34816 * 4)

__global__ void __launch_bounds__(256, 1)
k_node_tc(const float* __restrict__ x,
          const float* __restrict__ bq, const float* __restrict__ bk,
          const float* __restrict__ bv, const float* __restrict__ bs,
          float* __restrict__ out)
{
    extern __shared__ uint32_t sm4[];
    const uint32_t smem_base = s2u(sm4);
    const int tid = threadIdx.x;
    const int wid = tid >> 5;
    const int lane = tid & 31;
    const int mat = blockIdx.y;
    const int base = blockIdx.x * 128;

    uint32_t* AH = sm4;
    uint32_t* AL = sm4 + 8704;
    uint32_t* BH = sm4 + 17408;
    uint32_t* BL = sm4 + 26112;
    float* Es = (float*)sm4;

    {
        const uint4* gh = (const uint4*)g_imgW_h[mat];
        const uint4* gl = (const uint4*)g_imgW_l[mat];
        for (int idx = tid; idx < 128 * 16; idx += 256) {
            int row = idx >> 4, q = idx & 15;
            ((uint4*)(BH + row * KN_SA))[q] = gh[row * 16 + q];
            ((uint4*)(BL + row * KN_SA))[q] = gl[row * 16 + q];
        }
    }
    for (int idx = tid; idx < 128 * 64; idx += 256) {
        int i = idx >> 6, p = idx & 63;
        int node = base + i;
        float2 xv = make_float2(0.f, 0.f);
        if (node < N_NODES) xv = ((const float2*)x)[(size_t)node * 64 + p];
        uint32_t h, l; split2(xv.x, xv.y, h, l);
        AH[i * KN_SA + p] = h; AL[i * KN_SA + p] = l;
    }
    __syncthreads();

    const int wm = wid & 3;
    const int wn = wid >> 2;
    const int lrow = lane & 15;
    const int lk   = (lane >> 4) * 8;

    float d[2][8][4];
#pragma unroll
    for (int mi = 0; mi < 2; ++mi)
#pragma unroll
        for (int ni = 0; ni < 8; ++ni)
#pragma unroll
            for (int c = 0; c < 4; ++c) d[mi][ni][c] = 0.f;

#pragma unroll
    for (int pass = 0; pass < 3; ++pass) {
        const uint32_t aoff = (pass == 2) ? 8704u * 4u : 0u;
        const uint32_t boff = (pass == 1) ? 26112u * 4u : 17408u * 4u;
#pragma unroll
        for (int ks = 0; ks < 8; ++ks) {
            const int k0 = ks * 16;
            uint32_t a[2][4];
#pragma unroll
            for (int mi = 0; mi < 2; ++mi) {
                int row = wm * 32 + mi * 16 + lrow;
                uint32_t addr = smem_base + aoff + (uint32_t)(row * (KN_SA * 4)) + (uint32_t)((k0 + lk) * 2);
                ldsm4(a[mi][0], a[mi][1], a[mi][2], a[mi][3], addr);
            }
            uint32_t bf[4][4];
#pragma unroll
            for (int g = 0; g < 4; ++g) {
                int n = wn * 64 + g * 16 + lrow;
                uint32_t addr = smem_base + boff + (uint32_t)(n * (KN_SA * 4)) + (uint32_t)((k0 + lk) * 2);
                ldsm4(bf[g][0], bf[g][1], bf[g][2], bf[g][3], addr);
            }
#pragma unroll
            for (int mi = 0; mi < 2; ++mi)
#pragma unroll
                for (int g = 0; g < 4; ++g) {
                    mma16816(d[mi][2 * g + 0], a[mi], bf[g][0], bf[g][2]);
                    mma16816(d[mi][2 * g + 1], a[mi], bf[g][1], bf[g][3]);
                }
        }
    }
    __syncthreads();

#pragma unroll
    for (int mi = 0; mi < 2; ++mi) {
        int row0 = wm * 32 + mi * 16 + (lane >> 2);
#pragma unroll
        for (int ni = 0; ni < 8; ++ni) {
            int col = wn * 64 + ni * 8 + (lane & 3) * 2;
            Es[col * 129 + row0]           = d[mi][ni][0];
            Es[(col + 1) * 129 + row0]     = d[mi][ni][1];
            Es[col * 129 + row0 + 8]       = d[mi][ni][2];
            Es[(col + 1) * 129 + row0 + 8] = d[mi][ni][3];
        }
    }
    __syncthreads();

    const float* bias = (mat == 0) ? bq : (mat == 1) ? bk : (mat == 2) ? bv : bs;
    float* dst        = (mat == 0) ? g_q : (mat == 1) ? g_k : (mat == 2) ? g_v : out;

    for (int idx = tid; idx < 128 * 32; idx += 256) {
        int i = idx >> 5, c4 = idx & 31;
        int node = base + i;
        if (node < N_NODES) {
            float4 bb = ((const float4*)bias)[c4];
            float4 v = make_float4(Es[(c4 * 4 + 0) * 129 + i] + bb.x,
                                   Es[(c4 * 4 + 1) * 129 + i] + bb.y,
                                   Es[(c4 * 4 + 2) * 129 + i] + bb.z,
                                   Es[(c4 * 4 + 3) * 129 + i] + bb.w);
            ((float4*)dst)[(size_t)node * 32 + c4] = v;
        }
    }
}

// ---------------- edge GEMM + attention + fused scatter (persistent) ----------------
// SMEM words: src@0(128) dst@128 rel@256 tw@384 tb@448,
// AH@512 (128*100), AL@13312, BH@26112, BL@38912 -> total 51712 w = 206848 B
// Es row-major [128][132] (16896 w) overlays AH+AL (25600 w).
#define KE_SA 100
#define KE_SMEM (51712 * 4)

__global__ void __launch_bounds__(256, 1)
k_edge_tc(const float* __restrict__ t,
          const float* __restrict__ last_update,
          const float* __restrict__ msg,
          const float* __restrict__ time_w,
          const float* __restrict__ time_b)
{
    extern __shared__ uint32_t sm4[];
    const uint32_t smem_base = s2u(sm4);
    const int tid = threadIdx.x;
    const int wid = tid >> 5;
    const int lane = tid & 31;

    int*   s_src = (int*)(sm4);
    int*   s_dst = (int*)(sm4 + 128);
    float* s_rel = (float*)(sm4 + 256);
    float* s_tw  = (float*)(sm4 + 384);
    float* s_tb  = (float*)(sm4 + 448);
    uint32_t* AH = sm4 + 512;
    uint32_t* AL = sm4 + 13312;
    uint32_t* BH = sm4 + 26112;
    uint32_t* BL = sm4 + 38912;
    float* Es = (float*)AH;           // [128][132] row-major

    {
        const uint4* gh = (const uint4*)g_imgWe_h;
        const uint4* gl = (const uint4*)g_imgWe_l;
        for (int idx = tid; idx < 128 * 24; idx += 256) {
            int row = idx / 24, q = idx % 24;
            ((uint4*)(BH + row * KE_SA))[q] = gh[row * 24 + q];
            ((uint4*)(BL + row * KE_SA))[q] = gl[row * 24 + q];
        }
    }
    if (tid < 64) { s_tw[tid] = time_w[tid]; s_tb[tid] = time_b[tid]; }

    const int wm = wid & 3;
    const int wn = wid >> 2;
    const int lrow = lane & 15;
    const int lk   = (lane >> 4) * 8;
    const int lh   = lane >> 4;       // head of this lane (0: cols 0-63, 1: 64-127)

    for (int tile = blockIdx.x; tile < NT_EDGE; tile += gridDim.x) {
        __syncthreads();
        const int base = tile * 128;

        if (tid < 128) {
            int edge = base + tid;
            if (edge < N_EDGES) {
                int s = g_edge_i32[edge];
                s_src[tid] = s;
                s_dst[tid] = g_edge_i32[N_EDGES + edge];
                s_rel[tid] = t[edge] - last_update[s];
            } else {
                s_src[tid] = -1; s_dst[tid] = 0; s_rel[tid] = 0.f;
            }
        }
        __syncthreads();

        // A: time encoding (colpairs 0..31); |arg| small -> __cosf exact enough
        for (int idx = tid; idx < 128 * 32; idx += 256) {
            int i = idx >> 5, p = idx & 31;
            float rel = s_rel[i];
            float c0 = __cosf(fmaf(rel, s_tw[2 * p],     s_tb[2 * p]));
            float c1 = __cosf(fmaf(rel, s_tw[2 * p + 1], s_tb[2 * p + 1]));
            uint32_t h, l; split2(c0, c1, h, l);
            AH[i * KE_SA + p] = h; AL[i * KE_SA + p] = l;
        }
        // A: msg (colpairs 32..95)
        for (int idx = tid; idx < 128 * 64; idx += 256) {
            int i = idx >> 6, pm = idx & 63;
            int edge = base + i;
            float2 m = make_float2(0.f, 0.f);
            if (edge < N_EDGES) m = ((const float2*)msg)[(size_t)edge * 64 + pm];
            uint32_t h, l; split2(m.x, m.y, h, l);
            AH[i * KE_SA + 32 + pm] = h; AL[i * KE_SA + 32 + pm] = l;
        }
        __syncthreads();

        float d[2][8][4];
#pragma unroll
        for (int mi = 0; mi < 2; ++mi)
#pragma unroll
            for (int ni = 0; ni < 8; ++ni)
#pragma unroll
                for (int c = 0; c < 4; ++c) d[mi][ni][c] = 0.f;

#pragma unroll
        for (int pass = 0; pass < 3; ++pass) {
            const uint32_t aoff = (pass == 2) ? 13312u * 4u : 512u * 4u;
            const uint32_t boff = (pass == 1) ? 38912u * 4u : 26112u * 4u;
#pragma unroll
            for (int ks = 0; ks < 12; ++ks) {
                const int k0 = ks * 16;
                uint32_t a[2][4];
#pragma unroll
                for (int mi = 0; mi < 2; ++mi) {
                    int row = wm * 32 + mi * 16 + lrow;
                    uint32_t addr = smem_base + aoff + (uint32_t)(row * (KE_SA * 4)) + (uint32_t)((k0 + lk) * 2);
                    ldsm4(a[mi][0], a[mi][1], a[mi][2], a[mi][3], addr);
                }
                uint32_t bf[4][4];
#pragma unroll
                for (int g = 0; g < 4; ++g) {
                    int n = wn * 64 + g * 16 + lrow;
                    uint32_t addr = smem_base + boff + (uint32_t)(n * (KE_SA * 4)) + (uint32_t)((k0 + lk) * 2);
                    ldsm4(bf[g][0], bf[g][1], bf[g][2], bf[g][3], addr);
                }
#pragma unroll
                for (int mi = 0; mi < 2; ++mi)
#pragma unroll
                    for (int g = 0; g < 4; ++g) {
                        mma16816(d[mi][2 * g + 0], a[mi], bf[g][0], bf[g][2]);
                        mma16816(d[mi][2 * g + 1], a[mi], bf[g][1], bf[g][3]);
                    }
            }
        }
        __syncthreads();   // all warps done reading A before Es overlays it

        // stage e row-major [row][132]
#pragma unroll
        for (int mi = 0; mi < 2; ++mi) {
            int row0 = wm * 32 + mi * 16 + (lane >> 2);
#pragma unroll
            for (int ni = 0; ni < 8; ++ni) {
                int col = wn * 64 + ni * 8 + (lane & 3) * 2;
                *(float2*)&Es[row0 * 132 + col]       = make_float2(d[mi][ni][0], d[mi][ni][1]);
                *(float2*)&Es[(row0 + 8) * 132 + col] = make_float2(d[mi][ni][2], d[mi][ni][3]);
            }
        }
        __syncthreads();

        // attention + fused unnormalized scatter: one warp per edge per iter
#pragma unroll 2
        for (int it = 0; it < 16; ++it) {
            int i = it * 8 + wid;
            int sn = s_src[i];
            if (sn >= 0) {
                int dn = s_dst[i];
                float4 qv = ((const float4*)g_q)[(size_t)dn * 32 + lane];
                float4 kv = ((const float4*)g_k)[(size_t)sn * 32 + lane];
                float4 vv = ((const float4*)g_v)[(size_t)sn * 32 + lane];
                float4 ev = *(const float4*)&Es[i * 132 + lane * 4];
                float s = qv.x * (kv.x + ev.x) + qv.y * (kv.y + ev.y)
                        + qv.z * (kv.z + ev.z) + qv.w * (kv.w + ev.w);
                s += __shfl_xor_sync(0xffffffffu, s, 8);
                s += __shfl_xor_sync(0xffffffffu, s, 4);
                s += __shfl_xor_sync(0xffffffffu, s, 2);
                s += __shfl_xor_sync(0xffffffffu, s, 1);
                float al = expf(s * 0.125f);   // all 16 lanes of this head share s
                float ox = (vv.x + ev.x) * al;
                float oy = (vv.y + ev.y) * al;
                float oz = (vv.z + ev.z) * al;
                float ow = (vv.w + ev.w) * al;
                float* p = g_acc + (size_t)dn * 128 + lane * 4;
                asm volatile("red.global.add.v4.f32 [%0], {%1,%2,%3,%4};"
                             :: "l"(p), "f"(ox), "f"(oy), "f"(oz), "f"(ow) : "memory");
                if ((lane & 15) == 0)
                    atomicAdd(&g_asum[dn * 2 + lh], al);
            }
        }
    }
}

// ---------------- final: out = skip + acc / asum ----------------
__global__ void __launch_bounds__(256)
k_final(float* __restrict__ out)
{
    int idx = blockIdx.x * blockDim.x + threadIdx.x;
    if (idx >= N_NODES * 32) return;
    int n  = idx >> 5;
    int c4 = idx & 31;
    int h  = c4 >> 4;
    float inv = 1.f / (g_asum[n * 2 + h] + 1e-16f);
    float4 a = ((const float4*)g_acc)[idx];
    float4 o = ((float4*)out)[idx];
    o.x += a.x * inv; o.y += a.y * inv; o.z += a.z * inv; o.w += a.w * inv;
    ((float4*)out)[idx] = o;
}

// ---------------- launch ----------------
extern "C" void kernel_launch(void* const* d_in, const int* in_sizes, int n_in,
                              void* d_out, int out_size)
{
    const float* x    = (const float*)d_in[0];
    const float* lu   = (const float*)d_in[1];
    const float* t    = (const float*)d_in[2];
    const float* msg  = (const float*)d_in[3];
    const float* tw   = (const float*)d_in[4];
    const float* tb   = (const float*)d_in[5];
    const float* Wq   = (const float*)d_in[6];
    const float* bq   = (const float*)d_in[7];
    const float* Wk   = (const float*)d_in[8];
    const float* bk   = (const float*)d_in[9];
    const float* Wv   = (const float*)d_in[10];
    const float* bv   = (const float*)d_in[11];
    const float* We   = (const float*)d_in[12];
    const float* Wsk  = (const float*)d_in[13];
    const float* bsk  = (const float*)d_in[14];
    const void*  ei   = d_in[15];
    float* out = (float*)d_out;

    cudaFuncSetAttribute(k_node_tc, cudaFuncAttributeMaxDynamicSharedMemorySize, KN_SMEM);
    cudaFuncSetAttribute(k_edge_tc, cudaFuncAttributeMaxDynamicSharedMemorySize, KE_SMEM);

    k_detect<<<1, 256>>>((const int*)ei);                               // 0
    k_convert<<<(2 * N_EDGES + 255) / 256, 256>>>(ei);                  // 1
    k_zero<<<(N_NODES * 32 + 255) / 256, 256>>>();                      // 2
    k_prep<<<176, 256>>>(We, Wq, Wk, Wv, Wsk);                          // 3

    dim3 gnode(NT_NODE, 4);
    k_node_tc<<<gnode, 256, KN_SMEM>>>(x, bq, bk, bv, bsk, out);        // 4

    k_edge_tc<<<148, 256, KE_SMEM>>>(t, lu, msg, tw, tb);               // 5

    k_final<<<(N_NODES * 32 + 255) / 256, 256>>>(out);                  // 6
}

// round 5
// speedup vs baseline: 1.9676x; 1.2859x over previous
#include <cuda_runtime.h>
#include <cuda_bf16.h>
#include <cstdint>

#define N_NODES 50000
#define N_EDGES 500000
#define NT_EDGE ((N_EDGES + 127) / 128)   // 3907
#define NT_NODE ((N_NODES + 127) / 128)   // 391

// ---------------- global scratch ----------------
__device__ float g_q[(size_t)N_NODES * 128];
__device__ float g_k[(size_t)N_NODES * 128];
__device__ float g_v[(size_t)N_NODES * 128];
__device__ float g_acc[(size_t)N_NODES * 128];
__device__ float g_asum[(size_t)N_NODES * 2];
__device__ int   g_edge_i32[(size_t)2 * N_EDGES];
__device__ int   g_is64;
// pre-transposed bf16x2 hi/lo weight images: B[n][k] = W[k][n]
__device__ uint32_t g_imgWe_h[128 * 96], g_imgWe_l[128 * 96];     // edge: N=128, K=192
__device__ uint32_t g_imgW_h[4][128 * 64], g_imgW_l[4][128 * 64]; // node: N=128, K=128

// ---------------- helpers ----------------
__device__ __forceinline__ uint32_t s2u(const void* p) {
    uint32_t r;
    asm("{ .reg .u64 t; cvta.to.shared.u64 t, %1; cvt.u32.u64 %0, t; }" : "=r"(r) : "l"(p));
    return r;
}

__device__ __forceinline__ void ldsm4(uint32_t* r, uint32_t addr) {
    asm volatile("ldmatrix.sync.aligned.m8n8.x4.shared.b16 {%0,%1,%2,%3}, [%4];"
                 : "=r"(r[0]), "=r"(r[1]), "=r"(r[2]), "=r"(r[3]) : "r"(addr));
}

__device__ __forceinline__ void mma16816(float* d, const uint32_t* a, uint32_t b0, uint32_t b1) {
    asm volatile("mma.sync.aligned.m16n8k16.row.col.f32.bf16.bf16.f32 "
                 "{%0,%1,%2,%3}, {%4,%5,%6,%7}, {%8,%9}, {%0,%1,%2,%3};"
                 : "+f"(d[0]), "+f"(d[1]), "+f"(d[2]), "+f"(d[3])
                 : "r"(a[0]), "r"(a[1]), "r"(a[2]), "r"(a[3]), "r"(b0), "r"(b1));
}

__device__ __forceinline__ void split2(float a, float b, uint32_t& hi, uint32_t& lo) {
    __nv_bfloat16 ah = __float2bfloat16(a), bh = __float2bfloat16(b);
    float ar = a - __bfloat162float(ah);
    float br = b - __bfloat162float(bh);
    __nv_bfloat16 al = __float2bfloat16(ar), bl = __float2bfloat16(br);
    hi = ((uint32_t)__bfloat16_as_ushort(bh) << 16) | (uint32_t)__bfloat16_as_ushort(ah);
    lo = ((uint32_t)__bfloat16_as_ushort(bl) << 16) | (uint32_t)__bfloat16_as_ushort(al);
}

// ---------------- small kernels ----------------
__global__ void k_zero()
{
    int i = blockIdx.x * blockDim.x + threadIdx.x;
    if (i < N_NODES * 2) g_asum[i] = 0.f;
    if (i < N_NODES * 32) ((float4*)g_acc)[i] = make_float4(0.f, 0.f, 0.f, 0.f);
}

__global__ void k_detect(const int* __restrict__ words)
{
    __shared__ int nz;
    if (threadIdx.x == 0) nz = 0;
    __syncthreads();
    int local = 0;
    for (int idx = threadIdx.x; idx < 4096; idx += blockDim.x)
        if (words[2 * idx + 1] != 0) local = 1;
    if (local) atomicOr(&nz, 1);
    __syncthreads();
    if (threadIdx.x == 0) g_is64 = (nz == 0) ? 1 : 0;
}

__global__ void k_convert(const void* __restrict__ ei)
{
    int idx = blockIdx.x * blockDim.x + threadIdx.x;
    if (idx >= 2 * N_EDGES) return;
    int v;
    if (g_is64) v = (int)((const long long*)ei)[idx];
    else        v = ((const int*)ei)[idx];
    g_edge_i32[idx] = v;
}

__global__ void k_prep(const float* __restrict__ We,
                       const float* __restrict__ Wq, const float* __restrict__ Wk,
                       const float* __restrict__ Wv, const float* __restrict__ Ws)
{
    int idx = blockIdx.x * blockDim.x + threadIdx.x;
    if (idx < 12288) {
        int n = idx / 96, p = idx % 96;
        float a = We[(2 * p) * 128 + n];
        float b = We[(2 * p + 1) * 128 + n];
        uint32_t h, l; split2(a, b, h, l);
        g_imgWe_h[idx] = h; g_imgWe_l[idx] = l;
    } else if (idx < 45056) {
        int r = idx - 12288;
        int mat = r >> 13;
        int w_  = r & 8191;
        int n = w_ >> 6, p = w_ & 63;
        const float* W = (mat == 0) ? Wq : (mat == 1) ? Wk : (mat == 2) ? Wv : Ws;
        float a = W[(2 * p) * 128 + n];
        float b = W[(2 * p + 1) * 128 + n];
        uint32_t h, l; split2(a, b, h, l);
        g_imgW_h[mat][w_] = h; g_imgW_l[mat][w_] = l;
    }
}

// ---------------- node GEMM (HMMA, 3-split bf16, fragment-shared) ----------------
// SMEM words: AH@0 (128*68), AL@8704, BH@17408, BL@26112; 34816 w = 139264 B
#define KN_SA 68
#define KN_SMEM (34816 * 4)

__global__ void __launch_bounds__(256, 1)
k_node_tc(const float* __restrict__ x,
          const float* __restrict__ bq, const float* __restrict__ bk,
          const float* __restrict__ bv, const float* __restrict__ bs,
          float* __restrict__ out)
{
    extern __shared__ uint32_t sm4[];
    const uint32_t sb = s2u(sm4);
    const int tid = threadIdx.x;
    const int wid = tid >> 5;
    const int lane = tid & 31;
    const int mat = blockIdx.y;
    const int base = blockIdx.x * 128;

    uint32_t* AH = sm4;
    uint32_t* AL = sm4 + 8704;
    uint32_t* BH = sm4 + 17408;
    uint32_t* BL = sm4 + 26112;

    {
        const uint4* gh = (const uint4*)g_imgW_h[mat];
        const uint4* gl = (const uint4*)g_imgW_l[mat];
        for (int idx = tid; idx < 128 * 16; idx += 256) {
            int row = idx >> 4, q = idx & 15;
            ((uint4*)(BH + row * KN_SA))[q] = gh[row * 16 + q];
            ((uint4*)(BL + row * KN_SA))[q] = gl[row * 16 + q];
        }
    }
    for (int idx = tid; idx < 128 * 64; idx += 256) {
        int i = idx >> 6, p = idx & 63;
        int node = base + i;
        float2 xv = make_float2(0.f, 0.f);
        if (node < N_NODES) xv = ((const float2*)x)[(size_t)node * 64 + p];
        uint32_t h, l; split2(xv.x, xv.y, h, l);
        AH[i * KN_SA + p] = h; AL[i * KN_SA + p] = l;
    }
    __syncthreads();

    const int wm = wid & 3;
    const int wn = wid >> 2;
    const int lrow = lane & 15;
    const int lk   = (lane >> 4) * 8;

    float d[2][8][4];
#pragma unroll
    for (int mi = 0; mi < 2; ++mi)
#pragma unroll
        for (int ni = 0; ni < 8; ++ni)
#pragma unroll
            for (int c = 0; c < 4; ++c) d[mi][ni][c] = 0.f;

#pragma unroll 2
    for (int ks = 0; ks < 8; ++ks) {
        const int k0 = ks * 16;
        uint32_t ah[2][4], al[2][4], bh[4][4], bl[4][4];
#pragma unroll
        for (int mi = 0; mi < 2; ++mi) {
            int row = wm * 32 + mi * 16 + lrow;
            uint32_t ao = (uint32_t)(row * (KN_SA * 4)) + (uint32_t)((k0 + lk) * 2);
            ldsm4(ah[mi], sb + ao);
            ldsm4(al[mi], sb + 8704u * 4u + ao);
        }
#pragma unroll
        for (int g = 0; g < 4; ++g) {
            int n = wn * 64 + g * 16 + lrow;
            uint32_t bo = (uint32_t)(n * (KN_SA * 4)) + (uint32_t)((k0 + lk) * 2);
            ldsm4(bh[g], sb + 17408u * 4u + bo);
            ldsm4(bl[g], sb + 26112u * 4u + bo);
        }
#pragma unroll
        for (int mi = 0; mi < 2; ++mi)
#pragma unroll
            for (int g = 0; g < 4; ++g) {
                mma16816(d[mi][2 * g + 0], ah[mi], bh[g][0], bh[g][2]);
                mma16816(d[mi][2 * g + 1], ah[mi], bh[g][1], bh[g][3]);
                mma16816(d[mi][2 * g + 0], ah[mi], bl[g][0], bl[g][2]);
                mma16816(d[mi][2 * g + 1], ah[mi], bl[g][1], bl[g][3]);
                mma16816(d[mi][2 * g + 0], al[mi], bh[g][0], bh[g][2]);
                mma16816(d[mi][2 * g + 1], al[mi], bh[g][1], bh[g][3]);
            }
    }

    const float* bias = (mat == 0) ? bq : (mat == 1) ? bk : (mat == 2) ? bv : bs;
    float* dst        = (mat == 0) ? g_q : (mat == 1) ? g_k : (mat == 2) ? g_v : out;

    const int l2 = lane & 3;
    const int lr = lane >> 2;
#pragma unroll
    for (int g = 0; g < 4; ++g) {
        const int mi = g >> 1;
        const int c0 = (g & 1) * 2;
        int r = wm * 32 + mi * 16 + (g & 1) * 8 + lr;
        int node = base + r;
        if (node < N_NODES) {
#pragma unroll
            for (int ni = 0; ni < 8; ++ni) {
                int col = wn * 64 + ni * 8 + l2 * 2;
                float2 bb = *(const float2*)(bias + col);
                float2 o = make_float2(d[mi][ni][c0] + bb.x, d[mi][ni][c0 + 1] + bb.y);
                *(float2*)(dst + (size_t)node * 128 + col) = o;
            }
        }
    }
}

// ---------------- edge GEMM + attention + scatter (persistent, pipelined) ----------------
// SMEM words: src[2][128]@0, dst[2][128]@256, rel[2][128]@512, tw@768, tb@832,
// AH@1024 (128*100), AL@13824, BH@26624 (128*100), BL@39424; 52224 w = 208896 B
#define KE_SA 100
#define KE_SMEM (52224 * 4)

__device__ __forceinline__ void edge_load_idx(uint32_t* sm4, int buf, int base,
                                              const float* __restrict__ t,
                                              const float* __restrict__ lu)
{
    int tid = threadIdx.x;
    if (tid < 128) {
        int*   s_src = (int*)(sm4)        + buf * 128;
        int*   s_dst = (int*)(sm4 + 256)  + buf * 128;
        float* s_rel = (float*)(sm4 + 512) + buf * 128;
        int edge = base + tid;
        if (edge < N_EDGES) {
            int s = g_edge_i32[edge];
            s_src[tid] = s;
            s_dst[tid] = g_edge_i32[N_EDGES + edge];
            s_rel[tid] = t[edge] - lu[s];
        } else {
            s_src[tid] = -1; s_dst[tid] = 0; s_rel[tid] = 0.f;
        }
    }
}

__device__ __forceinline__ void edge_build_A(uint32_t* sm4, int buf, int base,
                                             const float* __restrict__ msg)
{
    int tid = threadIdx.x;
    float* s_rel = (float*)(sm4 + 512) + buf * 128;
    float* s_tw  = (float*)(sm4 + 768);
    float* s_tb  = (float*)(sm4 + 832);
    uint32_t* AH = sm4 + 1024;
    uint32_t* AL = sm4 + 13824;
    for (int idx = tid; idx < 128 * 32; idx += 256) {
        int i = idx >> 5, p = idx & 31;
        float rel = s_rel[i];
        float c0 = __cosf(fmaf(rel, s_tw[2 * p],     s_tb[2 * p]));
        float c1 = __cosf(fmaf(rel, s_tw[2 * p + 1], s_tb[2 * p + 1]));
        uint32_t h, l; split2(c0, c1, h, l);
        AH[i * KE_SA + p] = h; AL[i * KE_SA + p] = l;
    }
    for (int idx = tid; idx < 128 * 64; idx += 256) {
        int i = idx >> 6, pm = idx & 63;
        int edge = base + i;
        float2 m = make_float2(0.f, 0.f);
        if (edge < N_EDGES) m = ((const float2*)msg)[(size_t)edge * 64 + pm];
        uint32_t h, l; split2(m.x, m.y, h, l);
        AH[i * KE_SA + 32 + pm] = h; AL[i * KE_SA + 32 + pm] = l;
    }
}

__global__ void __launch_bounds__(256, 1)
k_edge_tc(const float* __restrict__ t,
          const float* __restrict__ last_update,
          const float* __restrict__ msg,
          const float* __restrict__ time_w,
          const float* __restrict__ time_b)
{
    extern __shared__ uint32_t sm4[];
    const uint32_t sb = s2u(sm4);
    const int tid = threadIdx.x;
    const int wid = tid >> 5;
    const int lane = tid & 31;

    // B images -> SMEM once
    {
        const uint4* gh = (const uint4*)g_imgWe_h;
        const uint4* gl = (const uint4*)g_imgWe_l;
        uint32_t* BH = sm4 + 26624;
        uint32_t* BL = sm4 + 39424;
        for (int idx = tid; idx < 128 * 24; idx += 256) {
            int row = idx / 24, q = idx % 24;
            ((uint4*)(BH + row * KE_SA))[q] = gh[row * 24 + q];
            ((uint4*)(BL + row * KE_SA))[q] = gl[row * 24 + q];
        }
    }
    if (tid < 64) {
        ((float*)(sm4 + 768))[tid] = time_w[tid];
        ((float*)(sm4 + 832))[tid] = time_b[tid];
    }
    __syncthreads();

    const int wm = wid & 3;
    const int wn = wid >> 2;        // head handled by this warp
    const int lrow = lane & 15;
    const int lk   = (lane >> 4) * 8;
    const int l2   = lane & 3;
    const int lr   = lane >> 2;

    // prologue: indices + A for first tile
    int tile = blockIdx.x;
    if (tile < NT_EDGE) {
        edge_load_idx(sm4, 0, tile * 128, t, last_update);
        __syncthreads();
        edge_build_A(sm4, 0, tile * 128, msg);
    }
    __syncthreads();

    int buf = 0;
    for (; tile < NT_EDGE; tile += gridDim.x) {
        const int base = tile * 128;

        // -------- MMA (fragment-shared 3-pass) --------
        float d[2][8][4];
#pragma unroll
        for (int mi = 0; mi < 2; ++mi)
#pragma unroll
            for (int ni = 0; ni < 8; ++ni)
#pragma unroll
                for (int c = 0; c < 4; ++c) d[mi][ni][c] = 0.f;

#pragma unroll 2
        for (int ks = 0; ks < 12; ++ks) {
            const int k0 = ks * 16;
            uint32_t ah[2][4], al[2][4], bh[4][4], bl[4][4];
#pragma unroll
            for (int mi = 0; mi < 2; ++mi) {
                int row = wm * 32 + mi * 16 + lrow;
                uint32_t ao = (uint32_t)(row * (KE_SA * 4)) + (uint32_t)((k0 + lk) * 2);
                ldsm4(ah[mi], sb + 1024u * 4u + ao);
                ldsm4(al[mi], sb + 13824u * 4u + ao);
            }
#pragma unroll
            for (int g = 0; g < 4; ++g) {
                int n = wn * 64 + g * 16 + lrow;
                uint32_t bo = (uint32_t)(n * (KE_SA * 4)) + (uint32_t)((k0 + lk) * 2);
                ldsm4(bh[g], sb + 26624u * 4u + bo);
                ldsm4(bl[g], sb + 39424u * 4u + bo);
            }
#pragma unroll
            for (int mi = 0; mi < 2; ++mi)
#pragma unroll
                for (int g = 0; g < 4; ++g) {
                    mma16816(d[mi][2 * g + 0], ah[mi], bh[g][0], bh[g][2]);
                    mma16816(d[mi][2 * g + 1], ah[mi], bh[g][1], bh[g][3]);
                    mma16816(d[mi][2 * g + 0], ah[mi], bl[g][0], bl[g][2]);
                    mma16816(d[mi][2 * g + 1], ah[mi], bl[g][1], bl[g][3]);
                    mma16816(d[mi][2 * g + 0], al[mi], bh[g][0], bh[g][2]);
                    mma16816(d[mi][2 * g + 1], al[mi], bh[g][1], bh[g][3]);
                }
        }
        __syncthreads();   // A consumable

        // -------- prefetch next tile indices + rebuild A --------
        int nxt = tile + gridDim.x;
        if (nxt < NT_EDGE)
            edge_load_idx(sm4, buf ^ 1, nxt * 128, t, last_update);
        __syncthreads();
        if (nxt < NT_EDGE)
            edge_build_A(sm4, buf ^ 1, nxt * 128, msg);

        // -------- register-resident epilogue --------
        {
            const int* s_src = (const int*)(sm4)        + buf * 128;
            const int* s_dst = (const int*)(sm4 + 256)  + buf * 128;
#pragma unroll
            for (int g = 0; g < 4; ++g) {
                const int mi = g >> 1;
                const int c0 = (g & 1) * 2;
                int r = wm * 32 + mi * 16 + (g & 1) * 8 + lr;
                int sn = s_src[r];
                int dn = s_dst[r];
                bool valid = (sn >= 0);
                int sn2 = valid ? sn : 0;
                int dn2 = valid ? dn : 0;

                float2 q2[8], k2[8];
#pragma unroll
                for (int ni = 0; ni < 8; ++ni) {
                    int col = wn * 64 + ni * 8 + l2 * 2;
                    q2[ni] = *(const float2*)(g_q + (size_t)dn2 * 128 + col);
                    k2[ni] = *(const float2*)(g_k + (size_t)sn2 * 128 + col);
                }
                float s = 0.f;
#pragma unroll
                for (int ni = 0; ni < 8; ++ni) {
                    s += q2[ni].x * (k2[ni].x + d[mi][ni][c0]);
                    s += q2[ni].y * (k2[ni].y + d[mi][ni][c0 + 1]);
                }
                s += __shfl_xor_sync(0xffffffffu, s, 1);
                s += __shfl_xor_sync(0xffffffffu, s, 2);
                float alv = __expf(s * 0.125f);

                float2 v2[8];
#pragma unroll
                for (int ni = 0; ni < 8; ++ni) {
                    int col = wn * 64 + ni * 8 + l2 * 2;
                    v2[ni] = *(const float2*)(g_v + (size_t)sn2 * 128 + col);
                }
                if (valid) {
#pragma unroll
                    for (int ni = 0; ni < 8; ++ni) {
                        int col = wn * 64 + ni * 8 + l2 * 2;
                        float ox = (v2[ni].x + d[mi][ni][c0])     * alv;
                        float oy = (v2[ni].y + d[mi][ni][c0 + 1]) * alv;
                        float* p = g_acc + (size_t)dn * 128 + col;
                        asm volatile("red.global.add.v2.f32 [%0], {%1,%2};"
                                     :: "l"(p), "f"(ox), "f"(oy) : "memory");
                    }
                    if (l2 == 0)
                        atomicAdd(&g_asum[dn * 2 + wn], alv);
                }
            }
        }
        __syncthreads();   // A(next) built, epilogue done
        buf ^= 1;
    }
}

// ---------------- final: out = skip + acc / asum ----------------
__global__ void __launch_bounds__(256)
k_final(float* __restrict__ out)
{
    int idx = blockIdx.x * blockDim.x + threadIdx.x;
    if (idx >= N_NODES * 32) return;
    int n  = idx >> 5;
    int c4 = idx & 31;
    int h  = c4 >> 4;
    float inv = 1.f / (g_asum[n * 2 + h] + 1e-16f);
    float4 a = ((const float4*)g_acc)[idx];
    float4 o = ((float4*)out)[idx];
    o.x += a.x * inv; o.y += a.y * inv; o.z += a.z * inv; o.w += a.w * inv;
    ((float4*)out)[idx] = o;
}

// ---------------- launch ----------------
extern "C" void kernel_launch(void* const* d_in, const int* in_sizes, int n_in,
                              void* d_out, int out_size)
{
    const float* x    = (const float*)d_in[0];
    const float* lu   = (const float*)d_in[1];
    const float* t    = (const float*)d_in[2];
    const float* msg  = (const float*)d_in[3];
    const float* tw   = (const float*)d_in[4];
    const float* tb   = (const float*)d_in[5];
    const float* Wq   = (const float*)d_in[6];
    const float* bq   = (const float*)d_in[7];
    const float* Wk   = (const float*)d_in[8];
    const float* bk   = (const float*)d_in[9];
    const float* Wv   = (const float*)d_in[10];
    const float* bv   = (const float*)d_in[11];
    const float* We   = (const float*)d_in[12];
    const float* Wsk  = (const float*)d_in[13];
    const float* bsk  = (const float*)d_in[14];
    const void*  ei   = d_in[15];
    float* out = (float*)d_out;

    cudaFuncSetAttribute(k_node_tc, cudaFuncAttributeMaxDynamicSharedMemorySize, KN_SMEM);
    cudaFuncSetAttribute(k_edge_tc, cudaFuncAttributeMaxDynamicSharedMemorySize, KE_SMEM);

    k_detect<<<1, 256>>>((const int*)ei);
    k_convert<<<(2 * N_EDGES + 255) / 256, 256>>>(ei);
    k_zero<<<(N_NODES * 32 + 255) / 256, 256>>>();
    k_prep<<<176, 256>>>(We, Wq, Wk, Wv, Wsk);

    dim3 gnode(NT_NODE, 4);
    k_node_tc<<<gnode, 256, KN_SMEM>>>(x, bq, bk, bv, bsk, out);

    k_edge_tc<<<152, 256, KE_SMEM>>>(t, lu, msg, tw, tb);

    k_final<<<(N_NODES * 32 + 255) / 256, 256>>>(out);
}

// round 8
// speedup vs baseline: 2.3947x; 1.2171x over previous
#include <cuda_runtime.h>
#include <cuda_bf16.h>
#include <cstdint>

#define N_NODES 50000
#define N_EDGES 500000
#define NT_EDGE ((N_EDGES + 127) / 128)   // 3907
#define NT_NODE ((N_NODES + 127) / 128)   // 391

// fused prep kernel block ranges
#define FB_CONV  3907                       // 2*N_EDGES / 256
#define FB_ZERO  6250                       // N_NODES*32 / 256
#define FB_PREP  176
#define FB_TOTAL (FB_CONV + FB_ZERO + FB_PREP)

// ---------------- global scratch ----------------
__device__ float g_q[(size_t)N_NODES * 128];
__device__ float g_k[(size_t)N_NODES * 128];
__device__ float g_v[(size_t)N_NODES * 128];
__device__ float g_acc[(size_t)N_NODES * 128];
__device__ float g_asum[(size_t)N_NODES * 2];
__device__ int   g_edge_i32[(size_t)2 * N_EDGES];
__device__ int   g_is64;
__device__ uint32_t g_imgWe_h[128 * 96], g_imgWe_l[128 * 96];
__device__ uint32_t g_imgW_h[4][128 * 64], g_imgW_l[4][128 * 64];

// ---------------- helpers ----------------
__device__ __forceinline__ uint32_t s2u(const void* p) {
    uint32_t r;
    asm("{ .reg .u64 t; cvta.to.shared.u64 t, %1; cvt.u32.u64 %0, t; }" : "=r"(r) : "l"(p));
    return r;
}

__device__ __forceinline__ void ldsm4(uint32_t* r, uint32_t addr) {
    asm volatile("ldmatrix.sync.aligned.m8n8.x4.shared.b16 {%0,%1,%2,%3}, [%4];"
                 : "=r"(r[0]), "=r"(r[1]), "=r"(r[2]), "=r"(r[3]) : "r"(addr));
}

__device__ __forceinline__ void mma16816(float* d, const uint32_t* a, uint32_t b0, uint32_t b1) {
    asm volatile("mma.sync.aligned.m16n8k16.row.col.f32.bf16.bf16.f32 "
                 "{%0,%1,%2,%3}, {%4,%5,%6,%7}, {%8,%9}, {%0,%1,%2,%3};"
                 : "+f"(d[0]), "+f"(d[1]), "+f"(d[2]), "+f"(d[3])
                 : "r"(a[0]), "r"(a[1]), "r"(a[2]), "r"(a[3]), "r"(b0), "r"(b1));
}

__device__ __forceinline__ void split2(float a, float b, uint32_t& hi, uint32_t& lo) {
    __nv_bfloat16 ah = __float2bfloat16(a), bh = __float2bfloat16(b);
    float ar = a - __bfloat162float(ah);
    float br = b - __bfloat162float(bh);
    __nv_bfloat16 al = __float2bfloat16(ar), bl = __float2bfloat16(br);
    hi = ((uint32_t)__bfloat16_as_ushort(bh) << 16) | (uint32_t)__bfloat16_as_ushort(ah);
    lo = ((uint32_t)__bfloat16_as_ushort(bl) << 16) | (uint32_t)__bfloat16_as_ushort(al);
}

// 256-bit streaming load with evict_first (the only legal evict form on this target)
__device__ __forceinline__ void ldg_ef8(const float* p, float* v) {
    uint32_t r0, r1, r2, r3, r4, r5, r6, r7;
    asm("ld.global.L2::evict_first.v8.b32 {%0,%1,%2,%3,%4,%5,%6,%7}, [%8];"
        : "=r"(r0), "=r"(r1), "=r"(r2), "=r"(r3),
          "=r"(r4), "=r"(r5), "=r"(r6), "=r"(r7) : "l"(p));
    v[0] = __uint_as_float(r0); v[1] = __uint_as_float(r1);
    v[2] = __uint_as_float(r2); v[3] = __uint_as_float(r3);
    v[4] = __uint_as_float(r4); v[5] = __uint_as_float(r5);
    v[6] = __uint_as_float(r6); v[7] = __uint_as_float(r7);
}

// ---------------- detect ----------------
__global__ void k_detect(const int* __restrict__ words)
{
    __shared__ int nz;
    if (threadIdx.x == 0) nz = 0;
    __syncthreads();
    int local = 0;
    for (int idx = threadIdx.x; idx < 4096; idx += blockDim.x)
        if (words[2 * idx + 1] != 0) local = 1;
    if (local) atomicOr(&nz, 1);
    __syncthreads();
    if (threadIdx.x == 0) g_is64 = (nz == 0) ? 1 : 0;
}

// ---------------- fused convert + zero + prep ----------------
__global__ void k_fused(const void* __restrict__ ei,
                        const float* __restrict__ We,
                        const float* __restrict__ Wq, const float* __restrict__ Wk,
                        const float* __restrict__ Wv, const float* __restrict__ Ws)
{
    int b = blockIdx.x;
    if (b < FB_CONV) {
        int idx = b * 256 + threadIdx.x;
        if (idx < 2 * N_EDGES) {
            int v;
            if (g_is64) v = (int)((const long long*)ei)[idx];
            else        v = ((const int*)ei)[idx];
            g_edge_i32[idx] = v;
        }
        return;
    }
    b -= FB_CONV;
    if (b < FB_ZERO) {
        int i = b * 256 + threadIdx.x;
        if (i < N_NODES * 2) g_asum[i] = 0.f;
        if (i < N_NODES * 32) ((float4*)g_acc)[i] = make_float4(0.f, 0.f, 0.f, 0.f);
        return;
    }
    b -= FB_ZERO;
    {
        int idx = b * 256 + threadIdx.x;
        if (idx < 12288) {
            int n = idx / 96, p = idx % 96;
            float a = We[(2 * p) * 128 + n];
            float bb = We[(2 * p + 1) * 128 + n];
            uint32_t h, l; split2(a, bb, h, l);
            g_imgWe_h[idx] = h; g_imgWe_l[idx] = l;
        } else if (idx < 45056) {
            int r = idx - 12288;
            int mat = r >> 13;
            int w_  = r & 8191;
            int n = w_ >> 6, p = w_ & 63;
            const float* W = (mat == 0) ? Wq : (mat == 1) ? Wk : (mat == 2) ? Wv : Ws;
            float a = W[(2 * p) * 128 + n];
            float bb = W[(2 * p + 1) * 128 + n];
            uint32_t h, l; split2(a, bb, h, l);
            g_imgW_h[mat][w_] = h; g_imgW_l[mat][w_] = l;
        }
    }
}

// ---------------- node GEMM: one CTA, all 4 matrices ----------------
// SMEM words: AH@0 (128*68), AL@8704, BH@17408, BL@26112; 34816 w = 139264 B
#define KN_SA 68
#define KN_SMEM (34816 * 4)

__global__ void __launch_bounds__(256, 1)
k_node_tc(const float* __restrict__ x,
          const float* __restrict__ bq, const float* __restrict__ bk,
          const float* __restrict__ bv, const float* __restrict__ bs,
          float* __restrict__ out)
{
    extern __shared__ uint32_t sm4[];
    const uint32_t sb = s2u(sm4);
    const int tid = threadIdx.x;
    const int wid = tid >> 5;
    const int lane = tid & 31;
    const int base = blockIdx.x * 128;

    uint32_t* AH = sm4;
    uint32_t* AL = sm4 + 8704;
    uint32_t* BH = sm4 + 17408;
    uint32_t* BL = sm4 + 26112;

    // A: split x tile once (streamed via v8 evict_first; 16 loads per row)
    for (int idx = tid; idx < 128 * 16; idx += 256) {
        int i = idx >> 4, p4 = idx & 15;       // p4: group of 4 colpairs
        int node = base + i;
        float v[8] = {0.f, 0.f, 0.f, 0.f, 0.f, 0.f, 0.f, 0.f};
        if (node < N_NODES) ldg_ef8(x + (size_t)node * 128 + p4 * 8, v);
#pragma unroll
        for (int j = 0; j < 4; ++j) {
            uint32_t h, l; split2(v[2 * j], v[2 * j + 1], h, l);
            AH[i * KN_SA + p4 * 4 + j] = h;
            AL[i * KN_SA + p4 * 4 + j] = l;
        }
    }

    const int wm = wid & 3;
    const int wn = wid >> 2;
    const int lrow = lane & 15;
    const int lk   = (lane >> 4) * 8;
    const int l2   = lane & 3;
    const int lr   = lane >> 2;

    for (int mat = 0; mat < 4; ++mat) {
        {
            const uint4* gh = (const uint4*)g_imgW_h[mat];
            const uint4* gl = (const uint4*)g_imgW_l[mat];
            for (int idx = tid; idx < 128 * 16; idx += 256) {
                int row = idx >> 4, q = idx & 15;
                ((uint4*)(BH + row * KN_SA))[q] = gh[row * 16 + q];
                ((uint4*)(BL + row * KN_SA))[q] = gl[row * 16 + q];
            }
        }
        __syncthreads();

        float d[2][8][4];
#pragma unroll
        for (int mi = 0; mi < 2; ++mi)
#pragma unroll
            for (int ni = 0; ni < 8; ++ni)
#pragma unroll
                for (int c = 0; c < 4; ++c) d[mi][ni][c] = 0.f;

#pragma unroll 2
        for (int ks = 0; ks < 8; ++ks) {
            const int k0 = ks * 16;
            uint32_t ah[2][4], al[2][4], bh[4][4], bl[4][4];
#pragma unroll
            for (int mi = 0; mi < 2; ++mi) {
                int row = wm * 32 + mi * 16 + lrow;
                uint32_t ao = (uint32_t)(row * (KN_SA * 4)) + (uint32_t)((k0 + lk) * 2);
                ldsm4(ah[mi], sb + ao);
                ldsm4(al[mi], sb + 8704u * 4u + ao);
            }
#pragma unroll
            for (int g = 0; g < 4; ++g) {
                int n = wn * 64 + g * 16 + lrow;
                uint32_t bo = (uint32_t)(n * (KN_SA * 4)) + (uint32_t)((k0 + lk) * 2);
                ldsm4(bh[g], sb + 17408u * 4u + bo);
                ldsm4(bl[g], sb + 26112u * 4u + bo);
            }
#pragma unroll
            for (int mi = 0; mi < 2; ++mi)
#pragma unroll
                for (int g = 0; g < 4; ++g) {
                    mma16816(d[mi][2 * g + 0], ah[mi], bh[g][0], bh[g][2]);
                    mma16816(d[mi][2 * g + 1], ah[mi], bh[g][1], bh[g][3]);
                    mma16816(d[mi][2 * g + 0], ah[mi], bl[g][0], bl[g][2]);
                    mma16816(d[mi][2 * g + 1], ah[mi], bl[g][1], bl[g][3]);
                    mma16816(d[mi][2 * g + 0], al[mi], bh[g][0], bh[g][2]);
                    mma16816(d[mi][2 * g + 1], al[mi], bh[g][1], bh[g][3]);
                }
        }

        const float* bias = (mat == 0) ? bq : (mat == 1) ? bk : (mat == 2) ? bv : bs;
        float* dst        = (mat == 0) ? g_q : (mat == 1) ? g_k : (mat == 2) ? g_v : out;

#pragma unroll
        for (int g = 0; g < 4; ++g) {
            const int mi = g >> 1;
            const int c0 = (g & 1) * 2;
            int r = wm * 32 + mi * 16 + (g & 1) * 8 + lr;
            int node = base + r;
            if (node < N_NODES) {
#pragma unroll
                for (int ni = 0; ni < 8; ++ni) {
                    int col = wn * 64 + ni * 8 + l2 * 2;
                    float2 bb = *(const float2*)(bias + col);
                    float2 o = make_float2(d[mi][ni][c0] + bb.x, d[mi][ni][c0 + 1] + bb.y);
                    *(float2*)(dst + (size_t)node * 128 + col) = o;
                }
            }
        }
        __syncthreads();   // B consumable for next mat
    }
}

// ---------------- edge GEMM + attention + scatter (persistent, pipelined) ----------------
// SMEM words: src[2][128]@0, dst[2][128]@256, rel[2][128]@512, tw@768, tb@832,
// AH@1024 (128*100), AL@13824, BH@26624 (128*100), BL@39424; 52224 w = 208896 B
#define KE_SA 100
#define KE_SMEM (52224 * 4)

__device__ __forceinline__ void edge_load_idx(uint32_t* sm4, int buf, int base,
                                              const float* __restrict__ t,
                                              const float* __restrict__ lu)
{
    int tid = threadIdx.x;
    if (tid < 128) {
        int*   s_src = (int*)(sm4)        + buf * 128;
        int*   s_dst = (int*)(sm4 + 256)  + buf * 128;
        float* s_rel = (float*)(sm4 + 512) + buf * 128;
        int edge = base + tid;
        if (edge < N_EDGES) {
            int s = g_edge_i32[edge];
            s_src[tid] = s;
            s_dst[tid] = g_edge_i32[N_EDGES + edge];
            s_rel[tid] = t[edge] - lu[s];
        } else {
            s_src[tid] = -1; s_dst[tid] = 0; s_rel[tid] = 0.f;
        }
    }
}

__device__ __forceinline__ void edge_build_A(uint32_t* sm4, int buf, int base,
                                             const float* __restrict__ msg)
{
    int tid = threadIdx.x;
    float* s_rel = (float*)(sm4 + 512) + buf * 128;
    float* s_tw  = (float*)(sm4 + 768);
    float* s_tb  = (float*)(sm4 + 832);
    uint32_t* AH = sm4 + 1024;
    uint32_t* AL = sm4 + 13824;
    for (int idx = tid; idx < 128 * 32; idx += 256) {
        int i = idx >> 5, p = idx & 31;
        float rel = s_rel[i];
        float c0 = __cosf(fmaf(rel, s_tw[2 * p],     s_tb[2 * p]));
        float c1 = __cosf(fmaf(rel, s_tw[2 * p + 1], s_tb[2 * p + 1]));
        uint32_t h, l; split2(c0, c1, h, l);
        AH[i * KE_SA + p] = h; AL[i * KE_SA + p] = l;
    }
    // msg: v8 evict_first streaming loads, 16 per row (512 B/row)
    for (int idx = tid; idx < 128 * 16; idx += 256) {
        int i = idx >> 4, p4 = idx & 15;
        int edge = base + i;
        float v[8] = {0.f, 0.f, 0.f, 0.f, 0.f, 0.f, 0.f, 0.f};
        if (edge < N_EDGES) ldg_ef8(msg + (size_t)edge * 128 + p4 * 8, v);
#pragma unroll
        for (int j = 0; j < 4; ++j) {
            uint32_t h, l; split2(v[2 * j], v[2 * j + 1], h, l);
            AH[i * KE_SA + 32 + p4 * 4 + j] = h;
            AL[i * KE_SA + 32 + p4 * 4 + j] = l;
        }
    }
}

__global__ void __launch_bounds__(256, 1)
k_edge_tc(const float* __restrict__ t,
          const float* __restrict__ last_update,
          const float* __restrict__ msg,
          const float* __restrict__ time_w,
          const float* __restrict__ time_b)
{
    extern __shared__ uint32_t sm4[];
    const uint32_t sb = s2u(sm4);
    const int tid = threadIdx.x;
    const int wid = tid >> 5;
    const int lane = tid & 31;

    // B images -> SMEM once
    {
        const uint4* gh = (const uint4*)g_imgWe_h;
        const uint4* gl = (const uint4*)g_imgWe_l;
        uint32_t* BH = sm4 + 26624;
        uint32_t* BL = sm4 + 39424;
        for (int idx = tid; idx < 128 * 24; idx += 256) {
            int row = idx / 24, q = idx % 24;
            ((uint4*)(BH + row * KE_SA))[q] = gh[row * 24 + q];
            ((uint4*)(BL + row * KE_SA))[q] = gl[row * 24 + q];
        }
    }
    if (tid < 64) {
        ((float*)(sm4 + 768))[tid] = time_w[tid];
        ((float*)(sm4 + 832))[tid] = time_b[tid];
    }
    __syncthreads();

    const int wm = wid & 3;
    const int wn = wid >> 2;
    const int lrow = lane & 15;
    const int lk   = (lane >> 4) * 8;
    const int l2   = lane & 3;
    const int lr   = lane >> 2;

    int tile = blockIdx.x;
    if (tile < NT_EDGE) {
        edge_load_idx(sm4, 0, tile * 128, t, last_update);
        __syncthreads();
        edge_build_A(sm4, 0, tile * 128, msg);
    }
    __syncthreads();

    int buf = 0;
    for (; tile < NT_EDGE; tile += gridDim.x) {
        int nxt = tile + gridDim.x;
        if (nxt < NT_EDGE)
            edge_load_idx(sm4, buf ^ 1, nxt * 128, t, last_update);

        // -------- MMA (fragment-shared 3-pass) --------
        float d[2][8][4];
#pragma unroll
        for (int mi = 0; mi < 2; ++mi)
#pragma unroll
            for (int ni = 0; ni < 8; ++ni)
#pragma unroll
                for (int c = 0; c < 4; ++c) d[mi][ni][c] = 0.f;

#pragma unroll 2
        for (int ks = 0; ks < 12; ++ks) {
            const int k0 = ks * 16;
            uint32_t ah[2][4], al[2][4], bh[4][4], bl[4][4];
#pragma unroll
            for (int mi = 0; mi < 2; ++mi) {
                int row = wm * 32 + mi * 16 + lrow;
                uint32_t ao = (uint32_t)(row * (KE_SA * 4)) + (uint32_t)((k0 + lk) * 2);
                ldsm4(ah[mi], sb + 1024u * 4u + ao);
                ldsm4(al[mi], sb + 13824u * 4u + ao);
            }
#pragma unroll
            for (int g = 0; g < 4; ++g) {
                int n = wn * 64 + g * 16 + lrow;
                uint32_t bo = (uint32_t)(n * (KE_SA * 4)) + (uint32_t)((k0 + lk) * 2);
                ldsm4(bh[g], sb + 26624u * 4u + bo);
                ldsm4(bl[g], sb + 39424u * 4u + bo);
            }
#pragma unroll
            for (int mi = 0; mi < 2; ++mi)
#pragma unroll
                for (int g = 0; g < 4; ++g) {
                    mma16816(d[mi][2 * g + 0], ah[mi], bh[g][0], bh[g][2]);
                    mma16816(d[mi][2 * g + 1], ah[mi], bh[g][1], bh[g][3]);
                    mma16816(d[mi][2 * g + 0], ah[mi], bl[g][0], bl[g][2]);
                    mma16816(d[mi][2 * g + 1], ah[mi], bl[g][1], bl[g][3]);
                    mma16816(d[mi][2 * g + 0], al[mi], bh[g][0], bh[g][2]);
                    mma16816(d[mi][2 * g + 1], al[mi], bh[g][1], bh[g][3]);
                }
        }
        __syncthreads();   // A consumed; next-tile idx visible

        // rebuild A for next tile (overlaps epilogue below in issue order)
        if (nxt < NT_EDGE)
            edge_build_A(sm4, buf ^ 1, nxt * 128, msg);

        // -------- register-resident epilogue --------
        {
            const int* s_src = (const int*)(sm4)        + buf * 128;
            const int* s_dst = (const int*)(sm4 + 256)  + buf * 128;
#pragma unroll
            for (int g = 0; g < 4; ++g) {
                const int mi = g >> 1;
                const int c0 = (g & 1) * 2;
                int r = wm * 32 + mi * 16 + (g & 1) * 8 + lr;
                int sn = s_src[r];
                int dn = s_dst[r];
                bool valid = (sn >= 0);
                int sn2 = valid ? sn : 0;
                int dn2 = valid ? dn : 0;

                float2 q2[8], k2[8];
#pragma unroll
                for (int ni = 0; ni < 8; ++ni) {
                    int col = wn * 64 + ni * 8 + l2 * 2;
                    q2[ni] = *(const float2*)(g_q + (size_t)dn2 * 128 + col);
                    k2[ni] = *(const float2*)(g_k + (size_t)sn2 * 128 + col);
                }
                float s = 0.f;
#pragma unroll
                for (int ni = 0; ni < 8; ++ni) {
                    s += q2[ni].x * (k2[ni].x + d[mi][ni][c0]);
                    s += q2[ni].y * (k2[ni].y + d[mi][ni][c0 + 1]);
                }
                s += __shfl_xor_sync(0xffffffffu, s, 1);
                s += __shfl_xor_sync(0xffffffffu, s, 2);
                float alv = __expf(s * 0.125f);

                float2 v2[8];
#pragma unroll
                for (int ni = 0; ni < 8; ++ni) {
                    int col = wn * 64 + ni * 8 + l2 * 2;
                    v2[ni] = *(const float2*)(g_v + (size_t)sn2 * 128 + col);
                }
                if (valid) {
#pragma unroll
                    for (int ni = 0; ni < 8; ++ni) {
                        int col = wn * 64 + ni * 8 + l2 * 2;
                        float ox = (v2[ni].x + d[mi][ni][c0])     * alv;
                        float oy = (v2[ni].y + d[mi][ni][c0 + 1]) * alv;
                        float* p = g_acc + (size_t)dn * 128 + col;
                        asm volatile("red.global.add.v2.f32 [%0], {%1,%2};"
                                     :: "l"(p), "f"(ox), "f"(oy) : "memory");
                    }
                    if (l2 == 0)
                        atomicAdd(&g_asum[dn * 2 + wn], alv);
                }
            }
        }
        __syncthreads();   // A(next) built + epilogue done
        buf ^= 1;
    }
}

// ---------------- final: out = skip + acc / asum ----------------
__global__ void __launch_bounds__(256)
k_final(float* __restrict__ out)
{
    int idx = blockIdx.x * blockDim.x + threadIdx.x;
    if (idx >= N_NODES * 32) return;
    int n  = idx >> 5;
    int c4 = idx & 31;
    int h  = c4 >> 4;
    float inv = 1.f / (g_asum[n * 2 + h] + 1e-16f);
    float4 a = ((const float4*)g_acc)[idx];
    float4 o = ((float4*)out)[idx];
    o.x += a.x * inv; o.y += a.y * inv; o.z += a.z * inv; o.w += a.w * inv;
    ((float4*)out)[idx] = o;
}

// ---------------- launch ----------------
extern "C" void kernel_launch(void* const* d_in, const int* in_sizes, int n_in,
                              void* d_out, int out_size)
{
    const float* x    = (const float*)d_in[0];
    const float* lu   = (const float*)d_in[1];
    const float* t    = (const float*)d_in[2];
    const float* msg  = (const float*)d_in[3];
    const float* tw   = (const float*)d_in[4];
    const float* tb   = (const float*)d_in[5];
    const float* Wq   = (const float*)d_in[6];
    const float* bq   = (const float*)d_in[7];
    const float* Wk   = (const float*)d_in[8];
    const float* bk   = (const float*)d_in[9];
    const float* Wv   = (const float*)d_in[10];
    const float* bv   = (const float*)d_in[11];
    const float* We   = (const float*)d_in[12];
    const float* Wsk  = (const float*)d_in[13];
    const float* bsk  = (const float*)d_in[14];
    const void*  ei   = d_in[15];
    float* out = (float*)d_out;

    cudaFuncSetAttribute(k_node_tc, cudaFuncAttributeMaxDynamicSharedMemorySize, KN_SMEM);
    cudaFuncSetAttribute(k_edge_tc, cudaFuncAttributeMaxDynamicSharedMemorySize, KE_SMEM);

    k_detect<<<1, 256>>>((const int*)ei);                              // my 0
    k_fused<<<FB_TOTAL, 256>>>(ei, We, Wq, Wk, Wv, Wsk);               // my 1
    k_node_tc<<<NT_NODE, 256, KN_SMEM>>>(x, bq, bk, bv, bsk, out);     // my 2
    k_edge_tc<<<152, 256, KE_SMEM>>>(t, lu, msg, tw, tb);              // my 3 (global 5)
    k_final<<<(N_NODES * 32 + 255) / 256, 256>>>(out);                 // my 4
}

// round 9
// speedup vs baseline: 3.2669x; 1.3642x over previous
#include <cuda_runtime.h>
#include <cuda_fp16.h>
#include <cstdint>

#define N_NODES 50000
#define N_EDGES 500000
#define NT_E256 ((N_EDGES + 255) / 256)   // 1954
#define NT_NODE ((N_NODES + 127) / 128)   // 391

// fused prep kernel block ranges
#define FB_CONV  3907
#define FB_ZERO  6250
#define FB_PREP  176
#define FB_TOTAL (FB_CONV + FB_ZERO + FB_PREP)

// ---------------- global scratch ----------------
__device__ float g_q[(size_t)N_NODES * 128];
__device__ float g_k[(size_t)N_NODES * 128];
__device__ float g_v[(size_t)N_NODES * 128];
__device__ float g_acc[(size_t)N_NODES * 128];
__device__ float g_asum[(size_t)N_NODES * 2];
__device__ int   g_edge_i32[(size_t)2 * N_EDGES];
__device__ int   g_is64;
// pre-transposed fp16x2 hi/lo weight images: B[n][k] = W[k][n]
__device__ uint32_t g_imgWe_h[128 * 96], g_imgWe_l[128 * 96];
__device__ uint32_t g_imgW_h[4][128 * 64], g_imgW_l[4][128 * 64];

// ---------------- helpers ----------------
__device__ __forceinline__ uint32_t s2u(const void* p) {
    uint32_t r;
    asm("{ .reg .u64 t; cvta.to.shared.u64 t, %1; cvt.u32.u64 %0, t; }" : "=r"(r) : "l"(p));
    return r;
}

__device__ __forceinline__ void ldsm4(uint32_t* r, uint32_t addr) {
    asm volatile("ldmatrix.sync.aligned.m8n8.x4.shared.b16 {%0,%1,%2,%3}, [%4];"
                 : "=r"(r[0]), "=r"(r[1]), "=r"(r[2]), "=r"(r[3]) : "r"(addr));
}

__device__ __forceinline__ void mma16816(float* d, const uint32_t* a, uint32_t b0, uint32_t b1) {
    asm volatile("mma.sync.aligned.m16n8k16.row.col.f32.f16.f16.f32 "
                 "{%0,%1,%2,%3}, {%4,%5,%6,%7}, {%8,%9}, {%0,%1,%2,%3};"
                 : "+f"(d[0]), "+f"(d[1]), "+f"(d[2]), "+f"(d[3])
                 : "r"(a[0]), "r"(a[1]), "r"(a[2]), "r"(a[3]), "r"(b0), "r"(b1));
}

__device__ __forceinline__ uint32_t packh2(float a, float b) {
    __half2 h = __floats2half2_rn(a, b);
    return *reinterpret_cast<uint32_t*>(&h);
}

__device__ __forceinline__ void splith(float a, float b, uint32_t& hi, uint32_t& lo) {
    __half2 h = __floats2half2_rn(a, b);
    float ra = a - __low2float(h);
    float rb = b - __high2float(h);
    __half2 l = __floats2half2_rn(ra, rb);
    hi = *reinterpret_cast<uint32_t*>(&h);
    lo = *reinterpret_cast<uint32_t*>(&l);
}

// 256-bit streaming load with evict_first
__device__ __forceinline__ void ldg_ef8(const float* p, float* v) {
    uint32_t r0, r1, r2, r3, r4, r5, r6, r7;
    asm("ld.global.L2::evict_first.v8.b32 {%0,%1,%2,%3,%4,%5,%6,%7}, [%8];"
        : "=r"(r0), "=r"(r1), "=r"(r2), "=r"(r3),
          "=r"(r4), "=r"(r5), "=r"(r6), "=r"(r7) : "l"(p));
    v[0] = __uint_as_float(r0); v[1] = __uint_as_float(r1);
    v[2] = __uint_as_float(r2); v[3] = __uint_as_float(r3);
    v[4] = __uint_as_float(r4); v[5] = __uint_as_float(r5);
    v[6] = __uint_as_float(r6); v[7] = __uint_as_float(r7);
}

// ---------------- detect ----------------
__global__ void k_detect(const int* __restrict__ words)
{
    __shared__ int nz;
    if (threadIdx.x == 0) nz = 0;
    __syncthreads();
    int local = 0;
    for (int idx = threadIdx.x; idx < 4096; idx += blockDim.x)
        if (words[2 * idx + 1] != 0) local = 1;
    if (local) atomicOr(&nz, 1);
    __syncthreads();
    if (threadIdx.x == 0) g_is64 = (nz == 0) ? 1 : 0;
}

// ---------------- fused convert + zero + prep ----------------
__global__ void k_fused(const void* __restrict__ ei,
                        const float* __restrict__ We,
                        const float* __restrict__ Wq, const float* __restrict__ Wk,
                        const float* __restrict__ Wv, const float* __restrict__ Ws)
{
    int b = blockIdx.x;
    if (b < FB_CONV) {
        int idx = b * 256 + threadIdx.x;
        if (idx < 2 * N_EDGES) {
            int v;
            if (g_is64) v = (int)((const long long*)ei)[idx];
            else        v = ((const int*)ei)[idx];
            g_edge_i32[idx] = v;
        }
        return;
    }
    b -= FB_CONV;
    if (b < FB_ZERO) {
        int i = b * 256 + threadIdx.x;
        if (i < N_NODES * 2) g_asum[i] = 0.f;
        if (i < N_NODES * 32) ((float4*)g_acc)[i] = make_float4(0.f, 0.f, 0.f, 0.f);
        return;
    }
    b -= FB_ZERO;
    {
        int idx = b * 256 + threadIdx.x;
        if (idx < 12288) {
            int n = idx / 96, p = idx % 96;
            float a = We[(2 * p) * 128 + n];
            float bb = We[(2 * p + 1) * 128 + n];
            uint32_t h, l; splith(a, bb, h, l);
            g_imgWe_h[idx] = h; g_imgWe_l[idx] = l;
        } else if (idx < 45056) {
            int r = idx - 12288;
            int mat = r >> 13;
            int w_  = r & 8191;
            int n = w_ >> 6, p = w_ & 63;
            const float* W = (mat == 0) ? Wq : (mat == 1) ? Wk : (mat == 2) ? Wv : Ws;
            float a = W[(2 * p) * 128 + n];
            float bb = W[(2 * p + 1) * 128 + n];
            uint32_t h, l; splith(a, bb, h, l);
            g_imgW_h[mat][w_] = h; g_imgW_l[mat][w_] = l;
        }
    }
}

// ---------------- node GEMM: fp16 2-pass, one CTA does all 4 matrices ----------------
// SMEM words: AH@0 (128*68), BH@8704, BL@17408; 26112 w = 104448 B
#define KN_SA 68
#define KN_SMEM (26112 * 4)

__global__ void __launch_bounds__(256, 1)
k_node_tc(const float* __restrict__ x,
          const float* __restrict__ bq, const float* __restrict__ bk,
          const float* __restrict__ bv, const float* __restrict__ bs,
          float* __restrict__ out)
{
    extern __shared__ uint32_t sm4[];
    const uint32_t sb = s2u(sm4);
    const int tid = threadIdx.x;
    const int wid = tid >> 5;
    const int lane = tid & 31;
    const int base = blockIdx.x * 128;

    uint32_t* AH = sm4;
    uint32_t* BH = sm4 + 8704;
    uint32_t* BL = sm4 + 17408;

    // A: fp16 hi tile (streamed via v8 evict_first)
    for (int idx = tid; idx < 128 * 16; idx += 256) {
        int i = idx >> 4, p4 = idx & 15;
        int node = base + i;
        float v[8] = {0.f, 0.f, 0.f, 0.f, 0.f, 0.f, 0.f, 0.f};
        if (node < N_NODES) ldg_ef8(x + (size_t)node * 128 + p4 * 8, v);
#pragma unroll
        for (int j = 0; j < 4; ++j)
            AH[i * KN_SA + p4 * 4 + j] = packh2(v[2 * j], v[2 * j + 1]);
    }

    const int wm = wid & 3;
    const int wn = wid >> 2;
    const int lrow = lane & 15;
    const int lk   = (lane >> 4) * 8;
    const int l2   = lane & 3;
    const int lr   = lane >> 2;

    for (int mat = 0; mat < 4; ++mat) {
        {
            const uint4* gh = (const uint4*)g_imgW_h[mat];
            const uint4* gl = (const uint4*)g_imgW_l[mat];
            for (int idx = tid; idx < 128 * 16; idx += 256) {
                int row = idx >> 4, q = idx & 15;
                ((uint4*)(BH + row * KN_SA))[q] = gh[row * 16 + q];
                ((uint4*)(BL + row * KN_SA))[q] = gl[row * 16 + q];
            }
        }
        __syncthreads();

        float d[2][8][4];
#pragma unroll
        for (int mi = 0; mi < 2; ++mi)
#pragma unroll
            for (int ni = 0; ni < 8; ++ni)
#pragma unroll
                for (int c = 0; c < 4; ++c) d[mi][ni][c] = 0.f;

#pragma unroll 2
        for (int ks = 0; ks < 8; ++ks) {
            const int k0 = ks * 16;
            uint32_t ah[2][4];
#pragma unroll
            for (int mi = 0; mi < 2; ++mi) {
                int row = wm * 32 + mi * 16 + lrow;
                ldsm4(ah[mi], sb + (uint32_t)(row * (KN_SA * 4)) + (uint32_t)((k0 + lk) * 2));
            }
#pragma unroll
            for (int g = 0; g < 4; ++g) {
                int n = wn * 64 + g * 16 + lrow;
                uint32_t bo = (uint32_t)(n * (KN_SA * 4)) + (uint32_t)((k0 + lk) * 2);
                uint32_t bh[4], bl[4];
                ldsm4(bh, sb + 8704u * 4u + bo);
                ldsm4(bl, sb + 17408u * 4u + bo);
#pragma unroll
                for (int mi = 0; mi < 2; ++mi) {
                    mma16816(d[mi][2 * g + 0], ah[mi], bh[0], bh[2]);
                    mma16816(d[mi][2 * g + 1], ah[mi], bh[1], bh[3]);
                    mma16816(d[mi][2 * g + 0], ah[mi], bl[0], bl[2]);
                    mma16816(d[mi][2 * g + 1], ah[mi], bl[1], bl[3]);
                }
            }
        }

        const float* bias = (mat == 0) ? bq : (mat == 1) ? bk : (mat == 2) ? bv : bs;
        float* dst        = (mat == 0) ? g_q : (mat == 1) ? g_k : (mat == 2) ? g_v : out;

#pragma unroll
        for (int g = 0; g < 4; ++g) {
            const int mi = g >> 1;
            const int c0 = (g & 1) * 2;
            int r = wm * 32 + mi * 16 + (g & 1) * 8 + lr;
            int node = base + r;
            if (node < N_NODES) {
#pragma unroll
                for (int ni = 0; ni < 8; ++ni) {
                    int col = wn * 64 + ni * 8 + l2 * 2;
                    float2 bb = *(const float2*)(bias + col);
                    float2 o = make_float2(d[mi][ni][c0] + bb.x, d[mi][ni][c0 + 1] + bb.y);
                    *(float2*)(dst + (size_t)node * 128 + col) = o;
                }
            }
        }
        __syncthreads();
    }
}

// ---------------- edge GEMM + attention + scatter (persistent, 256-tile, 512 thr) ----------------
// SMEM words: src[2][256]@0, dst[2][256]@512, rel[2][256]@1024, tw@1536, tb@1600,
// AH@1664 (256*100), BH@27264 (128*100), BL@40064; total 52864 w = 211456 B
#define KE_SA 100
#define KE_SMEM (52864 * 4)
#define AHB (1664u * 4u)
#define BHB (27264u * 4u)
#define BLB (40064u * 4u)

__device__ __forceinline__ void edge_load_idx(uint32_t* sm4, int buf, int base,
                                              const float* __restrict__ t,
                                              const float* __restrict__ lu)
{
    int tid = threadIdx.x;
    if (tid < 256) {
        int*   s_src = (int*)(sm4)         + buf * 256;
        int*   s_dst = (int*)(sm4 + 512)   + buf * 256;
        float* s_rel = (float*)(sm4 + 1024) + buf * 256;
        int edge = base + tid;
        if (edge < N_EDGES) {
            int s = g_edge_i32[edge];
            s_src[tid] = s;
            s_dst[tid] = g_edge_i32[N_EDGES + edge];
            s_rel[tid] = t[edge] - lu[s];
        } else {
            s_src[tid] = -1; s_dst[tid] = 0; s_rel[tid] = 0.f;
        }
    }
}

__device__ __forceinline__ void edge_build_A(uint32_t* sm4, int buf, int base,
                                             const float* __restrict__ msg)
{
    int tid = threadIdx.x;
    float* s_rel = (float*)(sm4 + 1024) + buf * 256;
    float* s_tw  = (float*)(sm4 + 1536);
    float* s_tb  = (float*)(sm4 + 1600);
    uint32_t* AH = sm4 + 1664;
    for (int idx = tid; idx < 256 * 32; idx += 512) {
        int i = idx >> 5, p = idx & 31;
        float rel = s_rel[i];
        float c0 = __cosf(fmaf(rel, s_tw[2 * p],     s_tb[2 * p]));
        float c1 = __cosf(fmaf(rel, s_tw[2 * p + 1], s_tb[2 * p + 1]));
        AH[i * KE_SA + p] = packh2(c0, c1);
    }
    for (int idx = tid; idx < 256 * 16; idx += 512) {
        int i = idx >> 4, p4 = idx & 15;
        int edge = base + i;
        float v[8] = {0.f, 0.f, 0.f, 0.f, 0.f, 0.f, 0.f, 0.f};
        if (edge < N_EDGES) ldg_ef8(msg + (size_t)edge * 128 + p4 * 8, v);
#pragma unroll
        for (int j = 0; j < 4; ++j)
            AH[i * KE_SA + 32 + p4 * 4 + j] = packh2(v[2 * j], v[2 * j + 1]);
    }
}

__global__ void __launch_bounds__(512, 1)
k_edge_tc(const float* __restrict__ t,
          const float* __restrict__ last_update,
          const float* __restrict__ msg,
          const float* __restrict__ time_w,
          const float* __restrict__ time_b)
{
    extern __shared__ uint32_t sm4[];
    const uint32_t sb = s2u(sm4);
    const int tid = threadIdx.x;
    const int wid = tid >> 5;
    const int lane = tid & 31;

    // B images -> SMEM once
    {
        const uint4* gh = (const uint4*)g_imgWe_h;
        const uint4* gl = (const uint4*)g_imgWe_l;
        uint32_t* BH = sm4 + 27264;
        uint32_t* BL = sm4 + 40064;
        for (int idx = tid; idx < 128 * 24; idx += 512) {
            int row = idx / 24, q = idx % 24;
            ((uint4*)(BH + row * KE_SA))[q] = gh[row * 24 + q];
            ((uint4*)(BL + row * KE_SA))[q] = gl[row * 24 + q];
        }
    }
    if (tid < 64) {
        ((float*)(sm4 + 1536))[tid] = time_w[tid];
        ((float*)(sm4 + 1600))[tid] = time_b[tid];
    }
    __syncthreads();

    const int wm = wid & 7;      // 8 m-blocks of 32 rows (256-edge tile)
    const int wn = wid >> 3;     // 2 n-blocks = heads
    const int lrow = lane & 15;
    const int lk   = (lane >> 4) * 8;
    const int l2   = lane & 3;
    const int lr   = lane >> 2;

    int tile = blockIdx.x;
    if (tile < NT_E256) {
        edge_load_idx(sm4, 0, tile * 256, t, last_update);
        __syncthreads();
        edge_build_A(sm4, 0, tile * 256, msg);
    }
    __syncthreads();

    int buf = 0;
    for (; tile < NT_E256; tile += gridDim.x) {
        int nxt = tile + gridDim.x;
        if (nxt < NT_E256)
            edge_load_idx(sm4, buf ^ 1, nxt * 256, t, last_update);

        // -------- MMA: fp16 2-pass (AhBh + AhBl) --------
        float d[2][8][4];
#pragma unroll
        for (int mi = 0; mi < 2; ++mi)
#pragma unroll
            for (int ni = 0; ni < 8; ++ni)
#pragma unroll
                for (int c = 0; c < 4; ++c) d[mi][ni][c] = 0.f;

#pragma unroll 2
        for (int ks = 0; ks < 12; ++ks) {
            const int k0 = ks * 16;
            uint32_t ah[2][4];
#pragma unroll
            for (int mi = 0; mi < 2; ++mi) {
                int row = wm * 32 + mi * 16 + lrow;
                ldsm4(ah[mi], sb + AHB + (uint32_t)(row * (KE_SA * 4)) + (uint32_t)((k0 + lk) * 2));
            }
#pragma unroll
            for (int g = 0; g < 4; ++g) {
                int n = wn * 64 + g * 16 + lrow;
                uint32_t bo = (uint32_t)(n * (KE_SA * 4)) + (uint32_t)((k0 + lk) * 2);
                uint32_t bh[4], bl[4];
                ldsm4(bh, sb + BHB + bo);
                ldsm4(bl, sb + BLB + bo);
#pragma unroll
                for (int mi = 0; mi < 2; ++mi) {
                    mma16816(d[mi][2 * g + 0], ah[mi], bh[0], bh[2]);
                    mma16816(d[mi][2 * g + 1], ah[mi], bh[1], bh[3]);
                    mma16816(d[mi][2 * g + 0], ah[mi], bl[0], bl[2]);
                    mma16816(d[mi][2 * g + 1], ah[mi], bl[1], bl[3]);
                }
            }
        }
        __syncthreads();   // A consumed; next-tile idx visible

        // rebuild A for next tile (overlaps epilogue in issue order)
        if (nxt < NT_E256)
            edge_build_A(sm4, buf ^ 1, nxt * 256, msg);

        // -------- register-resident epilogue --------
        {
            const int* s_src = (const int*)(sm4)       + buf * 256;
            const int* s_dst = (const int*)(sm4 + 512) + buf * 256;
#pragma unroll
            for (int g = 0; g < 4; ++g) {
                const int mi = g >> 1;
                const int c0 = (g & 1) * 2;
                int r = wm * 32 + mi * 16 + (g & 1) * 8 + lr;
                int sn = s_src[r];
                int dn = s_dst[r];
                bool valid = (sn >= 0);
                int sn2 = valid ? sn : 0;
                int dn2 = valid ? dn : 0;

                float2 q2[8], k2[8];
#pragma unroll
                for (int ni = 0; ni < 8; ++ni) {
                    int col = wn * 64 + ni * 8 + l2 * 2;
                    q2[ni] = *(const float2*)(g_q + (size_t)dn2 * 128 + col);
                    k2[ni] = *(const float2*)(g_k + (size_t)sn2 * 128 + col);
                }
                float s = 0.f;
#pragma unroll
                for (int ni = 0; ni < 8; ++ni) {
                    s += q2[ni].x * (k2[ni].x + d[mi][ni][c0]);
                    s += q2[ni].y * (k2[ni].y + d[mi][ni][c0 + 1]);
                }
                s += __shfl_xor_sync(0xffffffffu, s, 1);
                s += __shfl_xor_sync(0xffffffffu, s, 2);
                float alv = __expf(s * 0.125f);

                float2 v2[8];
#pragma unroll
                for (int ni = 0; ni < 8; ++ni) {
                    int col = wn * 64 + ni * 8 + l2 * 2;
                    v2[ni] = *(const float2*)(g_v + (size_t)sn2 * 128 + col);
                }
                if (valid) {
#pragma unroll
                    for (int ni = 0; ni < 8; ++ni) {
                        int col = wn * 64 + ni * 8 + l2 * 2;
                        float ox = (v2[ni].x + d[mi][ni][c0])     * alv;
                        float oy = (v2[ni].y + d[mi][ni][c0 + 1]) * alv;
                        float* p = g_acc + (size_t)dn * 128 + col;
                        asm volatile("red.global.add.v2.f32 [%0], {%1,%2};"
                                     :: "l"(p), "f"(ox), "f"(oy) : "memory");
                    }
                    if (l2 == 0)
                        atomicAdd(&g_asum[dn * 2 + wn], alv);
                }
            }
        }
        __syncthreads();   // A(next) built + epilogue done
        buf ^= 1;
    }
}

// ---------------- final: out = skip + acc / asum ----------------
__global__ void __launch_bounds__(256)
k_final(float* __restrict__ out)
{
    int idx = blockIdx.x * blockDim.x + threadIdx.x;
    if (idx >= N_NODES * 32) return;
    int n  = idx >> 5;
    int c4 = idx & 31;
    int h  = c4 >> 4;
    float inv = 1.f / (g_asum[n * 2 + h] + 1e-16f);
    float4 a = ((const float4*)g_acc)[idx];
    float4 o = ((float4*)out)[idx];
    o.x += a.x * inv; o.y += a.y * inv; o.z += a.z * inv; o.w += a.w * inv;
    ((float4*)out)[idx] = o;
}

// ---------------- launch ----------------
extern "C" void kernel_launch(void* const* d_in, const int* in_sizes, int n_in,
                              void* d_out, int out_size)
{
    const float* x    = (const float*)d_in[0];
    const float* lu   = (const float*)d_in[1];
    const float* t    = (const float*)d_in[2];
    const float* msg  = (const float*)d_in[3];
    const float* tw   = (const float*)d_in[4];
    const float* tb   = (const float*)d_in[5];
    const float* Wq   = (const float*)d_in[6];
    const float* bq   = (const float*)d_in[7];
    const float* Wk   = (const float*)d_in[8];
    const float* bk   = (const float*)d_in[9];
    const float* Wv   = (const float*)d_in[10];
    const float* bv   = (const float*)d_in[11];
    const float* We   = (const float*)d_in[12];
    const float* Wsk  = (const float*)d_in[13];
    const float* bsk  = (const float*)d_in[14];
    const void*  ei   = d_in[15];
    float* out = (float*)d_out;

    cudaFuncSetAttribute(k_node_tc, cudaFuncAttributeMaxDynamicSharedMemorySize, KN_SMEM);
    cudaFuncSetAttribute(k_edge_tc, cudaFuncAttributeMaxDynamicSharedMemorySize, KE_SMEM);

    k_detect<<<1, 256>>>((const int*)ei);                              // my 0
    k_fused<<<FB_TOTAL, 256>>>(ei, We, Wq, Wk, Wv, Wsk);               // my 1
    k_node_tc<<<NT_NODE, 256, KN_SMEM>>>(x, bq, bk, bv, bsk, out);     // my 2
    k_edge_tc<<<152, 512, KE_SMEM>>>(t, lu, msg, tw, tb);              // my 3 (global 5)
    k_final<<<(N_NODES * 32 + 255) / 256, 256>>>(out);                 // my 4
}

// round 10
// speedup vs baseline: 3.8602x; 1.1816x over previous
#include <cuda_runtime.h>
#include <cuda_fp16.h>
#include <cstdint>

#define N_NODES 50000
#define N_EDGES 500000
#define NT_EDGE ((N_EDGES + 127) / 128)   // 3907 tiles of 128
#define NT_NODE ((N_NODES + 127) / 128)   // 391

// fused prep kernel block ranges
#define FB_CONV  3907
#define FB_ZERO  6250
#define FB_PREP  176
#define FB_TOTAL (FB_CONV + FB_ZERO + FB_PREP)

// ---------------- global scratch ----------------
__device__ float g_q[(size_t)N_NODES * 128];
__device__ float g_k[(size_t)N_NODES * 128];
__device__ float g_v[(size_t)N_NODES * 128];
__device__ float g_acc[(size_t)N_NODES * 128];
__device__ float g_asum[(size_t)N_NODES * 2];
__device__ int   g_edge_i32[(size_t)2 * N_EDGES];
__device__ int   g_is64;
// pre-transposed fp16x2 weight images: B[n][k] = W[k][n]
__device__ uint32_t g_imgWe_h[128 * 96];                      // edge B (hi only)
__device__ uint32_t g_imgW_h[4][128 * 64], g_imgW_l[4][128 * 64]; // node B hi/lo

// ---------------- helpers ----------------
__device__ __forceinline__ uint32_t s2u(const void* p) {
    uint32_t r;
    asm("{ .reg .u64 t; cvta.to.shared.u64 t, %1; cvt.u32.u64 %0, t; }" : "=r"(r) : "l"(p));
    return r;
}

__device__ __forceinline__ void ldsm4(uint32_t* r, uint32_t addr) {
    asm volatile("ldmatrix.sync.aligned.m8n8.x4.shared.b16 {%0,%1,%2,%3}, [%4];"
                 : "=r"(r[0]), "=r"(r[1]), "=r"(r[2]), "=r"(r[3]) : "r"(addr));
}

__device__ __forceinline__ void mma16816(float* d, const uint32_t* a, uint32_t b0, uint32_t b1) {
    asm volatile("mma.sync.aligned.m16n8k16.row.col.f32.f16.f16.f32 "
                 "{%0,%1,%2,%3}, {%4,%5,%6,%7}, {%8,%9}, {%0,%1,%2,%3};"
                 : "+f"(d[0]), "+f"(d[1]), "+f"(d[2]), "+f"(d[3])
                 : "r"(a[0]), "r"(a[1]), "r"(a[2]), "r"(a[3]), "r"(b0), "r"(b1));
}

__device__ __forceinline__ uint32_t packh2(float a, float b) {
    __half2 h = __floats2half2_rn(a, b);
    return *reinterpret_cast<uint32_t*>(&h);
}

__device__ __forceinline__ void splith(float a, float b, uint32_t& hi, uint32_t& lo) {
    __half2 h = __floats2half2_rn(a, b);
    float ra = a - __low2float(h);
    float rb = b - __high2float(h);
    __half2 l = __floats2half2_rn(ra, rb);
    hi = *reinterpret_cast<uint32_t*>(&h);
    lo = *reinterpret_cast<uint32_t*>(&l);
}

// 256-bit streaming load with evict_first
__device__ __forceinline__ void ldg_ef8(const float* p, float* v) {
    uint32_t r0, r1, r2, r3, r4, r5, r6, r7;
    asm("ld.global.L2::evict_first.v8.b32 {%0,%1,%2,%3,%4,%5,%6,%7}, [%8];"
        : "=r"(r0), "=r"(r1), "=r"(r2), "=r"(r3),
          "=r"(r4), "=r"(r5), "=r"(r6), "=r"(r7) : "l"(p));
    v[0] = __uint_as_float(r0); v[1] = __uint_as_float(r1);
    v[2] = __uint_as_float(r2); v[3] = __uint_as_float(r3);
    v[4] = __uint_as_float(r4); v[5] = __uint_as_float(r5);
    v[6] = __uint_as_float(r6); v[7] = __uint_as_float(r7);
}

// ---------------- detect ----------------
__global__ void k_detect(const int* __restrict__ words)
{
    __shared__ int nz;
    if (threadIdx.x == 0) nz = 0;
    __syncthreads();
    int local = 0;
    for (int idx = threadIdx.x; idx < 4096; idx += blockDim.x)
        if (words[2 * idx + 1] != 0) local = 1;
    if (local) atomicOr(&nz, 1);
    __syncthreads();
    if (threadIdx.x == 0) g_is64 = (nz == 0) ? 1 : 0;
}

// ---------------- fused convert + zero + prep ----------------
__global__ void k_fused(const void* __restrict__ ei,
                        const float* __restrict__ We,
                        const float* __restrict__ Wq, const float* __restrict__ Wk,
                        const float* __restrict__ Wv, const float* __restrict__ Ws)
{
    int b = blockIdx.x;
    if (b < FB_CONV) {
        int idx = b * 256 + threadIdx.x;
        if (idx < 2 * N_EDGES) {
            int v;
            if (g_is64) v = (int)((const long long*)ei)[idx];
            else        v = ((const int*)ei)[idx];
            g_edge_i32[idx] = v;
        }
        return;
    }
    b -= FB_CONV;
    if (b < FB_ZERO) {
        int i = b * 256 + threadIdx.x;
        if (i < N_NODES * 2) g_asum[i] = 0.f;
        if (i < N_NODES * 32) ((float4*)g_acc)[i] = make_float4(0.f, 0.f, 0.f, 0.f);
        return;
    }
    b -= FB_ZERO;
    {
        int idx = b * 256 + threadIdx.x;
        if (idx < 12288) {
            int n = idx / 96, p = idx % 96;
            float a = We[(2 * p) * 128 + n];
            float bb = We[(2 * p + 1) * 128 + n];
            g_imgWe_h[idx] = packh2(a, bb);
        } else if (idx < 45056) {
            int r = idx - 12288;
            int mat = r >> 13;
            int w_  = r & 8191;
            int n = w_ >> 6, p = w_ & 63;
            const float* W = (mat == 0) ? Wq : (mat == 1) ? Wk : (mat == 2) ? Wv : Ws;
            float a = W[(2 * p) * 128 + n];
            float bb = W[(2 * p + 1) * 128 + n];
            uint32_t h, l; splith(a, bb, h, l);
            g_imgW_h[mat][w_] = h; g_imgW_l[mat][w_] = l;
        }
    }
}

// ---------------- node GEMM: fp16 2-pass (B compensated), all 4 matrices ----------------
#define KN_SA 68
#define KN_SMEM (26112 * 4)

__global__ void __launch_bounds__(256, 1)
k_node_tc(const float* __restrict__ x,
          const float* __restrict__ bq, const float* __restrict__ bk,
          const float* __restrict__ bv, const float* __restrict__ bs,
          float* __restrict__ out)
{
    extern __shared__ uint32_t sm4[];
    const uint32_t sb = s2u(sm4);
    const int tid = threadIdx.x;
    const int wid = tid >> 5;
    const int lane = tid & 31;
    const int base = blockIdx.x * 128;

    uint32_t* AH = sm4;
    uint32_t* BH = sm4 + 8704;
    uint32_t* BL = sm4 + 17408;

    for (int idx = tid; idx < 128 * 16; idx += 256) {
        int i = idx >> 4, p4 = idx & 15;
        int node = base + i;
        float v[8] = {0.f, 0.f, 0.f, 0.f, 0.f, 0.f, 0.f, 0.f};
        if (node < N_NODES) ldg_ef8(x + (size_t)node * 128 + p4 * 8, v);
#pragma unroll
        for (int j = 0; j < 4; ++j)
            AH[i * KN_SA + p4 * 4 + j] = packh2(v[2 * j], v[2 * j + 1]);
    }

    const int wm = wid & 3;
    const int wn = wid >> 2;
    const int lrow = lane & 15;
    const int lk   = (lane >> 4) * 8;
    const int l2   = lane & 3;
    const int lr   = lane >> 2;

    for (int mat = 0; mat < 4; ++mat) {
        {
            const uint4* gh = (const uint4*)g_imgW_h[mat];
            const uint4* gl = (const uint4*)g_imgW_l[mat];
            for (int idx = tid; idx < 128 * 16; idx += 256) {
                int row = idx >> 4, q = idx & 15;
                ((uint4*)(BH + row * KN_SA))[q] = gh[row * 16 + q];
                ((uint4*)(BL + row * KN_SA))[q] = gl[row * 16 + q];
            }
        }
        __syncthreads();

        float d[2][8][4];
#pragma unroll
        for (int mi = 0; mi < 2; ++mi)
#pragma unroll
            for (int ni = 0; ni < 8; ++ni)
#pragma unroll
                for (int c = 0; c < 4; ++c) d[mi][ni][c] = 0.f;

#pragma unroll 2
        for (int ks = 0; ks < 8; ++ks) {
            const int k0 = ks * 16;
            uint32_t ah[2][4];
#pragma unroll
            for (int mi = 0; mi < 2; ++mi) {
                int row = wm * 32 + mi * 16 + lrow;
                ldsm4(ah[mi], sb + (uint32_t)(row * (KN_SA * 4)) + (uint32_t)((k0 + lk) * 2));
            }
#pragma unroll
            for (int g = 0; g < 4; ++g) {
                int n = wn * 64 + g * 16 + lrow;
                uint32_t bo = (uint32_t)(n * (KN_SA * 4)) + (uint32_t)((k0 + lk) * 2);
                uint32_t bh[4], bl[4];
                ldsm4(bh, sb + 8704u * 4u + bo);
                ldsm4(bl, sb + 17408u * 4u + bo);
#pragma unroll
                for (int mi = 0; mi < 2; ++mi) {
                    mma16816(d[mi][2 * g + 0], ah[mi], bh[0], bh[2]);
                    mma16816(d[mi][2 * g + 1], ah[mi], bh[1], bh[3]);
                    mma16816(d[mi][2 * g + 0], ah[mi], bl[0], bl[2]);
                    mma16816(d[mi][2 * g + 1], ah[mi], bl[1], bl[3]);
                }
            }
        }

        const float* bias = (mat == 0) ? bq : (mat == 1) ? bk : (mat == 2) ? bv : bs;
        float* dst        = (mat == 0) ? g_q : (mat == 1) ? g_k : (mat == 2) ? g_v : out;

#pragma unroll
        for (int g = 0; g < 4; ++g) {
            const int mi = g >> 1;
            const int c0 = (g & 1) * 2;
            int r = wm * 32 + mi * 16 + (g & 1) * 8 + lr;
            int node = base + r;
            if (node < N_NODES) {
#pragma unroll
                for (int ni = 0; ni < 8; ++ni) {
                    int col = wn * 64 + ni * 8 + l2 * 2;
                    float2 bb = *(const float2*)(bias + col);
                    float2 o = make_float2(d[mi][ni][c0] + bb.x, d[mi][ni][c0 + 1] + bb.y);
                    *(float2*)(dst + (size_t)node * 128 + col) = o;
                }
            }
        }
        __syncthreads();
    }
}

// ---------------- edge GEMM + attention + scatter (persistent, 128-tile, 2 CTA/SM) ----------------
// SMEM words: src[2][128]@0(256), dst@256(256), rel@512(256), tw@768, tb@832,
// AH@896 (128*100=12800), BH@13696 (12800); total 26496 w = 105984 B
#define KE_SA 100
#define KE_SMEM (26496 * 4)
#define AHB (896u * 4u)
#define BHB (13696u * 4u)

__device__ __forceinline__ void edge_load_idx(uint32_t* sm4, int buf, int base,
                                              const float* __restrict__ t,
                                              const float* __restrict__ lu)
{
    int tid = threadIdx.x;
    if (tid < 128) {
        int*   s_src = (int*)(sm4)        + buf * 128;
        int*   s_dst = (int*)(sm4 + 256)  + buf * 128;
        float* s_rel = (float*)(sm4 + 512) + buf * 128;
        int edge = base + tid;
        if (edge < N_EDGES) {
            int s = g_edge_i32[edge];
            s_src[tid] = s;
            s_dst[tid] = g_edge_i32[N_EDGES + edge];
            s_rel[tid] = t[edge] - lu[s];
        } else {
            s_src[tid] = -1; s_dst[tid] = 0; s_rel[tid] = 0.f;
        }
    }
}

__device__ __forceinline__ void edge_build_A(uint32_t* sm4, int buf, int base,
                                             const float* __restrict__ msg)
{
    int tid = threadIdx.x;
    float* s_rel = (float*)(sm4 + 512) + buf * 128;
    float* s_tw  = (float*)(sm4 + 768);
    float* s_tb  = (float*)(sm4 + 832);
    uint32_t* AH = sm4 + 896;
    for (int idx = tid; idx < 128 * 32; idx += 256) {
        int i = idx >> 5, p = idx & 31;
        float rel = s_rel[i];
        float c0 = __cosf(fmaf(rel, s_tw[2 * p],     s_tb[2 * p]));
        float c1 = __cosf(fmaf(rel, s_tw[2 * p + 1], s_tb[2 * p + 1]));
        AH[i * KE_SA + p] = packh2(c0, c1);
    }
    for (int idx = tid; idx < 128 * 16; idx += 256) {
        int i = idx >> 4, p4 = idx & 15;
        int edge = base + i;
        float v[8] = {0.f, 0.f, 0.f, 0.f, 0.f, 0.f, 0.f, 0.f};
        if (edge < N_EDGES) ldg_ef8(msg + (size_t)edge * 128 + p4 * 8, v);
#pragma unroll
        for (int j = 0; j < 4; ++j)
            AH[i * KE_SA + 32 + p4 * 4 + j] = packh2(v[2 * j], v[2 * j + 1]);
    }
}

__global__ void __launch_bounds__(256, 2)
k_edge_tc(const float* __restrict__ t,
          const float* __restrict__ last_update,
          const float* __restrict__ msg,
          const float* __restrict__ time_w,
          const float* __restrict__ time_b)
{
    extern __shared__ uint32_t sm4[];
    const uint32_t sb = s2u(sm4);
    const int tid = threadIdx.x;
    const int wid = tid >> 5;
    const int lane = tid & 31;

    // B image -> SMEM once (hi only)
    {
        const uint4* gh = (const uint4*)g_imgWe_h;
        uint32_t* BH = sm4 + 13696;
        for (int idx = tid; idx < 128 * 24; idx += 256) {
            int row = idx / 24, q = idx % 24;
            ((uint4*)(BH + row * KE_SA))[q] = gh[row * 24 + q];
        }
    }
    if (tid < 64) {
        ((float*)(sm4 + 768))[tid] = time_w[tid];
        ((float*)(sm4 + 832))[tid] = time_b[tid];
    }
    __syncthreads();

    const int wm = wid & 3;      // 4 m-blocks of 32 rows
    const int wn = wid >> 2;     // 2 heads
    const int lrow = lane & 15;
    const int lk   = (lane >> 4) * 8;
    const int l2   = lane & 3;
    const int lr   = lane >> 2;

    int tile = blockIdx.x;
    if (tile < NT_EDGE) {
        edge_load_idx(sm4, 0, tile * 128, t, last_update);
        __syncthreads();
        edge_build_A(sm4, 0, tile * 128, msg);
    }
    __syncthreads();

    int buf = 0;
    for (; tile < NT_EDGE; tile += gridDim.x) {
        int nxt = tile + gridDim.x;
        if (nxt < NT_EDGE)
            edge_load_idx(sm4, buf ^ 1, nxt * 128, t, last_update);

        // -------- MMA: fp16 single pass --------
        float d[2][8][4];
#pragma unroll
        for (int mi = 0; mi < 2; ++mi)
#pragma unroll
            for (int ni = 0; ni < 8; ++ni)
#pragma unroll
                for (int c = 0; c < 4; ++c) d[mi][ni][c] = 0.f;

#pragma unroll 3
        for (int ks = 0; ks < 12; ++ks) {
            const int k0 = ks * 16;
            uint32_t ah[2][4];
#pragma unroll
            for (int mi = 0; mi < 2; ++mi) {
                int row = wm * 32 + mi * 16 + lrow;
                ldsm4(ah[mi], sb + AHB + (uint32_t)(row * (KE_SA * 4)) + (uint32_t)((k0 + lk) * 2));
            }
#pragma unroll
            for (int g = 0; g < 4; ++g) {
                int n = wn * 64 + g * 16 + lrow;
                uint32_t bh[4];
                ldsm4(bh, sb + BHB + (uint32_t)(n * (KE_SA * 4)) + (uint32_t)((k0 + lk) * 2));
#pragma unroll
                for (int mi = 0; mi < 2; ++mi) {
                    mma16816(d[mi][2 * g + 0], ah[mi], bh[0], bh[2]);
                    mma16816(d[mi][2 * g + 1], ah[mi], bh[1], bh[3]);
                }
            }
        }
        __syncthreads();   // A consumed; next-tile idx visible

        // rebuild A for next tile (overlaps epilogue in issue order)
        if (nxt < NT_EDGE)
            edge_build_A(sm4, buf ^ 1, nxt * 128, msg);

        // -------- register-resident epilogue with v4 atomic combining --------
        {
            const int* s_src = (const int*)(sm4)       + buf * 128;
            const int* s_dst = (const int*)(sm4 + 256) + buf * 128;
#pragma unroll
            for (int g = 0; g < 4; ++g) {
                const int mi = g >> 1;
                const int c0 = (g & 1) * 2;
                int r = wm * 32 + mi * 16 + (g & 1) * 8 + lr;
                int sn = s_src[r];
                int dn = s_dst[r];
                bool valid = (sn >= 0);
                int sn2 = valid ? sn : 0;
                int dn2 = valid ? dn : 0;

                float2 q2[8], k2[8];
#pragma unroll
                for (int ni = 0; ni < 8; ++ni) {
                    int col = wn * 64 + ni * 8 + l2 * 2;
                    q2[ni] = *(const float2*)(g_q + (size_t)dn2 * 128 + col);
                    k2[ni] = *(const float2*)(g_k + (size_t)sn2 * 128 + col);
                }
                float s = 0.f;
#pragma unroll
                for (int ni = 0; ni < 8; ++ni) {
                    s += q2[ni].x * (k2[ni].x + d[mi][ni][c0]);
                    s += q2[ni].y * (k2[ni].y + d[mi][ni][c0 + 1]);
                }
                s += __shfl_xor_sync(0xffffffffu, s, 1);
                s += __shfl_xor_sync(0xffffffffu, s, 2);
                float alv = __expf(s * 0.125f);

                float2 v2[8];
#pragma unroll
                for (int ni = 0; ni < 8; ++ni) {
                    int col = wn * 64 + ni * 8 + l2 * 2;
                    v2[ni] = *(const float2*)(g_v + (size_t)sn2 * 128 + col);
                }
#pragma unroll
                for (int ni = 0; ni < 8; ++ni) {
                    float ox = (v2[ni].x + d[mi][ni][c0])     * alv;
                    float oy = (v2[ni].y + d[mi][ni][c0 + 1]) * alv;
                    float px = __shfl_xor_sync(0xffffffffu, ox, 1);
                    float py = __shfl_xor_sync(0xffffffffu, oy, 1);
                    if (valid && (lane & 1) == 0) {
                        int colb = wn * 64 + ni * 8 + (l2 >> 1) * 4;
                        float* p = g_acc + (size_t)dn * 128 + colb;
                        asm volatile("red.global.add.v4.f32 [%0], {%1,%2,%3,%4};"
                                     :: "l"(p), "f"(ox), "f"(oy), "f"(px), "f"(py) : "memory");
                    }
                }
                if (valid && l2 == 0)
                    atomicAdd(&g_asum[dn * 2 + wn], alv);
            }
        }
        __syncthreads();   // A(next) built + epilogue done
        buf ^= 1;
    }
}

// ---------------- final: out = skip + acc / asum ----------------
__global__ void __launch_bounds__(256)
k_final(float* __restrict__ out)
{
    int idx = blockIdx.x * blockDim.x + threadIdx.x;
    if (idx >= N_NODES * 32) return;
    int n  = idx >> 5;
    int c4 = idx & 31;
    int h  = c4 >> 4;
    float inv = 1.f / (g_asum[n * 2 + h] + 1e-16f);
    float4 a = ((const float4*)g_acc)[idx];
    float4 o = ((float4*)out)[idx];
    o.x += a.x * inv; o.y += a.y * inv; o.z += a.z * inv; o.w += a.w * inv;
    ((float4*)out)[idx] = o;
}

// ---------------- launch ----------------
extern "C" void kernel_launch(void* const* d_in, const int* in_sizes, int n_in,
                              void* d_out, int out_size)
{
    const float* x    = (const float*)d_in[0];
    const float* lu   = (const float*)d_in[1];
    const float* t    = (const float*)d_in[2];
    const float* msg  = (const float*)d_in[3];
    const float* tw   = (const float*)d_in[4];
    const float* tb   = (const float*)d_in[5];
    const float* Wq   = (const float*)d_in[6];
    const float* bq   = (const float*)d_in[7];
    const float* Wk   = (const float*)d_in[8];
    const float* bk   = (const float*)d_in[9];
    const float* Wv   = (const float*)d_in[10];
    const float* bv   = (const float*)d_in[11];
    const float* We   = (const float*)d_in[12];
    const float* Wsk  = (const float*)d_in[13];
    const float* bsk  = (const float*)d_in[14];
    const void*  ei   = d_in[15];
    float* out = (float*)d_out;

    cudaFuncSetAttribute(k_node_tc, cudaFuncAttributeMaxDynamicSharedMemorySize, KN_SMEM);
    cudaFuncSetAttribute(k_edge_tc, cudaFuncAttributeMaxDynamicSharedMemorySize, KE_SMEM);

    k_detect<<<1, 256>>>((const int*)ei);                              // my 0
    k_fused<<<FB_TOTAL, 256>>>(ei, We, Wq, Wk, Wv, Wsk);               // my 1
    k_node_tc<<<NT_NODE, 256, KN_SMEM>>>(x, bq, bk, bv, bsk, out);     // my 2
    k_edge_tc<<<304, 256, KE_SMEM>>>(t, lu, msg, tw, tb);              // my 3 (global 5)
    k_final<<<(N_NODES * 32 + 255) / 256, 256>>>(out);                 // my 4
}

// round 11
// speedup vs baseline: 4.5256x; 1.1724x over previous
#include <cuda_runtime.h>
#include <cuda_fp16.h>
#include <cstdint>

#define N_NODES 50000
#define N_EDGES 500000
#define NT_EDGE ((N_EDGES + 127) / 128)   // 3907
#define NT_NODE ((N_NODES + 127) / 128)   // 391

#define FB_CONV  3907
#define FB_ZERO  6250
#define FB_PREP  176
#define FB_TOTAL (FB_CONV + FB_ZERO + FB_PREP)

// ---------------- global scratch ----------------
// q/k/v stored as packed fp16 (half2 per uint32): node*64 + col/2
__device__ uint32_t g_qh[(size_t)N_NODES * 64];
__device__ uint32_t g_kh[(size_t)N_NODES * 64];
__device__ uint32_t g_vh[(size_t)N_NODES * 64];
__device__ float g_acc[(size_t)N_NODES * 128];
__device__ float g_asum[(size_t)N_NODES * 2];
__device__ int   g_edge_i32[(size_t)2 * N_EDGES];
__device__ int   g_is64;
__device__ uint32_t g_imgWe_h[128 * 96];                          // edge B (hi only)
__device__ uint32_t g_imgW_h[4][128 * 64], g_imgW_l[4][128 * 64]; // node B hi/lo

// ---------------- helpers ----------------
__device__ __forceinline__ uint32_t s2u(const void* p) {
    uint32_t r;
    asm("{ .reg .u64 t; cvta.to.shared.u64 t, %1; cvt.u32.u64 %0, t; }" : "=r"(r) : "l"(p));
    return r;
}

__device__ __forceinline__ void ldsm4(uint32_t* r, uint32_t addr) {
    asm volatile("ldmatrix.sync.aligned.m8n8.x4.shared.b16 {%0,%1,%2,%3}, [%4];"
                 : "=r"(r[0]), "=r"(r[1]), "=r"(r[2]), "=r"(r[3]) : "r"(addr));
}

__device__ __forceinline__ void mma16816(float* d, const uint32_t* a, uint32_t b0, uint32_t b1) {
    asm volatile("mma.sync.aligned.m16n8k16.row.col.f32.f16.f16.f32 "
                 "{%0,%1,%2,%3}, {%4,%5,%6,%7}, {%8,%9}, {%0,%1,%2,%3};"
                 : "+f"(d[0]), "+f"(d[1]), "+f"(d[2]), "+f"(d[3])
                 : "r"(a[0]), "r"(a[1]), "r"(a[2]), "r"(a[3]), "r"(b0), "r"(b1));
}

__device__ __forceinline__ uint32_t packh2(float a, float b) {
    __half2 h = __floats2half2_rn(a, b);
    return *reinterpret_cast<uint32_t*>(&h);
}

__device__ __forceinline__ float2 unpackh2(uint32_t u) {
    return __half22float2(*reinterpret_cast<__half2*>(&u));
}

__device__ __forceinline__ void splith(float a, float b, uint32_t& hi, uint32_t& lo) {
    __half2 h = __floats2half2_rn(a, b);
    float ra = a - __low2float(h);
    float rb = b - __high2float(h);
    __half2 l = __floats2half2_rn(ra, rb);
    hi = *reinterpret_cast<uint32_t*>(&h);
    lo = *reinterpret_cast<uint32_t*>(&l);
}

__device__ __forceinline__ void ldg_ef8(const float* p, float* v) {
    uint32_t r0, r1, r2, r3, r4, r5, r6, r7;
    asm("ld.global.L2::evict_first.v8.b32 {%0,%1,%2,%3,%4,%5,%6,%7}, [%8];"
        : "=r"(r0), "=r"(r1), "=r"(r2), "=r"(r3),
          "=r"(r4), "=r"(r5), "=r"(r6), "=r"(r7) : "l"(p));
    v[0] = __uint_as_float(r0); v[1] = __uint_as_float(r1);
    v[2] = __uint_as_float(r2); v[3] = __uint_as_float(r3);
    v[4] = __uint_as_float(r4); v[5] = __uint_as_float(r5);
    v[6] = __uint_as_float(r6); v[7] = __uint_as_float(r7);
}

// ---------------- detect ----------------
__global__ void k_detect(const int* __restrict__ words)
{
    __shared__ int nz;
    if (threadIdx.x == 0) nz = 0;
    __syncthreads();
    int local = 0;
    for (int idx = threadIdx.x; idx < 4096; idx += blockDim.x)
        if (words[2 * idx + 1] != 0) local = 1;
    if (local) atomicOr(&nz, 1);
    __syncthreads();
    if (threadIdx.x == 0) g_is64 = (nz == 0) ? 1 : 0;
}

// ---------------- fused convert + zero + prep ----------------
__global__ void k_fused(const void* __restrict__ ei,
                        const float* __restrict__ We,
                        const float* __restrict__ Wq, const float* __restrict__ Wk,
                        const float* __restrict__ Wv, const float* __restrict__ Ws)
{
    int b = blockIdx.x;
    if (b < FB_CONV) {
        int idx = b * 256 + threadIdx.x;
        if (idx < 2 * N_EDGES) {
            int v;
            if (g_is64) v = (int)((const long long*)ei)[idx];
            else        v = ((const int*)ei)[idx];
            g_edge_i32[idx] = v;
        }
        return;
    }
    b -= FB_CONV;
    if (b < FB_ZERO) {
        int i = b * 256 + threadIdx.x;
        if (i < N_NODES * 2) g_asum[i] = 0.f;
        if (i < N_NODES * 32) ((float4*)g_acc)[i] = make_float4(0.f, 0.f, 0.f, 0.f);
        return;
    }
    b -= FB_ZERO;
    {
        int idx = b * 256 + threadIdx.x;
        if (idx < 12288) {
            int n = idx / 96, p = idx % 96;
            float a = We[(2 * p) * 128 + n];
            float bb = We[(2 * p + 1) * 128 + n];
            g_imgWe_h[idx] = packh2(a, bb);
        } else if (idx < 45056) {
            int r = idx - 12288;
            int mat = r >> 13;
            int w_  = r & 8191;
            int n = w_ >> 6, p = w_ & 63;
            const float* W = (mat == 0) ? Wq : (mat == 1) ? Wk : (mat == 2) ? Wv : Ws;
            float a = W[(2 * p) * 128 + n];
            float bb = W[(2 * p + 1) * 128 + n];
            uint32_t h, l; splith(a, bb, h, l);
            g_imgW_h[mat][w_] = h; g_imgW_l[mat][w_] = l;
        }
    }
}

// ---------------- node GEMM: fp16 2-pass (B compensated), all 4 matrices ----------------
#define KN_SA 68
#define KN_SMEM (26112 * 4)

__global__ void __launch_bounds__(256, 2)
k_node_tc(const float* __restrict__ x,
          const float* __restrict__ bq, const float* __restrict__ bk,
          const float* __restrict__ bv, const float* __restrict__ bs,
          float* __restrict__ out)
{
    extern __shared__ uint32_t sm4[];
    const uint32_t sb = s2u(sm4);
    const int tid = threadIdx.x;
    const int wid = tid >> 5;
    const int lane = tid & 31;
    const int base = blockIdx.x * 128;

    uint32_t* AH = sm4;
    uint32_t* BH = sm4 + 8704;
    uint32_t* BL = sm4 + 17408;

    for (int idx = tid; idx < 128 * 16; idx += 256) {
        int i = idx >> 4, p4 = idx & 15;
        int node = base + i;
        float v[8] = {0.f, 0.f, 0.f, 0.f, 0.f, 0.f, 0.f, 0.f};
        if (node < N_NODES) ldg_ef8(x + (size_t)node * 128 + p4 * 8, v);
#pragma unroll
        for (int j = 0; j < 4; ++j)
            AH[i * KN_SA + p4 * 4 + j] = packh2(v[2 * j], v[2 * j + 1]);
    }

    const int wm = wid & 3;
    const int wn = wid >> 2;
    const int lrow = lane & 15;
    const int lk   = (lane >> 4) * 8;
    const int l2   = lane & 3;
    const int lr   = lane >> 2;

    for (int mat = 0; mat < 4; ++mat) {
        {
            const uint4* gh = (const uint4*)g_imgW_h[mat];
            const uint4* gl = (const uint4*)g_imgW_l[mat];
            for (int idx = tid; idx < 128 * 16; idx += 256) {
                int row = idx >> 4, q = idx & 15;
                ((uint4*)(BH + row * KN_SA))[q] = gh[row * 16 + q];
                ((uint4*)(BL + row * KN_SA))[q] = gl[row * 16 + q];
            }
        }
        __syncthreads();

        float d[2][8][4];
#pragma unroll
        for (int mi = 0; mi < 2; ++mi)
#pragma unroll
            for (int ni = 0; ni < 8; ++ni)
#pragma unroll
                for (int c = 0; c < 4; ++c) d[mi][ni][c] = 0.f;

#pragma unroll 2
        for (int ks = 0; ks < 8; ++ks) {
            const int k0 = ks * 16;
            uint32_t ah[2][4];
#pragma unroll
            for (int mi = 0; mi < 2; ++mi) {
                int row = wm * 32 + mi * 16 + lrow;
                ldsm4(ah[mi], sb + (uint32_t)(row * (KN_SA * 4)) + (uint32_t)((k0 + lk) * 2));
            }
#pragma unroll
            for (int g = 0; g < 4; ++g) {
                int n = wn * 64 + g * 16 + lrow;
                uint32_t bo = (uint32_t)(n * (KN_SA * 4)) + (uint32_t)((k0 + lk) * 2);
                uint32_t bh[4], bl[4];
                ldsm4(bh, sb + 8704u * 4u + bo);
                ldsm4(bl, sb + 17408u * 4u + bo);
#pragma unroll
                for (int mi = 0; mi < 2; ++mi) {
                    mma16816(d[mi][2 * g + 0], ah[mi], bh[0], bh[2]);
                    mma16816(d[mi][2 * g + 1], ah[mi], bh[1], bh[3]);
                    mma16816(d[mi][2 * g + 0], ah[mi], bl[0], bl[2]);
                    mma16816(d[mi][2 * g + 1], ah[mi], bl[1], bl[3]);
                }
            }
        }

        const float* bias = (mat == 0) ? bq : (mat == 1) ? bk : (mat == 2) ? bv : bs;
        uint32_t* dsth    = (mat == 0) ? g_qh : (mat == 1) ? g_kh : g_vh;

#pragma unroll
        for (int g = 0; g < 4; ++g) {
            const int mi = g >> 1;
            const int c0 = (g & 1) * 2;
            int r = wm * 32 + mi * 16 + (g & 1) * 8 + lr;
            int node = base + r;
            if (node < N_NODES) {
#pragma unroll
                for (int ni = 0; ni < 8; ++ni) {
                    int col = wn * 64 + ni * 8 + l2 * 2;
                    float2 bb = *(const float2*)(bias + col);
                    float ox = d[mi][ni][c0] + bb.x;
                    float oy = d[mi][ni][c0 + 1] + bb.y;
                    if (mat < 3) {
                        dsth[(size_t)node * 64 + (col >> 1)] = packh2(ox, oy);
                    } else {
                        *(float2*)(out + (size_t)node * 128 + col) = make_float2(ox, oy);
                    }
                }
            }
        }
        __syncthreads();
    }
}

// ---------------- edge GEMM + attention + scatter (persistent, 128-tile, 2 CTA/SM) ----------------
#define KE_SA 100
#define KE_SMEM (26496 * 4)
#define AHB (896u * 4u)
#define BHB (13696u * 4u)

__device__ __forceinline__ void edge_load_idx(uint32_t* sm4, int buf, int base,
                                              const float* __restrict__ t,
                                              const float* __restrict__ lu)
{
    int tid = threadIdx.x;
    if (tid < 128) {
        int*   s_src = (int*)(sm4)        + buf * 128;
        int*   s_dst = (int*)(sm4 + 256)  + buf * 128;
        float* s_rel = (float*)(sm4 + 512) + buf * 128;
        int edge = base + tid;
        if (edge < N_EDGES) {
            int s = g_edge_i32[edge];
            s_src[tid] = s;
            s_dst[tid] = g_edge_i32[N_EDGES + edge];
            s_rel[tid] = t[edge] - lu[s];
        } else {
            s_src[tid] = -1; s_dst[tid] = 0; s_rel[tid] = 0.f;
        }
    }
}

__device__ __forceinline__ void edge_build_A(uint32_t* sm4, int buf, int base,
                                             const float* __restrict__ msg)
{
    int tid = threadIdx.x;
    float* s_rel = (float*)(sm4 + 512) + buf * 128;
    float* s_tw  = (float*)(sm4 + 768);
    float* s_tb  = (float*)(sm4 + 832);
    uint32_t* AH = sm4 + 896;
    for (int idx = tid; idx < 128 * 32; idx += 256) {
        int i = idx >> 5, p = idx & 31;
        float rel = s_rel[i];
        float c0 = __cosf(fmaf(rel, s_tw[2 * p],     s_tb[2 * p]));
        float c1 = __cosf(fmaf(rel, s_tw[2 * p + 1], s_tb[2 * p + 1]));
        AH[i * KE_SA + p] = packh2(c0, c1);
    }
    for (int idx = tid; idx < 128 * 16; idx += 256) {
        int i = idx >> 4, p4 = idx & 15;
        int edge = base + i;
        float v[8] = {0.f, 0.f, 0.f, 0.f, 0.f, 0.f, 0.f, 0.f};
        if (edge < N_EDGES) ldg_ef8(msg + (size_t)edge * 128 + p4 * 8, v);
#pragma unroll
        for (int j = 0; j < 4; ++j)
            AH[i * KE_SA + 32 + p4 * 4 + j] = packh2(v[2 * j], v[2 * j + 1]);
    }
}

__global__ void __launch_bounds__(256, 2)
k_edge_tc(const float* __restrict__ t,
          const float* __restrict__ last_update,
          const float* __restrict__ msg,
          const float* __restrict__ time_w,
          const float* __restrict__ time_b)
{
    extern __shared__ uint32_t sm4[];
    const uint32_t sb = s2u(sm4);
    const int tid = threadIdx.x;
    const int wid = tid >> 5;
    const int lane = tid & 31;

    {
        const uint4* gh = (const uint4*)g_imgWe_h;
        uint32_t* BH = sm4 + 13696;
        for (int idx = tid; idx < 128 * 24; idx += 256) {
            int row = idx / 24, q = idx % 24;
            ((uint4*)(BH + row * KE_SA))[q] = gh[row * 24 + q];
        }
    }
    if (tid < 64) {
        ((float*)(sm4 + 768))[tid] = time_w[tid];
        ((float*)(sm4 + 832))[tid] = time_b[tid];
    }
    __syncthreads();

    const int wm = wid & 3;
    const int wn = wid >> 2;
    const int lrow = lane & 15;
    const int lk   = (lane >> 4) * 8;
    const int l2   = lane & 3;
    const int lr   = lane >> 2;

    int tile = blockIdx.x;
    if (tile < NT_EDGE) {
        edge_load_idx(sm4, 0, tile * 128, t, last_update);
        __syncthreads();
        edge_build_A(sm4, 0, tile * 128, msg);
    }
    __syncthreads();

    int buf = 0;
    for (; tile < NT_EDGE; tile += gridDim.x) {
        int nxt = tile + gridDim.x;
        if (nxt < NT_EDGE)
            edge_load_idx(sm4, buf ^ 1, nxt * 128, t, last_update);

        // -------- MMA: fp16 single pass --------
        float d[2][8][4];
#pragma unroll
        for (int mi = 0; mi < 2; ++mi)
#pragma unroll
            for (int ni = 0; ni < 8; ++ni)
#pragma unroll
                for (int c = 0; c < 4; ++c) d[mi][ni][c] = 0.f;

#pragma unroll 3
        for (int ks = 0; ks < 12; ++ks) {
            const int k0 = ks * 16;
            uint32_t ah[2][4];
#pragma unroll
            for (int mi = 0; mi < 2; ++mi) {
                int row = wm * 32 + mi * 16 + lrow;
                ldsm4(ah[mi], sb + AHB + (uint32_t)(row * (KE_SA * 4)) + (uint32_t)((k0 + lk) * 2));
            }
#pragma unroll
            for (int g = 0; g < 4; ++g) {
                int n = wn * 64 + g * 16 + lrow;
                uint32_t bh[4];
                ldsm4(bh, sb + BHB + (uint32_t)(n * (KE_SA * 4)) + (uint32_t)((k0 + lk) * 2));
#pragma unroll
                for (int mi = 0; mi < 2; ++mi) {
                    mma16816(d[mi][2 * g + 0], ah[mi], bh[0], bh[2]);
                    mma16816(d[mi][2 * g + 1], ah[mi], bh[1], bh[3]);
                }
            }
        }
        __syncthreads();

        if (nxt < NT_EDGE)
            edge_build_A(sm4, buf ^ 1, nxt * 128, msg);

        // -------- register-resident epilogue (fp16 gathers, v4 atomic combining) --------
        {
            const int* s_src = (const int*)(sm4)       + buf * 128;
            const int* s_dst = (const int*)(sm4 + 256) + buf * 128;
#pragma unroll
            for (int g = 0; g < 4; ++g) {
                const int mi = g >> 1;
                const int c0 = (g & 1) * 2;
                int r = wm * 32 + mi * 16 + (g & 1) * 8 + lr;
                int sn = s_src[r];
                int dn = s_dst[r];
                bool valid = (sn >= 0);
                int sn2 = valid ? sn : 0;
                int dn2 = valid ? dn : 0;

                uint32_t qh[8], kh[8];
#pragma unroll
                for (int ni = 0; ni < 8; ++ni) {
                    int hidx = wn * 32 + ni * 4 + l2;
                    qh[ni] = g_qh[(size_t)dn2 * 64 + hidx];
                    kh[ni] = g_kh[(size_t)sn2 * 64 + hidx];
                }
                float s = 0.f;
#pragma unroll
                for (int ni = 0; ni < 8; ++ni) {
                    float2 q2 = unpackh2(qh[ni]);
                    float2 k2 = unpackh2(kh[ni]);
                    s += q2.x * (k2.x + d[mi][ni][c0]);
                    s += q2.y * (k2.y + d[mi][ni][c0 + 1]);
                }
                s += __shfl_xor_sync(0xffffffffu, s, 1);
                s += __shfl_xor_sync(0xffffffffu, s, 2);
                float alv = __expf(s * 0.125f);

                uint32_t vh[8];
#pragma unroll
                for (int ni = 0; ni < 8; ++ni)
                    vh[ni] = g_vh[(size_t)sn2 * 64 + wn * 32 + ni * 4 + l2];

#pragma unroll
                for (int ni = 0; ni < 8; ++ni) {
                    float2 v2 = unpackh2(vh[ni]);
                    float ox = (v2.x + d[mi][ni][c0])     * alv;
                    float oy = (v2.y + d[mi][ni][c0 + 1]) * alv;
                    float px = __shfl_xor_sync(0xffffffffu, ox, 1);
                    float py = __shfl_xor_sync(0xffffffffu, oy, 1);
                    if (valid && (lane & 1) == 0) {
                        int colb = wn * 64 + ni * 8 + (l2 >> 1) * 4;
                        float* p = g_acc + (size_t)dn * 128 + colb;
                        asm volatile("red.global.add.v4.f32 [%0], {%1,%2,%3,%4};"
                                     :: "l"(p), "f"(ox), "f"(oy), "f"(px), "f"(py) : "memory");
                    }
                }
                if (valid && l2 == 0)
                    atomicAdd(&g_asum[dn * 2 + wn], alv);
            }
        }
        __syncthreads();
        buf ^= 1;
    }
}

// ---------------- final: out = skip + acc / asum ----------------
__global__ void __launch_bounds__(256)
k_final(float* __restrict__ out)
{
    int idx = blockIdx.x * blockDim.x + threadIdx.x;
    if (idx >= N_NODES * 32) return;
    int n  = idx >> 5;
    int c4 = idx & 31;
    int h  = c4 >> 4;
    float inv = 1.f / (g_asum[n * 2 + h] + 1e-16f);
    float4 a = ((const float4*)g_acc)[idx];
    float4 o = ((float4*)out)[idx];
    o.x += a.x * inv; o.y += a.y * inv; o.z += a.z * inv; o.w += a.w * inv;
    ((float4*)out)[idx] = o;
}

// ---------------- launch ----------------
extern "C" void kernel_launch(void* const* d_in, const int* in_sizes, int n_in,
                              void* d_out, int out_size)
{
    const float* x    = (const float*)d_in[0];
    const float* lu   = (const float*)d_in[1];
    const float* t    = (const float*)d_in[2];
    const float* msg  = (const float*)d_in[3];
    const float* tw   = (const float*)d_in[4];
    const float* tb   = (const float*)d_in[5];
    const float* Wq   = (const float*)d_in[6];
    const float* bq   = (const float*)d_in[7];
    const float* Wk   = (const float*)d_in[8];
    const float* bk   = (const float*)d_in[9];
    const float* Wv   = (const float*)d_in[10];
    const float* bv   = (const float*)d_in[11];
    const float* We   = (const float*)d_in[12];
    const float* Wsk  = (const float*)d_in[13];
    const float* bsk  = (const float*)d_in[14];
    const void*  ei   = d_in[15];
    float* out = (float*)d_out;

    cudaFuncSetAttribute(k_node_tc, cudaFuncAttributeMaxDynamicSharedMemorySize, KN_SMEM);
    cudaFuncSetAttribute(k_edge_tc, cudaFuncAttributeMaxDynamicSharedMemorySize, KE_SMEM);

    k_detect<<<1, 256>>>((const int*)ei);                              // my 0
    k_fused<<<FB_TOTAL, 256>>>(ei, We, Wq, Wk, Wv, Wsk);               // my 1
    k_node_tc<<<NT_NODE, 256, KN_SMEM>>>(x, bq, bk, bv, bsk, out);     // my 2
    k_edge_tc<<<304, 256, KE_SMEM>>>(t, lu, msg, tw, tb);              // my 3 (global 5)
    k_final<<<(N_NODES * 32 + 255) / 256, 256>>>(out);                 // my 4
}

// round 12
// speedup vs baseline: 5.0497x; 1.1158x over previous
#include <cuda_runtime.h>
#include <cuda_fp16.h>
#include <cstdint>

#define N_NODES 50000
#define N_EDGES 500000
#define NT_EDGE ((N_EDGES + 127) / 128)   // 3907
#define NT_NODE ((N_NODES + 127) / 128)   // 391

#define FB_CONV  3907
#define FB_ZERO  6250
#define FB_PREP  176
#define FB_TOTAL (FB_CONV + FB_ZERO + FB_PREP)

// ---------------- global scratch ----------------
// q/k/v packed fp16 (half2 per uint32), LOGICAL column order: node*64 + col/2
__device__ uint32_t g_qh[(size_t)N_NODES * 64];
__device__ uint32_t g_kh[(size_t)N_NODES * 64];
__device__ uint32_t g_vh[(size_t)N_NODES * 64];
__device__ float g_acc[(size_t)N_NODES * 128];
__device__ float g_asum[(size_t)N_NODES * 2];
__device__ int   g_edge_i32[(size_t)2 * N_EDGES];
__device__ int   g_is64;
// weight images with PERMUTED N order (fragment-contiguous)
__device__ uint32_t g_imgWe_h[128 * 96];
__device__ uint32_t g_imgW_h[4][128 * 64], g_imgW_l[4][128 * 64];

// fragment->contiguous column permutation (within each 64-col block)
__device__ __forceinline__ int permN(int n) {
    int p = n & 63;
    return (n & 64) + (((p & 7) >> 1) << 4) + ((p >> 3) << 1) + (p & 1);
}

// ---------------- helpers ----------------
__device__ __forceinline__ uint32_t s2u(const void* p) {
    uint32_t r;
    asm("{ .reg .u64 t; cvta.to.shared.u64 t, %1; cvt.u32.u64 %0, t; }" : "=r"(r) : "l"(p));
    return r;
}

__device__ __forceinline__ void ldsm4(uint32_t* r, uint32_t addr) {
    asm volatile("ldmatrix.sync.aligned.m8n8.x4.shared.b16 {%0,%1,%2,%3}, [%4];"
                 : "=r"(r[0]), "=r"(r[1]), "=r"(r[2]), "=r"(r[3]) : "r"(addr));
}

__device__ __forceinline__ void mma16816(float* d, const uint32_t* a, uint32_t b0, uint32_t b1) {
    asm volatile("mma.sync.aligned.m16n8k16.row.col.f32.f16.f16.f32 "
                 "{%0,%1,%2,%3}, {%4,%5,%6,%7}, {%8,%9}, {%0,%1,%2,%3};"
                 : "+f"(d[0]), "+f"(d[1]), "+f"(d[2]), "+f"(d[3])
                 : "r"(a[0]), "r"(a[1]), "r"(a[2]), "r"(a[3]), "r"(b0), "r"(b1));
}

__device__ __forceinline__ uint32_t packh2(float a, float b) {
    __half2 h = __floats2half2_rn(a, b);
    return *reinterpret_cast<uint32_t*>(&h);
}

__device__ __forceinline__ float2 unpackh2(uint32_t u) {
    return __half22float2(*reinterpret_cast<__half2*>(&u));
}

__device__ __forceinline__ void splith(float a, float b, uint32_t& hi, uint32_t& lo) {
    __half2 h = __floats2half2_rn(a, b);
    float ra = a - __low2float(h);
    float rb = b - __high2float(h);
    __half2 l = __floats2half2_rn(ra, rb);
    hi = *reinterpret_cast<uint32_t*>(&h);
    lo = *reinterpret_cast<uint32_t*>(&l);
}

__device__ __forceinline__ void ldg_ef8(const float* p, float* v) {
    uint32_t r0, r1, r2, r3, r4, r5, r6, r7;
    asm("ld.global.L2::evict_first.v8.b32 {%0,%1,%2,%3,%4,%5,%6,%7}, [%8];"
        : "=r"(r0), "=r"(r1), "=r"(r2), "=r"(r3),
          "=r"(r4), "=r"(r5), "=r"(r6), "=r"(r7) : "l"(p));
    v[0] = __uint_as_float(r0); v[1] = __uint_as_float(r1);
    v[2] = __uint_as_float(r2); v[3] = __uint_as_float(r3);
    v[4] = __uint_as_float(r4); v[5] = __uint_as_float(r5);
    v[6] = __uint_as_float(r6); v[7] = __uint_as_float(r7);
}

// ---------------- detect ----------------
__global__ void k_detect(const int* __restrict__ words)
{
    __shared__ int nz;
    if (threadIdx.x == 0) nz = 0;
    __syncthreads();
    int local = 0;
    for (int idx = threadIdx.x; idx < 4096; idx += blockDim.x)
        if (words[2 * idx + 1] != 0) local = 1;
    if (local) atomicOr(&nz, 1);
    __syncthreads();
    if (threadIdx.x == 0) g_is64 = (nz == 0) ? 1 : 0;
}

// ---------------- fused convert + zero + prep (permuted N) ----------------
__global__ void k_fused(const void* __restrict__ ei,
                        const float* __restrict__ We,
                        const float* __restrict__ Wq, const float* __restrict__ Wk,
                        const float* __restrict__ Wv, const float* __restrict__ Ws)
{
    int b = blockIdx.x;
    if (b < FB_CONV) {
        int idx = b * 256 + threadIdx.x;
        if (idx < 2 * N_EDGES) {
            int v;
            if (g_is64) v = (int)((const long long*)ei)[idx];
            else        v = ((const int*)ei)[idx];
            g_edge_i32[idx] = v;
        }
        return;
    }
    b -= FB_CONV;
    if (b < FB_ZERO) {
        int i = b * 256 + threadIdx.x;
        if (i < N_NODES * 2) g_asum[i] = 0.f;
        if (i < N_NODES * 32) ((float4*)g_acc)[i] = make_float4(0.f, 0.f, 0.f, 0.f);
        return;
    }
    b -= FB_ZERO;
    {
        int idx = b * 256 + threadIdx.x;
        if (idx < 12288) {
            int n = idx / 96, p = idx % 96;
            int ns = permN(n);
            float a = We[(2 * p) * 128 + ns];
            float bb = We[(2 * p + 1) * 128 + ns];
            g_imgWe_h[idx] = packh2(a, bb);
        } else if (idx < 45056) {
            int r = idx - 12288;
            int mat = r >> 13;
            int w_  = r & 8191;
            int n = w_ >> 6, p = w_ & 63;
            int ns = permN(n);
            const float* W = (mat == 0) ? Wq : (mat == 1) ? Wk : (mat == 2) ? Wv : Ws;
            float a = W[(2 * p) * 128 + ns];
            float bb = W[(2 * p + 1) * 128 + ns];
            uint32_t h, l; splith(a, bb, h, l);
            g_imgW_h[mat][w_] = h; g_imgW_l[mat][w_] = l;
        }
    }
}

// ---------------- node GEMM: fp16 2-pass (B compensated), all 4 matrices ----------------
#define KN_SA 68
#define KN_SMEM (26112 * 4)

__global__ void __launch_bounds__(256, 2)
k_node_tc(const float* __restrict__ x,
          const float* __restrict__ bq, const float* __restrict__ bk,
          const float* __restrict__ bv, const float* __restrict__ bs,
          float* __restrict__ out)
{
    extern __shared__ uint32_t sm4[];
    const uint32_t sb = s2u(sm4);
    const int tid = threadIdx.x;
    const int wid = tid >> 5;
    const int lane = tid & 31;
    const int base = blockIdx.x * 128;

    uint32_t* AH = sm4;
    uint32_t* BH = sm4 + 8704;
    uint32_t* BL = sm4 + 17408;

    for (int idx = tid; idx < 128 * 16; idx += 256) {
        int i = idx >> 4, p4 = idx & 15;
        int node = base + i;
        float v[8] = {0.f, 0.f, 0.f, 0.f, 0.f, 0.f, 0.f, 0.f};
        if (node < N_NODES) ldg_ef8(x + (size_t)node * 128 + p4 * 8, v);
#pragma unroll
        for (int j = 0; j < 4; ++j)
            AH[i * KN_SA + p4 * 4 + j] = packh2(v[2 * j], v[2 * j + 1]);
    }

    const int wm = wid & 3;
    const int wn = wid >> 2;
    const int lrow = lane & 15;
    const int lk   = (lane >> 4) * 8;
    const int l2   = lane & 3;
    const int lr   = lane >> 2;

    for (int mat = 0; mat < 4; ++mat) {
        {
            const uint4* gh = (const uint4*)g_imgW_h[mat];
            const uint4* gl = (const uint4*)g_imgW_l[mat];
            for (int idx = tid; idx < 128 * 16; idx += 256) {
                int row = idx >> 4, q = idx & 15;
                ((uint4*)(BH + row * KN_SA))[q] = gh[row * 16 + q];
                ((uint4*)(BL + row * KN_SA))[q] = gl[row * 16 + q];
            }
        }
        __syncthreads();

        float d[2][8][4];
#pragma unroll
        for (int mi = 0; mi < 2; ++mi)
#pragma unroll
            for (int ni = 0; ni < 8; ++ni)
#pragma unroll
                for (int c = 0; c < 4; ++c) d[mi][ni][c] = 0.f;

#pragma unroll 2
        for (int ks = 0; ks < 8; ++ks) {
            const int k0 = ks * 16;
            uint32_t ah[2][4];
#pragma unroll
            for (int mi = 0; mi < 2; ++mi) {
                int row = wm * 32 + mi * 16 + lrow;
                ldsm4(ah[mi], sb + (uint32_t)(row * (KN_SA * 4)) + (uint32_t)((k0 + lk) * 2));
            }
#pragma unroll
            for (int g = 0; g < 4; ++g) {
                int n = wn * 64 + g * 16 + lrow;
                uint32_t bo = (uint32_t)(n * (KN_SA * 4)) + (uint32_t)((k0 + lk) * 2);
                uint32_t bh[4], bl[4];
                ldsm4(bh, sb + 8704u * 4u + bo);
                ldsm4(bl, sb + 17408u * 4u + bo);
#pragma unroll
                for (int mi = 0; mi < 2; ++mi) {
                    mma16816(d[mi][2 * g + 0], ah[mi], bh[0], bh[2]);
                    mma16816(d[mi][2 * g + 1], ah[mi], bh[1], bh[3]);
                    mma16816(d[mi][2 * g + 0], ah[mi], bl[0], bl[2]);
                    mma16816(d[mi][2 * g + 1], ah[mi], bl[1], bl[3]);
                }
            }
        }

        const float* bias = (mat == 0) ? bq : (mat == 1) ? bk : (mat == 2) ? bv : bs;
        uint32_t* dsth    = (mat == 0) ? g_qh : (mat == 1) ? g_kh : g_vh;

        // lane holds LOGICAL cols wn*64 + l2*16 + 2*ni + b  (contiguous 16)
#pragma unroll
        for (int g = 0; g < 4; ++g) {
            const int mi = g >> 1;
            const int c0 = (g & 1) * 2;
            int r = wm * 32 + mi * 16 + (g & 1) * 8 + lr;
            int node = base + r;
            if (node < N_NODES) {
                const float4* b4 = (const float4*)(bias + wn * 64 + l2 * 16);
                float o[16];
#pragma unroll
                for (int q = 0; q < 4; ++q) {
                    float4 bb = b4[q];
                    o[4 * q + 0] = d[mi][2 * q + 0][c0]     + bb.x;
                    o[4 * q + 1] = d[mi][2 * q + 0][c0 + 1] + bb.y;
                    o[4 * q + 2] = d[mi][2 * q + 1][c0]     + bb.z;
                    o[4 * q + 3] = d[mi][2 * q + 1][c0 + 1] + bb.w;
                }
                if (mat < 3) {
                    uint32_t hw[8];
#pragma unroll
                    for (int w = 0; w < 8; ++w)
                        hw[w] = packh2(o[2 * w], o[2 * w + 1]);
                    uint4* dst4 = (uint4*)&dsth[(size_t)node * 64 + wn * 32 + l2 * 8];
                    dst4[0] = make_uint4(hw[0], hw[1], hw[2], hw[3]);
                    dst4[1] = make_uint4(hw[4], hw[5], hw[6], hw[7]);
                } else {
                    float4* dst4 = (float4*)(out + (size_t)node * 128 + wn * 64 + l2 * 16);
#pragma unroll
                    for (int q = 0; q < 4; ++q)
                        dst4[q] = make_float4(o[4 * q], o[4 * q + 1], o[4 * q + 2], o[4 * q + 3]);
                }
            }
        }
        __syncthreads();
    }
}

// ---------------- edge GEMM + attention + scatter (persistent, 128-tile, 2 CTA/SM) ----------------
#define KE_SA 100
#define KE_SMEM (26496 * 4)
#define AHB (896u * 4u)
#define BHB (13696u * 4u)

__device__ __forceinline__ void edge_load_idx(uint32_t* sm4, int buf, int base,
                                              const float* __restrict__ t,
                                              const float* __restrict__ lu)
{
    int tid = threadIdx.x;
    if (tid < 128) {
        int*   s_src = (int*)(sm4)        + buf * 128;
        int*   s_dst = (int*)(sm4 + 256)  + buf * 128;
        float* s_rel = (float*)(sm4 + 512) + buf * 128;
        int edge = base + tid;
        if (edge < N_EDGES) {
            int s = g_edge_i32[edge];
            s_src[tid] = s;
            s_dst[tid] = g_edge_i32[N_EDGES + edge];
            s_rel[tid] = t[edge] - lu[s];
        } else {
            s_src[tid] = -1; s_dst[tid] = 0; s_rel[tid] = 0.f;
        }
    }
}

__device__ __forceinline__ void edge_build_A(uint32_t* sm4, int buf, int base,
                                             const float* __restrict__ msg)
{
    int tid = threadIdx.x;
    float* s_rel = (float*)(sm4 + 512) + buf * 128;
    float* s_tw  = (float*)(sm4 + 768);
    float* s_tb  = (float*)(sm4 + 832);
    uint32_t* AH = sm4 + 896;
    for (int idx = tid; idx < 128 * 32; idx += 256) {
        int i = idx >> 5, p = idx & 31;
        float rel = s_rel[i];
        float c0 = __cosf(fmaf(rel, s_tw[2 * p],     s_tb[2 * p]));
        float c1 = __cosf(fmaf(rel, s_tw[2 * p + 1], s_tb[2 * p + 1]));
        AH[i * KE_SA + p] = packh2(c0, c1);
    }
    for (int idx = tid; idx < 128 * 16; idx += 256) {
        int i = idx >> 4, p4 = idx & 15;
        int edge = base + i;
        float v[8] = {0.f, 0.f, 0.f, 0.f, 0.f, 0.f, 0.f, 0.f};
        if (edge < N_EDGES) ldg_ef8(msg + (size_t)edge * 128 + p4 * 8, v);
#pragma unroll
        for (int j = 0; j < 4; ++j)
            AH[i * KE_SA + 32 + p4 * 4 + j] = packh2(v[2 * j], v[2 * j + 1]);
    }
}

__global__ void __launch_bounds__(256, 2)
k_edge_tc(const float* __restrict__ t,
          const float* __restrict__ last_update,
          const float* __restrict__ msg,
          const float* __restrict__ time_w,
          const float* __restrict__ time_b)
{
    extern __shared__ uint32_t sm4[];
    const uint32_t sb = s2u(sm4);
    const int tid = threadIdx.x;
    const int wid = tid >> 5;
    const int lane = tid & 31;

    {
        const uint4* gh = (const uint4*)g_imgWe_h;
        uint32_t* BH = sm4 + 13696;
        for (int idx = tid; idx < 128 * 24; idx += 256) {
            int row = idx / 24, q = idx % 24;
            ((uint4*)(BH + row * KE_SA))[q] = gh[row * 24 + q];
        }
    }
    if (tid < 64) {
        ((float*)(sm4 + 768))[tid] = time_w[tid];
        ((float*)(sm4 + 832))[tid] = time_b[tid];
    }
    __syncthreads();

    const int wm = wid & 3;
    const int wn = wid >> 2;
    const int lrow = lane & 15;
    const int lk   = (lane >> 4) * 8;
    const int l2   = lane & 3;
    const int lr   = lane >> 2;

    int tile = blockIdx.x;
    if (tile < NT_EDGE) {
        edge_load_idx(sm4, 0, tile * 128, t, last_update);
        __syncthreads();
        edge_build_A(sm4, 0, tile * 128, msg);
    }
    __syncthreads();

    int buf = 0;
    for (; tile < NT_EDGE; tile += gridDim.x) {
        int nxt = tile + gridDim.x;
        if (nxt < NT_EDGE)
            edge_load_idx(sm4, buf ^ 1, nxt * 128, t, last_update);

        // -------- MMA: fp16 single pass --------
        float d[2][8][4];
#pragma unroll
        for (int mi = 0; mi < 2; ++mi)
#pragma unroll
            for (int ni = 0; ni < 8; ++ni)
#pragma unroll
                for (int c = 0; c < 4; ++c) d[mi][ni][c] = 0.f;

#pragma unroll 3
        for (int ks = 0; ks < 12; ++ks) {
            const int k0 = ks * 16;
            uint32_t ah[2][4];
#pragma unroll
            for (int mi = 0; mi < 2; ++mi) {
                int row = wm * 32 + mi * 16 + lrow;
                ldsm4(ah[mi], sb + AHB + (uint32_t)(row * (KE_SA * 4)) + (uint32_t)((k0 + lk) * 2));
            }
#pragma unroll
            for (int g = 0; g < 4; ++g) {
                int n = wn * 64 + g * 16 + lrow;
                uint32_t bh[4];
                ldsm4(bh, sb + BHB + (uint32_t)(n * (KE_SA * 4)) + (uint32_t)((k0 + lk) * 2));
#pragma unroll
                for (int mi = 0; mi < 2; ++mi) {
                    mma16816(d[mi][2 * g + 0], ah[mi], bh[0], bh[2]);
                    mma16816(d[mi][2 * g + 1], ah[mi], bh[1], bh[3]);
                }
            }
        }
        __syncthreads();

        if (nxt < NT_EDGE)
            edge_build_A(sm4, buf ^ 1, nxt * 128, msg);

        // -------- epilogue: coalesced 128-bit gathers, contiguous v4 atomics --------
        // lane's fragment = LOGICAL cols wn*64 + l2*16 + 2*ni + b (contiguous 16)
        {
            const int* s_src = (const int*)(sm4)       + buf * 128;
            const int* s_dst = (const int*)(sm4 + 256) + buf * 128;
#pragma unroll
            for (int g = 0; g < 4; ++g) {
                const int mi = g >> 1;
                const int c0 = (g & 1) * 2;
                int r = wm * 32 + mi * 16 + (g & 1) * 8 + lr;
                int sn = s_src[r];
                int dn = s_dst[r];
                bool valid = (sn >= 0);
                int sn2 = valid ? sn : 0;
                int dn2 = valid ? dn : 0;

                const uint4* qp = (const uint4*)&g_qh[(size_t)dn2 * 64 + wn * 32 + l2 * 8];
                const uint4* kp = (const uint4*)&g_kh[(size_t)sn2 * 64 + wn * 32 + l2 * 8];
                uint4 qa = qp[0], qb = qp[1];
                uint4 ka = kp[0], kb = kp[1];
                uint32_t qw[8] = {qa.x, qa.y, qa.z, qa.w, qb.x, qb.y, qb.z, qb.w};
                uint32_t kw[8] = {ka.x, ka.y, ka.z, ka.w, kb.x, kb.y, kb.z, kb.w};

                float s = 0.f;
#pragma unroll
                for (int w = 0; w < 8; ++w) {
                    float2 q2 = unpackh2(qw[w]);
                    float2 k2 = unpackh2(kw[w]);
                    s += q2.x * (k2.x + d[mi][w][c0]);
                    s += q2.y * (k2.y + d[mi][w][c0 + 1]);
                }
                s += __shfl_xor_sync(0xffffffffu, s, 1);
                s += __shfl_xor_sync(0xffffffffu, s, 2);
                float alv = __expf(s * 0.125f);

                const uint4* vp = (const uint4*)&g_vh[(size_t)sn2 * 64 + wn * 32 + l2 * 8];
                uint4 va = vp[0], vb = vp[1];
                uint32_t vw[8] = {va.x, va.y, va.z, va.w, vb.x, vb.y, vb.z, vb.w};

                float o[16];
#pragma unroll
                for (int w = 0; w < 8; ++w) {
                    float2 v2 = unpackh2(vw[w]);
                    o[2 * w]     = (v2.x + d[mi][w][c0])     * alv;
                    o[2 * w + 1] = (v2.y + d[mi][w][c0 + 1]) * alv;
                }
                if (valid) {
                    float* p = g_acc + (size_t)dn * 128 + wn * 64 + l2 * 16;
                    asm volatile("red.global.add.v4.f32 [%0], {%1,%2,%3,%4};"
                                 :: "l"(p), "f"(o[0]), "f"(o[1]), "f"(o[2]), "f"(o[3]) : "memory");
                    asm volatile("red.global.add.v4.f32 [%0], {%1,%2,%3,%4};"
                                 :: "l"(p + 4), "f"(o[4]), "f"(o[5]), "f"(o[6]), "f"(o[7]) : "memory");
                    asm volatile("red.global.add.v4.f32 [%0], {%1,%2,%3,%4};"
                                 :: "l"(p + 8), "f"(o[8]), "f"(o[9]), "f"(o[10]), "f"(o[11]) : "memory");
                    asm volatile("red.global.add.v4.f32 [%0], {%1,%2,%3,%4};"
                                 :: "l"(p + 12), "f"(o[12]), "f"(o[13]), "f"(o[14]), "f"(o[15]) : "memory");
                    if (l2 == 0)
                        atomicAdd(&g_asum[dn * 2 + wn], alv);
                }
            }
        }
        __syncthreads();
        buf ^= 1;
    }
}

// ---------------- final: out = skip + acc / asum ----------------
__global__ void __launch_bounds__(256)
k_final(float* __restrict__ out)
{
    int idx = blockIdx.x * blockDim.x + threadIdx.x;
    if (idx >= N_NODES * 32) return;
    int n  = idx >> 5;
    int c4 = idx & 31;
    int h  = c4 >> 4;
    float inv = 1.f / (g_asum[n * 2 + h] + 1e-16f);
    float4 a = ((const float4*)g_acc)[idx];
    float4 o = ((float4*)out)[idx];
    o.x += a.x * inv; o.y += a.y * inv; o.z += a.z * inv; o.w += a.w * inv;
    ((float4*)out)[idx] = o;
}

// ---------------- launch ----------------
extern "C" void kernel_launch(void* const* d_in, const int* in_sizes, int n_in,
                              void* d_out, int out_size)
{
    const float* x    = (const float*)d_in[0];
    const float* lu   = (const float*)d_in[1];
    const float* t    = (const float*)d_in[2];
    const float* msg  = (const float*)d_in[3];
    const float* tw   = (const float*)d_in[4];
    const float* tb   = (const float*)d_in[5];
    const float* Wq   = (const float*)d_in[6];
    const float* bq   = (const float*)d_in[7];
    const float* Wk   = (const float*)d_in[8];
    const float* bk   = (const float*)d_in[9];
    const float* Wv   = (const float*)d_in[10];
    const float* bv   = (const float*)d_in[11];
    const float* We   = (const float*)d_in[12];
    const float* Wsk  = (const float*)d_in[13];
    const float* bsk  = (const float*)d_in[14];
    const void*  ei   = d_in[15];
    float* out = (float*)d_out;

    cudaFuncSetAttribute(k_node_tc, cudaFuncAttributeMaxDynamicSharedMemorySize, KN_SMEM);
    cudaFuncSetAttribute(k_edge_tc, cudaFuncAttributeMaxDynamicSharedMemorySize, KE_SMEM);

    k_detect<<<1, 256>>>((const int*)ei);                              // my 0
    k_fused<<<FB_TOTAL, 256>>>(ei, We, Wq, Wk, Wv, Wsk);               // my 1
    k_node_tc<<<NT_NODE, 256, KN_SMEM>>>(x, bq, bk, bv, bsk, out);     // my 2
    k_edge_tc<<<304, 256, KE_SMEM>>>(t, lu, msg, tw, tb);              // my 3 (global 5)
    k_final<<<(N_NODES * 32 + 255) / 256, 256>>>(out);                 // my 4
}

// round 13
// speedup vs baseline: 5.6197x; 1.1129x over previous
#include <cuda_runtime.h>
#include <cuda_fp16.h>
#include <cstdint>

#define N_NODES 50000
#define N_EDGES 500000
#define NT_EDGE ((N_EDGES + 127) / 128)   // 3907
#define NT_NODE ((N_NODES + 127) / 128)   // 391

#define FB_CONV  3907
#define FB_ZERO  6250
#define FB_PREP  176
#define FB_TOTAL (FB_CONV + FB_ZERO + FB_PREP)

// ---------------- global scratch ----------------
// q/k/v packed fp16 (half2 per uint32), LOGICAL column order: node*64 + col/2
__device__ uint32_t g_qh[(size_t)N_NODES * 64];
__device__ uint32_t g_kh[(size_t)N_NODES * 64];
__device__ uint32_t g_vh[(size_t)N_NODES * 64];
// accumulator in fp16x2 (atomic target): node*64 + col/2
__device__ uint32_t g_acch[(size_t)N_NODES * 64];
__device__ float g_asum[(size_t)N_NODES * 2];
__device__ int   g_edge_i32[(size_t)2 * N_EDGES];
__device__ int   g_is64;
// weight images with PERMUTED N order (fragment-contiguous)
__device__ uint32_t g_imgWe_h[128 * 96];
__device__ uint32_t g_imgW_h[4][128 * 64], g_imgW_l[4][128 * 64];

// fragment->contiguous column permutation (within each 64-col block)
__device__ __forceinline__ int permN(int n) {
    int p = n & 63;
    return (n & 64) + (((p & 7) >> 1) << 4) + ((p >> 3) << 1) + (p & 1);
}

// ---------------- helpers ----------------
__device__ __forceinline__ uint32_t s2u(const void* p) {
    uint32_t r;
    asm("{ .reg .u64 t; cvta.to.shared.u64 t, %1; cvt.u32.u64 %0, t; }" : "=r"(r) : "l"(p));
    return r;
}

__device__ __forceinline__ void ldsm4(uint32_t* r, uint32_t addr) {
    asm volatile("ldmatrix.sync.aligned.m8n8.x4.shared.b16 {%0,%1,%2,%3}, [%4];"
                 : "=r"(r[0]), "=r"(r[1]), "=r"(r[2]), "=r"(r[3]) : "r"(addr));
}

__device__ __forceinline__ void mma16816(float* d, const uint32_t* a, uint32_t b0, uint32_t b1) {
    asm volatile("mma.sync.aligned.m16n8k16.row.col.f32.f16.f16.f32 "
                 "{%0,%1,%2,%3}, {%4,%5,%6,%7}, {%8,%9}, {%0,%1,%2,%3};"
                 : "+f"(d[0]), "+f"(d[1]), "+f"(d[2]), "+f"(d[3])
                 : "r"(a[0]), "r"(a[1]), "r"(a[2]), "r"(a[3]), "r"(b0), "r"(b1));
}

__device__ __forceinline__ uint32_t packh2(float a, float b) {
    __half2 h = __floats2half2_rn(a, b);
    return *reinterpret_cast<uint32_t*>(&h);
}

__device__ __forceinline__ float2 unpackh2(uint32_t u) {
    return __half22float2(*reinterpret_cast<__half2*>(&u));
}

__device__ __forceinline__ void splith(float a, float b, uint32_t& hi, uint32_t& lo) {
    __half2 h = __floats2half2_rn(a, b);
    float ra = a - __low2float(h);
    float rb = b - __high2float(h);
    __half2 l = __floats2half2_rn(ra, rb);
    hi = *reinterpret_cast<uint32_t*>(&h);
    lo = *reinterpret_cast<uint32_t*>(&l);
}

__device__ __forceinline__ void ldg_ef8(const float* p, float* v) {
    uint32_t r0, r1, r2, r3, r4, r5, r6, r7;
    asm("ld.global.L2::evict_first.v8.b32 {%0,%1,%2,%3,%4,%5,%6,%7}, [%8];"
        : "=r"(r0), "=r"(r1), "=r"(r2), "=r"(r3),
          "=r"(r4), "=r"(r5), "=r"(r6), "=r"(r7) : "l"(p));
    v[0] = __uint_as_float(r0); v[1] = __uint_as_float(r1);
    v[2] = __uint_as_float(r2); v[3] = __uint_as_float(r3);
    v[4] = __uint_as_float(r4); v[5] = __uint_as_float(r5);
    v[6] = __uint_as_float(r6); v[7] = __uint_as_float(r7);
}

// ---------------- detect ----------------
__global__ void k_detect(const int* __restrict__ words)
{
    __shared__ int nz;
    if (threadIdx.x == 0) nz = 0;
    __syncthreads();
    int local = 0;
    for (int idx = threadIdx.x; idx < 4096; idx += blockDim.x)
        if (words[2 * idx + 1] != 0) local = 1;
    if (local) atomicOr(&nz, 1);
    __syncthreads();
    if (threadIdx.x == 0) g_is64 = (nz == 0) ? 1 : 0;
}

// ---------------- fused convert + zero + prep (permuted N) ----------------
__global__ void k_fused(const void* __restrict__ ei,
                        const float* __restrict__ We,
                        const float* __restrict__ Wq, const float* __restrict__ Wk,
                        const float* __restrict__ Wv, const float* __restrict__ Ws)
{
    int b = blockIdx.x;
    if (b < FB_CONV) {
        int idx = b * 256 + threadIdx.x;
        if (idx < 2 * N_EDGES) {
            int v;
            if (g_is64) v = (int)((const long long*)ei)[idx];
            else        v = ((const int*)ei)[idx];
            g_edge_i32[idx] = v;
        }
        return;
    }
    b -= FB_CONV;
    if (b < FB_ZERO) {
        int i = b * 256 + threadIdx.x;
        if (i < N_NODES * 2) g_asum[i] = 0.f;
        if (i < N_NODES * 16) ((uint4*)g_acch)[i] = make_uint4(0u, 0u, 0u, 0u);
        return;
    }
    b -= FB_ZERO;
    {
        int idx = b * 256 + threadIdx.x;
        if (idx < 12288) {
            int n = idx / 96, p = idx % 96;
            int ns = permN(n);
            float a = We[(2 * p) * 128 + ns];
            float bb = We[(2 * p + 1) * 128 + ns];
            g_imgWe_h[idx] = packh2(a, bb);
        } else if (idx < 45056) {
            int r = idx - 12288;
            int mat = r >> 13;
            int w_  = r & 8191;
            int n = w_ >> 6, p = w_ & 63;
            int ns = permN(n);
            const float* W = (mat == 0) ? Wq : (mat == 1) ? Wk : (mat == 2) ? Wv : Ws;
            float a = W[(2 * p) * 128 + ns];
            float bb = W[(2 * p + 1) * 128 + ns];
            uint32_t h, l; splith(a, bb, h, l);
            g_imgW_h[mat][w_] = h; g_imgW_l[mat][w_] = l;
        }
    }
}

// ---------------- node GEMM: fp16 2-pass (B compensated), all 4 matrices ----------------
#define KN_SA 68
#define KN_SMEM (26112 * 4)

__global__ void __launch_bounds__(256, 2)
k_node_tc(const float* __restrict__ x,
          const float* __restrict__ bq, const float* __restrict__ bk,
          const float* __restrict__ bv, const float* __restrict__ bs,
          float* __restrict__ out)
{
    extern __shared__ uint32_t sm4[];
    const uint32_t sb = s2u(sm4);
    const int tid = threadIdx.x;
    const int wid = tid >> 5;
    const int lane = tid & 31;
    const int base = blockIdx.x * 128;

    uint32_t* AH = sm4;
    uint32_t* BH = sm4 + 8704;
    uint32_t* BL = sm4 + 17408;

    for (int idx = tid; idx < 128 * 16; idx += 256) {
        int i = idx >> 4, p4 = idx & 15;
        int node = base + i;
        float v[8] = {0.f, 0.f, 0.f, 0.f, 0.f, 0.f, 0.f, 0.f};
        if (node < N_NODES) ldg_ef8(x + (size_t)node * 128 + p4 * 8, v);
#pragma unroll
        for (int j = 0; j < 4; ++j)
            AH[i * KN_SA + p4 * 4 + j] = packh2(v[2 * j], v[2 * j + 1]);
    }

    const int wm = wid & 3;
    const int wn = wid >> 2;
    const int lrow = lane & 15;
    const int lk   = (lane >> 4) * 8;
    const int l2   = lane & 3;
    const int lr   = lane >> 2;

    for (int mat = 0; mat < 4; ++mat) {
        {
            const uint4* gh = (const uint4*)g_imgW_h[mat];
            const uint4* gl = (const uint4*)g_imgW_l[mat];
            for (int idx = tid; idx < 128 * 16; idx += 256) {
                int row = idx >> 4, q = idx & 15;
                ((uint4*)(BH + row * KN_SA))[q] = gh[row * 16 + q];
                ((uint4*)(BL + row * KN_SA))[q] = gl[row * 16 + q];
            }
        }
        __syncthreads();

        float d[2][8][4];
#pragma unroll
        for (int mi = 0; mi < 2; ++mi)
#pragma unroll
            for (int ni = 0; ni < 8; ++ni)
#pragma unroll
                for (int c = 0; c < 4; ++c) d[mi][ni][c] = 0.f;

#pragma unroll 2
        for (int ks = 0; ks < 8; ++ks) {
            const int k0 = ks * 16;
            uint32_t ah[2][4];
#pragma unroll
            for (int mi = 0; mi < 2; ++mi) {
                int row = wm * 32 + mi * 16 + lrow;
                ldsm4(ah[mi], sb + (uint32_t)(row * (KN_SA * 4)) + (uint32_t)((k0 + lk) * 2));
            }
#pragma unroll
            for (int g = 0; g < 4; ++g) {
                int n = wn * 64 + g * 16 + lrow;
                uint32_t bo = (uint32_t)(n * (KN_SA * 4)) + (uint32_t)((k0 + lk) * 2);
                uint32_t bh[4], bl[4];
                ldsm4(bh, sb + 8704u * 4u + bo);
                ldsm4(bl, sb + 17408u * 4u + bo);
#pragma unroll
                for (int mi = 0; mi < 2; ++mi) {
                    mma16816(d[mi][2 * g + 0], ah[mi], bh[0], bh[2]);
                    mma16816(d[mi][2 * g + 1], ah[mi], bh[1], bh[3]);
                    mma16816(d[mi][2 * g + 0], ah[mi], bl[0], bl[2]);
                    mma16816(d[mi][2 * g + 1], ah[mi], bl[1], bl[3]);
                }
            }
        }

        const float* bias = (mat == 0) ? bq : (mat == 1) ? bk : (mat == 2) ? bv : bs;
        uint32_t* dsth    = (mat == 0) ? g_qh : (mat == 1) ? g_kh : g_vh;

        // lane holds LOGICAL cols wn*64 + l2*16 + 2*ni + b  (contiguous 16)
#pragma unroll
        for (int g = 0; g < 4; ++g) {
            const int mi = g >> 1;
            const int c0 = (g & 1) * 2;
            int r = wm * 32 + mi * 16 + (g & 1) * 8 + lr;
            int node = base + r;
            if (node < N_NODES) {
                const float4* b4 = (const float4*)(bias + wn * 64 + l2 * 16);
                float o[16];
#pragma unroll
                for (int q = 0; q < 4; ++q) {
                    float4 bb = b4[q];
                    o[4 * q + 0] = d[mi][2 * q + 0][c0]     + bb.x;
                    o[4 * q + 1] = d[mi][2 * q + 0][c0 + 1] + bb.y;
                    o[4 * q + 2] = d[mi][2 * q + 1][c0]     + bb.z;
                    o[4 * q + 3] = d[mi][2 * q + 1][c0 + 1] + bb.w;
                }
                if (mat < 3) {
                    uint32_t hw[8];
#pragma unroll
                    for (int w = 0; w < 8; ++w)
                        hw[w] = packh2(o[2 * w], o[2 * w + 1]);
                    uint4* dst4 = (uint4*)&dsth[(size_t)node * 64 + wn * 32 + l2 * 8];
                    dst4[0] = make_uint4(hw[0], hw[1], hw[2], hw[3]);
                    dst4[1] = make_uint4(hw[4], hw[5], hw[6], hw[7]);
                } else {
                    float4* dst4 = (float4*)(out + (size_t)node * 128 + wn * 64 + l2 * 16);
#pragma unroll
                    for (int q = 0; q < 4; ++q)
                        dst4[q] = make_float4(o[4 * q], o[4 * q + 1], o[4 * q + 2], o[4 * q + 3]);
                }
            }
        }
        __syncthreads();
    }
}

// ---------------- edge GEMM + attention + scatter (persistent, 128-tile, 2 CTA/SM) ----------------
#define KE_SA 100
#define KE_SMEM (26496 * 4)
#define AHB (896u * 4u)
#define BHB (13696u * 4u)

__device__ __forceinline__ void edge_load_idx(uint32_t* sm4, int buf, int base,
                                              const float* __restrict__ t,
                                              const float* __restrict__ lu)
{
    int tid = threadIdx.x;
    if (tid < 128) {
        int*   s_src = (int*)(sm4)        + buf * 128;
        int*   s_dst = (int*)(sm4 + 256)  + buf * 128;
        float* s_rel = (float*)(sm4 + 512) + buf * 128;
        int edge = base + tid;
        if (edge < N_EDGES) {
            int s = g_edge_i32[edge];
            s_src[tid] = s;
            s_dst[tid] = g_edge_i32[N_EDGES + edge];
            s_rel[tid] = t[edge] - lu[s];
        } else {
            s_src[tid] = -1; s_dst[tid] = 0; s_rel[tid] = 0.f;
        }
    }
}

__device__ __forceinline__ void edge_build_A(uint32_t* sm4, int buf, int base,
                                             const float* __restrict__ msg)
{
    int tid = threadIdx.x;
    float* s_rel = (float*)(sm4 + 512) + buf * 128;
    float* s_tw  = (float*)(sm4 + 768);
    float* s_tb  = (float*)(sm4 + 832);
    uint32_t* AH = sm4 + 896;
    for (int idx = tid; idx < 128 * 32; idx += 256) {
        int i = idx >> 5, p = idx & 31;
        float rel = s_rel[i];
        float c0 = __cosf(fmaf(rel, s_tw[2 * p],     s_tb[2 * p]));
        float c1 = __cosf(fmaf(rel, s_tw[2 * p + 1], s_tb[2 * p + 1]));
        AH[i * KE_SA + p] = packh2(c0, c1);
    }
    for (int idx = tid; idx < 128 * 16; idx += 256) {
        int i = idx >> 4, p4 = idx & 15;
        int edge = base + i;
        float v[8] = {0.f, 0.f, 0.f, 0.f, 0.f, 0.f, 0.f, 0.f};
        if (edge < N_EDGES) ldg_ef8(msg + (size_t)edge * 128 + p4 * 8, v);
#pragma unroll
        for (int j = 0; j < 4; ++j)
            AH[i * KE_SA + 32 + p4 * 4 + j] = packh2(v[2 * j], v[2 * j + 1]);
    }
}

__global__ void __launch_bounds__(256, 2)
k_edge_tc(const float* __restrict__ t,
          const float* __restrict__ last_update,
          const float* __restrict__ msg,
          const float* __restrict__ time_w,
          const float* __restrict__ time_b)
{
    extern __shared__ uint32_t sm4[];
    const uint32_t sb = s2u(sm4);
    const int tid = threadIdx.x;
    const int wid = tid >> 5;
    const int lane = tid & 31;

    {
        const uint4* gh = (const uint4*)g_imgWe_h;
        uint32_t* BH = sm4 + 13696;
        for (int idx = tid; idx < 128 * 24; idx += 256) {
            int row = idx / 24, q = idx % 24;
            ((uint4*)(BH + row * KE_SA))[q] = gh[row * 24 + q];
        }
    }
    if (tid < 64) {
        ((float*)(sm4 + 768))[tid] = time_w[tid];
        ((float*)(sm4 + 832))[tid] = time_b[tid];
    }
    __syncthreads();

    const int wm = wid & 3;
    const int wn = wid >> 2;
    const int lrow = lane & 15;
    const int lk   = (lane >> 4) * 8;
    const int l2   = lane & 3;
    const int lr   = lane >> 2;

    int tile = blockIdx.x;
    if (tile < NT_EDGE) {
        edge_load_idx(sm4, 0, tile * 128, t, last_update);
        __syncthreads();
        edge_build_A(sm4, 0, tile * 128, msg);
    }
    __syncthreads();

    int buf = 0;
    for (; tile < NT_EDGE; tile += gridDim.x) {
        int nxt = tile + gridDim.x;
        if (nxt < NT_EDGE)
            edge_load_idx(sm4, buf ^ 1, nxt * 128, t, last_update);

        // -------- MMA: fp16 single pass --------
        float d[2][8][4];
#pragma unroll
        for (int mi = 0; mi < 2; ++mi)
#pragma unroll
            for (int ni = 0; ni < 8; ++ni)
#pragma unroll
                for (int c = 0; c < 4; ++c) d[mi][ni][c] = 0.f;

#pragma unroll 3
        for (int ks = 0; ks < 12; ++ks) {
            const int k0 = ks * 16;
            uint32_t ah[2][4];
#pragma unroll
            for (int mi = 0; mi < 2; ++mi) {
                int row = wm * 32 + mi * 16 + lrow;
                ldsm4(ah[mi], sb + AHB + (uint32_t)(row * (KE_SA * 4)) + (uint32_t)((k0 + lk) * 2));
            }
#pragma unroll
            for (int g = 0; g < 4; ++g) {
                int n = wn * 64 + g * 16 + lrow;
                uint32_t bh[4];
                ldsm4(bh, sb + BHB + (uint32_t)(n * (KE_SA * 4)) + (uint32_t)((k0 + lk) * 2));
#pragma unroll
                for (int mi = 0; mi < 2; ++mi) {
                    mma16816(d[mi][2 * g + 0], ah[mi], bh[0], bh[2]);
                    mma16816(d[mi][2 * g + 1], ah[mi], bh[1], bh[3]);
                }
            }
        }
        __syncthreads();

        if (nxt < NT_EDGE)
            edge_build_A(sm4, buf ^ 1, nxt * 128, msg);

        // -------- epilogue: coalesced gathers, packed-half v4 atomics --------
        {
            const int* s_src = (const int*)(sm4)       + buf * 128;
            const int* s_dst = (const int*)(sm4 + 256) + buf * 128;
#pragma unroll
            for (int g = 0; g < 4; ++g) {
                const int mi = g >> 1;
                const int c0 = (g & 1) * 2;
                int r = wm * 32 + mi * 16 + (g & 1) * 8 + lr;
                int sn = s_src[r];
                int dn = s_dst[r];
                bool valid = (sn >= 0);
                int sn2 = valid ? sn : 0;
                int dn2 = valid ? dn : 0;

                const uint4* qp = (const uint4*)&g_qh[(size_t)dn2 * 64 + wn * 32 + l2 * 8];
                const uint4* kp = (const uint4*)&g_kh[(size_t)sn2 * 64 + wn * 32 + l2 * 8];
                uint4 qa = qp[0], qb = qp[1];
                uint4 ka = kp[0], kb = kp[1];
                uint32_t qw[8] = {qa.x, qa.y, qa.z, qa.w, qb.x, qb.y, qb.z, qb.w};
                uint32_t kw[8] = {ka.x, ka.y, ka.z, ka.w, kb.x, kb.y, kb.z, kb.w};

                float s = 0.f;
#pragma unroll
                for (int w = 0; w < 8; ++w) {
                    float2 q2 = unpackh2(qw[w]);
                    float2 k2 = unpackh2(kw[w]);
                    s += q2.x * (k2.x + d[mi][w][c0]);
                    s += q2.y * (k2.y + d[mi][w][c0 + 1]);
                }
                s += __shfl_xor_sync(0xffffffffu, s, 1);
                s += __shfl_xor_sync(0xffffffffu, s, 2);
                float alv = __expf(s * 0.125f);

                const uint4* vp = (const uint4*)&g_vh[(size_t)sn2 * 64 + wn * 32 + l2 * 8];
                uint4 va = vp[0], vb = vp[1];
                uint32_t vw[8] = {va.x, va.y, va.z, va.w, vb.x, vb.y, vb.z, vb.w};

                uint32_t ho[8];
#pragma unroll
                for (int w = 0; w < 8; ++w) {
                    float2 v2 = unpackh2(vw[w]);
                    float ox = (v2.x + d[mi][w][c0])     * alv;
                    float oy = (v2.y + d[mi][w][c0 + 1]) * alv;
                    ho[w] = packh2(ox, oy);
                }
                if (valid) {
                    uint32_t* p = &g_acch[(size_t)dn * 64 + wn * 32 + l2 * 8];
                    asm volatile("red.global.add.noftz.v4.f16x2 [%0], {%1,%2,%3,%4};"
                                 :: "l"(p), "r"(ho[0]), "r"(ho[1]), "r"(ho[2]), "r"(ho[3]) : "memory");
                    asm volatile("red.global.add.noftz.v4.f16x2 [%0], {%1,%2,%3,%4};"
                                 :: "l"(p + 4), "r"(ho[4]), "r"(ho[5]), "r"(ho[6]), "r"(ho[7]) : "memory");
                    if (l2 == 0)
                        asm volatile("red.global.add.f32 [%0], %1;"
                                     :: "l"(&g_asum[dn * 2 + wn]), "f"(alv) : "memory");
                }
            }
        }
        __syncthreads();
        buf ^= 1;
    }
}

// ---------------- final: out = skip + acc / asum ----------------
__global__ void __launch_bounds__(256)
k_final(float* __restrict__ out)
{
    int idx = blockIdx.x * blockDim.x + threadIdx.x;
    if (idx >= N_NODES * 32) return;
    int n  = idx >> 5;
    int c4 = idx & 31;
    int h  = c4 >> 4;
    float inv = 1.f / (g_asum[n * 2 + h] + 1e-16f);
    float2 a0 = unpackh2(g_acch[(size_t)n * 64 + c4 * 2]);
    float2 a1 = unpackh2(g_acch[(size_t)n * 64 + c4 * 2 + 1]);
    float4 o = ((float4*)out)[idx];
    o.x += a0.x * inv; o.y += a0.y * inv; o.z += a1.x * inv; o.w += a1.y * inv;
    ((float4*)out)[idx] = o;
}

// ---------------- launch ----------------
extern "C" void kernel_launch(void* const* d_in, const int* in_sizes, int n_in,
                              void* d_out, int out_size)
{
    const float* x    = (const float*)d_in[0];
    const float* lu   = (const float*)d_in[1];
    const float* t    = (const float*)d_in[2];
    const float* msg  = (const float*)d_in[3];
    const float* tw   = (const float*)d_in[4];
    const float* tb   = (const float*)d_in[5];
    const float* Wq   = (const float*)d_in[6];
    const float* bq   = (const float*)d_in[7];
    const float* Wk   = (const float*)d_in[8];
    const float* bk   = (const float*)d_in[9];
    const float* Wv   = (const float*)d_in[10];
    const float* bv   = (const float*)d_in[11];
    const float* We   = (const float*)d_in[12];
    const float* Wsk  = (const float*)d_in[13];
    const float* bsk  = (const float*)d_in[14];
    const void*  ei   = d_in[15];
    float* out = (float*)d_out;

    cudaFuncSetAttribute(k_node_tc, cudaFuncAttributeMaxDynamicSharedMemorySize, KN_SMEM);
    cudaFuncSetAttribute(k_edge_tc, cudaFuncAttributeMaxDynamicSharedMemorySize, KE_SMEM);

    k_detect<<<1, 256>>>((const int*)ei);                              // my 0
    k_fused<<<FB_TOTAL, 256>>>(ei, We, Wq, Wk, Wv, Wsk);               // my 1
    k_node_tc<<<NT_NODE, 256, KN_SMEM>>>(x, bq, bk, bv, bsk, out);     // my 2
    k_edge_tc<<<304, 256, KE_SMEM>>>(t, lu, msg, tw, tb);              // my 3 (global 5)
    k_final<<<(N_NODES * 32 + 255) / 256, 256>>>(out);                 // my 4
}